// round 4
// baseline (speedup 1.0000x reference)
#include <cuda_runtime.h>
#include <cuda_bf16.h>

// Problem constants
#define NN   1024
#define CCH_C 16
#define HW   1024
#define NE   4096
#define MAXD 64

// Scratch (__device__ globals — sanctioned allocation-free scratch)
__device__ float g_x [(size_t)NN * 48 * HW];   // concat [feats, pos, neg]
__device__ float g_t1[(size_t)NN * 32 * HW];   // conv1 out
__device__ float g_t2[(size_t)NN * 32 * HW];   // conv2 out
__device__ int   g_deg[NN];
__device__ int   g_nbr[NN * MAXD];
__device__ int   g_sgn[NN * MAXD];

// ---------------------------------------------------------------------------
__global__ void k_zero_deg() {
    g_deg[threadIdx.x] = 0;
}

// Detect edge buffer encoding from its first 24 32-bit words.
// Returns 0 = int64, 1 = int32, 2 = float32.
__device__ __forceinline__ int detect_edge_mode(const unsigned* w) {
    bool any_floatish = false;
    bool odd_ok = true;
#pragma unroll
    for (int i = 0; i < 24; i++) {
        unsigned v = w[i];
        if (v >= 0x30000000u && v < 0xF0000000u) any_floatish = true;
        if ((i & 1) && !(v == 0u || v == 0xFFFFFFFFu)) odd_ok = false;
    }
    if (any_floatish) return 2;
    if (odd_ok) return 0;
    return 1;
}

// Build adjacency (incidence) lists from edges, dtype-agnostic.
__global__ void k_adj(const void* __restrict__ edges_raw) {
    int e = blockIdx.x * blockDim.x + threadIdx.x;
    if (e >= NE) return;
    int mode = detect_edge_mode((const unsigned*)edges_raw);
    int src, dst, sgn;
    if (mode == 0) {
        const long long* p = (const long long*)edges_raw;
        src = (int)p[3 * e + 0];
        sgn = (p[3 * e + 1] > 0) ? 1 : -1;
        dst = (int)p[3 * e + 2];
    } else if (mode == 1) {
        const int* p = (const int*)edges_raw;
        src = p[3 * e + 0];
        sgn = (p[3 * e + 1] > 0) ? 1 : -1;
        dst = p[3 * e + 2];
    } else {
        const float* p = (const float*)edges_raw;
        src = (int)p[3 * e + 0];
        sgn = (p[3 * e + 1] > 0.f) ? 1 : -1;
        dst = (int)p[3 * e + 2];
    }
    if ((unsigned)src >= NN || (unsigned)dst >= NN) return;
    int q = atomicAdd(&g_deg[dst], 1);
    if (q < MAXD) { g_nbr[dst * MAXD + q] = src; g_sgn[dst * MAXD + q] = sgn; }
    q = atomicAdd(&g_deg[src], 1);
    if (q < MAXD) { g_nbr[src * MAXD + q] = dst; g_sgn[src * MAXD + q] = sgn; }
}

// Gather-pool and build x = concat([feats, pos, neg]) — one CTA per node.
__global__ __launch_bounds__(256) void k_build(const float* __restrict__ feats) {
    int n = blockIdx.x;
    __shared__ int s_nbr[MAXD];
    __shared__ int s_sgn[MAXD];
    __shared__ int s_deg;
    if (threadIdx.x == 0) s_deg = min(g_deg[n], MAXD);
    if (threadIdx.x < MAXD) {
        int nb = g_nbr[n * MAXD + threadIdx.x];
        s_nbr[threadIdx.x] = ((unsigned)nb < NN) ? nb : 0;
        s_sgn[threadIdx.x] = g_sgn[n * MAXD + threadIdx.x];
    }
    __syncthreads();
    int deg = s_deg;
    const float* f = feats + (size_t)n * (CCH_C * HW);
    float* x = g_x + (size_t)n * (48 * HW);
    for (int j = threadIdx.x; j < CCH_C * HW; j += 256) {
        float self = f[j];
        float pos = 0.f, neg = 0.f;
        for (int d = 0; d < deg; d++) {
            float v = feats[(size_t)s_nbr[d] * (CCH_C * HW) + j];
            if (s_sgn[d] > 0) pos += v; else neg += v;
        }
        x[j]                  = self;
        x[CCH_C * HW + j]     = pos;
        x[2 * CCH_C * HW + j] = neg;
    }
}

// ---------------------------------------------------------------------------
// Direct 3x3 conv + bias + leaky ReLU. One CTA per image, 256 threads.
// Each thread: 4 pixels (rows row0+8j) x COUT channels in registers.
template <int CIN, int COUT>
__device__ __forceinline__ void conv_body(
    const float* __restrict__ in, const float* __restrict__ wgt,
    const float* __restrict__ bias, float* __restrict__ out)
{
    constexpr int CCH = 8;
    __shared__ float s_in[CCH * 34 * 34];
    __shared__ float s_w[CCH * 9 * COUT];

    int n = blockIdx.x;
    int tid = threadIdx.x;
    int col = tid & 31;
    int row0 = tid >> 5;

    const float* inb = in + (size_t)n * CIN * HW;

    float acc[4][COUT];
#pragma unroll
    for (int j = 0; j < 4; j++)
#pragma unroll
        for (int o = 0; o < COUT; o++) acc[j][o] = 0.f;

    for (int c0 = 0; c0 < CIN; c0 += CCH) {
        __syncthreads();
        for (int idx = tid; idx < CCH * 34 * 34; idx += 256) {
            int i  = idx / (34 * 34);
            int r  = (idx / 34) % 34 - 1;
            int cc = (idx % 34) - 1;
            float v = 0.f;
            if (r >= 0 && r < 32 && cc >= 0 && cc < 32)
                v = inb[(size_t)(c0 + i) * HW + r * 32 + cc];
            s_in[idx] = v;
        }
        for (int idx = tid; idx < CCH * 9 * COUT; idx += 256) {
            int o  = idx % COUT;
            int ik = idx / COUT;
            int k  = ik % 9;
            int i  = ik / 9;
            s_w[idx] = wgt[(size_t)o * (CIN * 9) + (size_t)(c0 + i) * 9 + k];
        }
        __syncthreads();

#pragma unroll
        for (int i = 0; i < CCH; i++) {
#pragma unroll
            for (int kh = 0; kh < 3; kh++) {
#pragma unroll
                for (int kw = 0; kw < 3; kw++) {
                    float x0 = s_in[i * (34 * 34) + (row0      + kh) * 34 + col + kw];
                    float x1 = s_in[i * (34 * 34) + (row0 + 8  + kh) * 34 + col + kw];
                    float x2 = s_in[i * (34 * 34) + (row0 + 16 + kh) * 34 + col + kw];
                    float x3 = s_in[i * (34 * 34) + (row0 + 24 + kh) * 34 + col + kw];
                    const float* wp = &s_w[((i * 3 + kh) * 3 + kw) * COUT];
#pragma unroll
                    for (int o = 0; o < COUT; o++) {
                        float wv = wp[o];
                        acc[0][o] += x0 * wv;
                        acc[1][o] += x1 * wv;
                        acc[2][o] += x2 * wv;
                        acc[3][o] += x3 * wv;
                    }
                }
            }
        }
    }

    float* ob = out + (size_t)n * COUT * HW;
#pragma unroll
    for (int j = 0; j < 4; j++) {
        int p = (row0 + 8 * j) * 32 + col;
#pragma unroll
        for (int o = 0; o < COUT; o++) {
            float v = acc[j][o] + bias[o];
            v = v > 0.f ? v : 0.1f * v;
            ob[(size_t)o * HW + p] = v;
        }
    }
}

__global__ __launch_bounds__(256, 1) void k_conv1(
    const float* __restrict__ w, const float* __restrict__ b) {
    conv_body<48, 32>(g_x, w, b, g_t1);
}
__global__ __launch_bounds__(256, 1) void k_conv2(
    const float* __restrict__ w, const float* __restrict__ b) {
    conv_body<32, 32>(g_t1, w, b, g_t2);
}
__global__ __launch_bounds__(256, 1) void k_conv3(
    const float* __restrict__ w, const float* __restrict__ b,
    float* __restrict__ out) {
    conv_body<32, 16>(g_t2, w, b, out);
}

// ---------------------------------------------------------------------------
extern "C" void kernel_launch(void* const* d_in, const int* in_sizes, int n_in,
                              void* d_out, int out_size) {
    // Identify inputs BY ELEMENT COUNT (robust to metadata ordering):
    //   feats: 16777216 (f32); edges: 12288 (any dtype) or 24576 (word-count)
    //   w1: 13824, w2: 9216, w3: 4608; b1: 32 (first), b2: 32 (second), b3: 16
    const float* feats = nullptr;
    const void*  edges = nullptr;
    const float *w1 = nullptr, *b1 = nullptr, *w2 = nullptr, *b2 = nullptr;
    const float *w3 = nullptr, *b3 = nullptr;
    int b32_seen = 0;
    for (int i = 0; i < n_in; i++) {
        switch (in_sizes[i]) {
            case 16777216: feats = (const float*)d_in[i]; break;
            case 12288:
            case 24576:    edges = d_in[i]; break;
            case 13824:    w1 = (const float*)d_in[i]; break;
            case 9216:     w2 = (const float*)d_in[i]; break;
            case 4608:     w3 = (const float*)d_in[i]; break;
            case 32:       if (b32_seen++ == 0) b1 = (const float*)d_in[i];
                           else                 b2 = (const float*)d_in[i];
                           break;
            case 16:       b3 = (const float*)d_in[i]; break;
            default: break;
        }
    }
    if (!feats || !edges || !w1 || !b1 || !w2 || !b2 || !w3 || !b3) {
        feats = (const float*)d_in[0];
        edges = d_in[1];
        w1 = (const float*)d_in[2]; b1 = (const float*)d_in[3];
        w2 = (const float*)d_in[4]; b2 = (const float*)d_in[5];
        w3 = (const float*)d_in[6]; b3 = (const float*)d_in[7];
    }
    float* out = (float*)d_out;

    k_zero_deg<<<1, NN>>>();
    k_adj<<<(NE + 255) / 256, 256>>>(edges);
    k_build<<<NN, 256>>>(feats);
    k_conv1<<<NN, 256>>>(w1, b1);
    k_conv2<<<NN, 256>>>(w2, b2);
    k_conv3<<<NN, 256>>>(w3, b3, out);
}

// round 7
// speedup vs baseline: 1.5625x; 1.5625x over previous
#include <cuda_runtime.h>
#include <cuda_bf16.h>
#include <cstdint>

// Problem constants
#define NN   1024
#define HW   1024
#define NE   4096
#define MAXD 64

// ---------------------------------------------------------------------------
// Scratch (__device__ globals)
__device__ float g_x [(size_t)NN * 48 * HW];   // concat [feats, pos, neg]
__device__ float g_t1[(size_t)NN * 32 * HW];   // conv1 out
__device__ float g_t2[(size_t)NN * 32 * HW];   // conv2 out
__device__ int   g_deg[NN];
__device__ int   g_nbr[NN * MAXD];
__device__ int   g_sgn[NN * MAXD];
// Pre-formatted bf16 weight images: [rep(hi/lo)][oc][cin*16+tap (+4 pad elems)]
__device__ __nv_bfloat16 g_wb1[2 * 32 * (48 * 16 + 8)];
__device__ __nv_bfloat16 g_wb2[2 * 32 * (32 * 16 + 8)];
__device__ __nv_bfloat16 g_wb3[2 * 16 * (32 * 16 + 8)];

// ---------------------------------------------------------------------------
__device__ __forceinline__ uint32_t smem_u32(const void* p) {
    uint32_t a;
    asm("{ .reg .u64 t; cvta.to.shared.u64 t, %1; cvt.u32.u64 %0, t; }" : "=r"(a) : "l"(p));
    return a;
}

#define LDSM_X4(r0, r1, r2, r3, addr) \
    asm volatile("ldmatrix.sync.aligned.m8n8.x4.shared.b16 {%0,%1,%2,%3}, [%4];" \
        : "=r"(r0), "=r"(r1), "=r"(r2), "=r"(r3) : "r"(addr))

#define MMA16816(d, a0, a1, a2, a3, b0, b1) \
    asm volatile("mma.sync.aligned.m16n8k16.row.col.f32.bf16.bf16.f32 " \
        "{%0,%1,%2,%3}, {%4,%5,%6,%7}, {%8,%9}, {%0,%1,%2,%3};" \
        : "+f"((d)[0]), "+f"((d)[1]), "+f"((d)[2]), "+f"((d)[3]) \
        : "r"(a0), "r"(a1), "r"(a2), "r"(a3), "r"(b0), "r"(b1))

#define STS128(addr, p0, p1, p2, p3) \
    asm volatile("st.shared.v4.b32 [%0], {%1,%2,%3,%4};" :: \
        "r"(addr), "r"(p0), "r"(p1), "r"(p2), "r"(p3))

// ---------------------------------------------------------------------------
// Graph prologue kernels (proven in R4)
__global__ void k_zero_deg() { g_deg[threadIdx.x] = 0; }

__device__ __forceinline__ int detect_edge_mode(const unsigned* w) {
    bool any_floatish = false, odd_ok = true;
#pragma unroll
    for (int i = 0; i < 24; i++) {
        unsigned v = w[i];
        if (v >= 0x30000000u && v < 0xF0000000u) any_floatish = true;
        if ((i & 1) && !(v == 0u || v == 0xFFFFFFFFu)) odd_ok = false;
    }
    if (any_floatish) return 2;
    if (odd_ok) return 0;
    return 1;
}

__global__ void k_adj(const void* __restrict__ edges_raw) {
    int e = blockIdx.x * blockDim.x + threadIdx.x;
    if (e >= NE) return;
    int mode = detect_edge_mode((const unsigned*)edges_raw);
    int src, dst, sgn;
    if (mode == 0) {
        const long long* p = (const long long*)edges_raw;
        src = (int)p[3 * e]; sgn = (p[3 * e + 1] > 0) ? 1 : -1; dst = (int)p[3 * e + 2];
    } else if (mode == 1) {
        const int* p = (const int*)edges_raw;
        src = p[3 * e]; sgn = (p[3 * e + 1] > 0) ? 1 : -1; dst = p[3 * e + 2];
    } else {
        const float* p = (const float*)edges_raw;
        src = (int)p[3 * e]; sgn = (p[3 * e + 1] > 0.f) ? 1 : -1; dst = (int)p[3 * e + 2];
    }
    if ((unsigned)src >= NN || (unsigned)dst >= NN) return;
    int q = atomicAdd(&g_deg[dst], 1);
    if (q < MAXD) { g_nbr[dst * MAXD + q] = src; g_sgn[dst * MAXD + q] = sgn; }
    q = atomicAdd(&g_deg[src], 1);
    if (q < MAXD) { g_nbr[src * MAXD + q] = dst; g_sgn[src * MAXD + q] = sgn; }
}

__global__ __launch_bounds__(256) void k_build(const float* __restrict__ feats) {
    int n = blockIdx.x;
    __shared__ int s_nbr[MAXD], s_sgn[MAXD], s_deg;
    if (threadIdx.x == 0) s_deg = min(g_deg[n], MAXD);
    if (threadIdx.x < MAXD) {
        int nb = g_nbr[n * MAXD + threadIdx.x];
        s_nbr[threadIdx.x] = ((unsigned)nb < NN) ? nb : 0;
        s_sgn[threadIdx.x] = g_sgn[n * MAXD + threadIdx.x];
    }
    __syncthreads();
    int deg = s_deg;
    const float* f = feats + (size_t)n * (16 * HW);
    float* x = g_x + (size_t)n * (48 * HW);
    for (int j = threadIdx.x; j < 16 * HW; j += 256) {
        float self = f[j];
        float pos = 0.f, neg = 0.f;
        for (int d = 0; d < deg; d++) {
            float v = feats[(size_t)s_nbr[d] * (16 * HW) + j];
            if (s_sgn[d] > 0) pos += v; else neg += v;
        }
        x[j] = self; x[16 * HW + j] = pos; x[32 * HW + j] = neg;
    }
}

// ---------------------------------------------------------------------------
// Weight prep: fp32 OIHW -> [rep][oc][cin*16+tap] bf16 (taps 9..15 = 0,
// +4 bf16 row padding so B row stride = CIN*32+16 bytes: conflict-free ldmatrix)
__device__ __forceinline__ void prep_one(const float* __restrict__ wgt,
                                         __nv_bfloat16* __restrict__ gB,
                                         int idx, int CIN, int COUT) {
    int rowlen = CIN * 16 + 8;
    int row = idx / rowlen, kp = idx % rowlen;
    int rep = row / COUT, oc = row % COUT;
    __nv_bfloat16 val = __float2bfloat16(0.f);
    if (kp < CIN * 16) {
        int cin = kp >> 4, tap = kp & 15;
        if (tap < 9) {
            float wv = wgt[(oc * CIN + cin) * 9 + tap];
            __nv_bfloat16 h = __float2bfloat16(wv);
            val = rep ? __float2bfloat16(wv - __bfloat162float(h)) : h;
        }
    }
    gB[idx] = val;
}
__global__ void k_prep1(const float* __restrict__ w) {
    int idx = blockIdx.x * 256 + threadIdx.x;
    if (idx < 2 * 32 * (48 * 16 + 8)) prep_one(w, g_wb1, idx, 48, 32);
}
__global__ void k_prep2(const float* __restrict__ w) {
    int idx = blockIdx.x * 256 + threadIdx.x;
    if (idx < 2 * 32 * (32 * 16 + 8)) prep_one(w, g_wb2, idx, 32, 32);
}
__global__ void k_prep3(const float* __restrict__ w) {
    int idx = blockIdx.x * 256 + threadIdx.x;
    if (idx < 2 * 16 * (32 * 16 + 8)) prep_one(w, g_wb3, idx, 32, 16);
}

// ---------------------------------------------------------------------------
// HMMA implicit-GEMM conv. Persistent CTAs; per tile: 128 px (4 image rows)
// x COUT.  3-term bf16 hi/lo split:
//   pass 0 (A=hi): MMA vs B rep0 (w_hi) AND rep1 (w_lo)
//   pass 1 (A=lo): MMA vs B rep0 (w_hi)
// A chunk in smem: 128 px x 256 k (16 cins x 16 taps), XOR-swizzled 16B units.
template <int CIN, int COUT>
__device__ void conv_mma_body(const float* __restrict__ in,
                              const __nv_bfloat16* __restrict__ gB,
                              const float* __restrict__ bias,
                              float* __restrict__ out) {
    constexpr int NCB    = CIN / 16;            // A chunks per pass
    constexpr int BROW   = CIN * 32 + 16;       // bytes per oc row
    constexpr int BBYTES = 2 * COUT * BROW;
    constexpr int ABYTES = 128 * 512;
    constexpr int RW = 34, RH = 6;
    constexpr int NT = COUT / 8;                // n-tiles (4 or 2)

    extern __shared__ char smem[];
    char* Bs = smem;
    char* As = smem + BBYTES;
    uint32_t* raws = (uint32_t*)(As + ABYTES);

    const int tid = threadIdx.x, wid = tid >> 5, lane = tid & 31;

    // stage B once (persistent CTA)
    for (int i = tid; i < BBYTES / 4; i += 256)
        ((uint32_t*)Bs)[i] = ((const uint32_t*)gB)[i];

    const uint32_t As_u = smem_u32(As);
    const uint32_t Bs_u = smem_u32(Bs);

    // producer mapping: thread -> (px, 8 cin-groups)
    const int px = tid & 127;
    const int jbase = (tid >> 7) * 8;
    const int pr = px >> 5, pxc = px & 31;
    const int pxl = px & 7;
    const uint32_t a_st_base = As_u + px * 512;

    // consumer mapping (mma fragments)
    const int g_r = lane >> 2, tg = lane & 3;
    const int m0 = wid * 16;
    const int a_row = m0 + ((lane >> 3) & 1) * 8 + (lane & 7);
    const int a_kb = lane >> 4;                  // k-block (0/1) per ldmatrix.x4
    const uint32_t a_ld_base = As_u + a_row * 512;
    const int a_xr = a_row & 7;
    const int b_oc = ((lane >> 4) & 1) * 8 + (lane & 7);
    const int b_kb = (lane >> 3) & 1;

    for (int tile = blockIdx.x; tile < NN * 8; tile += gridDim.x) {
        const int n = tile >> 3, t = tile & 7;
        const int y0 = t * 4;
        const float* inb = in + (size_t)n * CIN * HW;

        // stage raw hi/lo halo: [cin][6][34] u32 = hi16 | (lo16<<16)
        for (int i2 = tid; i2 < CIN * RH * RW; i2 += 256) {
            int cin = i2 / (RH * RW), rem = i2 % (RH * RW);
            int ry = rem / RW, rx = rem % RW;
            int y = y0 - 1 + ry, x = rx - 1;
            uint32_t pk = 0;
            if ((unsigned)y < 32u && (unsigned)x < 32u) {
                float v = inb[cin * HW + y * 32 + x];
                __nv_bfloat16 h = __float2bfloat16(v);
                __nv_bfloat16 l = __float2bfloat16(v - __bfloat162float(h));
                pk = (uint32_t)__bfloat16_as_ushort(h) |
                     ((uint32_t)__bfloat16_as_ushort(l) << 16);
            }
            raws[i2] = pk;
        }

        float acc[NT][4];
#pragma unroll
        for (int nt = 0; nt < NT; nt++)
            acc[nt][0] = acc[nt][1] = acc[nt][2] = acc[nt][3] = 0.f;

        __syncthreads();

#pragma unroll
        for (int pass = 0; pass < 2; pass++) {
            const uint32_t sel = pass ? 0x7632u : 0x5410u;  // hi / lo halves
            for (int cb = 0; cb < NCB; cb++) {
                // ---- build A chunk: cins cb*16 .. cb*16+15 ----
                const uint32_t* rp0 = raws + (1 + pr) * RW + (1 + pxc);
#pragma unroll
                for (int j = 0; j < 8; j++) {
                    int gl = jbase + j;
                    int cin = cb * 16 + gl;
                    const uint32_t* rp = rp0 + cin * (RH * RW);
                    uint32_t t0 = rp[-RW - 1], t1 = rp[-RW], t2 = rp[-RW + 1];
                    uint32_t t3 = rp[-1],      t4 = rp[0],   t5 = rp[1];
                    uint32_t t6 = rp[RW - 1],  t7 = rp[RW],  t8 = rp[RW + 1];
                    uint32_t p0 = __byte_perm(t0, t1, sel);
                    uint32_t p1 = __byte_perm(t2, t3, sel);
                    uint32_t p2 = __byte_perm(t4, t5, sel);
                    uint32_t p3 = __byte_perm(t6, t7, sel);
                    uint32_t p4 = __byte_perm(t8, 0u, sel);
                    uint32_t u0 = (uint32_t)(((gl * 2)     ^ pxl) * 16);
                    uint32_t u1 = (uint32_t)(((gl * 2 + 1) ^ pxl) * 16);
                    STS128(a_st_base + u0, p0, p1, p2, p3);
                    STS128(a_st_base + u1, p4, 0u, 0u, 0u);
                }
                __syncthreads();

                // ---- MMA over the 16 k-steps of this chunk ----
#pragma unroll
                for (int ks = 0; ks < 16; ks++) {
                    uint32_t a0, a1, a2, a3;
                    LDSM_X4(a0, a1, a2, a3,
                            a_ld_base + (uint32_t)((((ks * 2 + a_kb) ^ a_xr)) * 16));
                    uint32_t koff = (uint32_t)(cb * 512 + ks * 32 + b_kb * 16);
                    // rep 0 (w_hi)
                    {
                        uint32_t b0, b1, b2, b3;
                        LDSM_X4(b0, b1, b2, b3, Bs_u + b_oc * BROW + koff);
                        MMA16816(acc[0], a0, a1, a2, a3, b0, b1);
                        MMA16816(acc[1], a0, a1, a2, a3, b2, b3);
                        if constexpr (NT > 2) {
                            uint32_t c0, c1, c2, c3;
                            LDSM_X4(c0, c1, c2, c3, Bs_u + (16 + b_oc) * BROW + koff);
                            MMA16816(acc[2], a0, a1, a2, a3, c0, c1);
                            MMA16816(acc[3], a0, a1, a2, a3, c2, c3);
                        }
                    }
                    // rep 1 (w_lo) — only against A=hi
                    if (pass == 0) {
                        uint32_t roff = (uint32_t)(COUT * BROW);
                        uint32_t b0, b1, b2, b3;
                        LDSM_X4(b0, b1, b2, b3, Bs_u + b_oc * BROW + roff + koff);
                        MMA16816(acc[0], a0, a1, a2, a3, b0, b1);
                        MMA16816(acc[1], a0, a1, a2, a3, b2, b3);
                        if constexpr (NT > 2) {
                            uint32_t c0, c1, c2, c3;
                            LDSM_X4(c0, c1, c2, c3,
                                    Bs_u + (16 + b_oc) * BROW + roff + koff);
                            MMA16816(acc[2], a0, a1, a2, a3, c0, c1);
                            MMA16816(acc[3], a0, a1, a2, a3, c2, c3);
                        }
                    }
                }
                __syncthreads();
            }
        }

        // ---- epilogue: bias + leaky, write fp32 ----
        {
            float* ob = out + (size_t)n * COUT * HW + y0 * 32;
            const int pA = m0 + g_r, pB = pA + 8;
#pragma unroll
            for (int nt = 0; nt < NT; nt++) {
                int oc = nt * 8 + tg * 2;
                float bv0 = __ldg(bias + oc), bv1 = __ldg(bias + oc + 1);
                float v;
                v = acc[nt][0] + bv0; v = v > 0.f ? v : 0.1f * v; ob[(size_t)oc * HW + pA] = v;
                v = acc[nt][1] + bv1; v = v > 0.f ? v : 0.1f * v; ob[(size_t)(oc + 1) * HW + pA] = v;
                v = acc[nt][2] + bv0; v = v > 0.f ? v : 0.1f * v; ob[(size_t)oc * HW + pB] = v;
                v = acc[nt][3] + bv1; v = v > 0.f ? v : 0.1f * v; ob[(size_t)(oc + 1) * HW + pB] = v;
            }
        }
        __syncthreads();   // raw/A reused next tile
    }
}

__global__ __launch_bounds__(256, 1) void k_mconv1(const float* __restrict__ b) {
    conv_mma_body<48, 32>(g_x, g_wb1, b, g_t1);
}
__global__ __launch_bounds__(256, 1) void k_mconv2(const float* __restrict__ b) {
    conv_mma_body<32, 32>(g_t1, g_wb2, b, g_t2);
}
__global__ __launch_bounds__(256, 1) void k_mconv3(const float* __restrict__ b,
                                                   float* __restrict__ out) {
    conv_mma_body<32, 16>(g_t2, g_wb3, b, out);
}

// ---------------------------------------------------------------------------
static inline int smsz(int CIN, int COUT) {
    return 2 * COUT * (CIN * 32 + 16) + 128 * 512 + CIN * 6 * 34 * 4;
}

extern "C" void kernel_launch(void* const* d_in, const int* in_sizes, int n_in,
                              void* d_out, int out_size) {
    const float* feats = nullptr;
    const void*  edges = nullptr;
    const float *w1 = nullptr, *b1 = nullptr, *w2 = nullptr, *b2 = nullptr;
    const float *w3 = nullptr, *b3 = nullptr;
    int b32_seen = 0;
    for (int i = 0; i < n_in; i++) {
        switch (in_sizes[i]) {
            case 16777216: feats = (const float*)d_in[i]; break;
            case 12288:
            case 24576:    edges = d_in[i]; break;
            case 13824:    w1 = (const float*)d_in[i]; break;
            case 9216:     w2 = (const float*)d_in[i]; break;
            case 4608:     w3 = (const float*)d_in[i]; break;
            case 32:       if (b32_seen++ == 0) b1 = (const float*)d_in[i];
                           else                 b2 = (const float*)d_in[i];
                           break;
            case 16:       b3 = (const float*)d_in[i]; break;
            default: break;
        }
    }
    if (!feats || !edges || !w1 || !b1 || !w2 || !b2 || !w3 || !b3) {
        feats = (const float*)d_in[0];
        edges = d_in[1];
        w1 = (const float*)d_in[2]; b1 = (const float*)d_in[3];
        w2 = (const float*)d_in[4]; b2 = (const float*)d_in[5];
        w3 = (const float*)d_in[6]; b3 = (const float*)d_in[7];
    }
    float* out = (float*)d_out;

    // Idempotent, not a stream op — safe on every call.
    cudaFuncSetAttribute(k_mconv1, cudaFuncAttributeMaxDynamicSharedMemorySize, smsz(48, 32));
    cudaFuncSetAttribute(k_mconv2, cudaFuncAttributeMaxDynamicSharedMemorySize, smsz(32, 32));
    cudaFuncSetAttribute(k_mconv3, cudaFuncAttributeMaxDynamicSharedMemorySize, smsz(32, 16));

    k_zero_deg<<<1, NN>>>();
    k_adj<<<(NE + 255) / 256, 256>>>(edges);
    k_prep1<<<(2 * 32 * (48 * 16 + 8) + 255) / 256, 256>>>(w1);
    k_prep2<<<(2 * 32 * (32 * 16 + 8) + 255) / 256, 256>>>(w2);
    k_prep3<<<(2 * 16 * (32 * 16 + 8) + 255) / 256, 256>>>(w3);
    k_build<<<NN, 256>>>(feats);
    k_mconv1<<<148, 256, smsz(48, 32)>>>(b1);
    k_mconv2<<<148, 256, smsz(32, 32)>>>(b2);
    k_mconv3<<<148, 256, smsz(32, 16)>>>(b3, out);
}

// round 8
// speedup vs baseline: 2.8239x; 1.8073x over previous
#include <cuda_runtime.h>
#include <cuda_bf16.h>
#include <cstdint>

// Problem constants
#define NN   1024
#define HW   1024
#define NE   4096
#define MAXD 64

// ---------------------------------------------------------------------------
// Scratch (__device__ globals)
__device__ float g_x [(size_t)NN * 48 * HW];   // concat [feats, pos, neg]
__device__ float g_t1[(size_t)NN * 32 * HW];   // conv1 out
__device__ float g_t2[(size_t)NN * 32 * HW];   // conv2 out
__device__ int   g_deg[NN];
__device__ int   g_nbr[NN * MAXD];
__device__ int   g_sgn[NN * MAXD];
// Weight images: [rep(hi/lo)][oc][k = tap*CIN + cin], row padded to KP elems
__device__ __nv_bfloat16 g_wb1[2 * 32 * 440];
__device__ __nv_bfloat16 g_wb2[2 * 32 * 296];
__device__ __nv_bfloat16 g_wb3[2 * 16 * 296];

// ---------------------------------------------------------------------------
__device__ __forceinline__ uint32_t smem_u32(const void* p) {
    uint32_t a;
    asm("{ .reg .u64 t; cvta.to.shared.u64 t, %1; cvt.u32.u64 %0, t; }" : "=r"(a) : "l"(p));
    return a;
}

#define LDSM_X4(r0, r1, r2, r3, addr) \
    asm volatile("ldmatrix.sync.aligned.m8n8.x4.shared.b16 {%0,%1,%2,%3}, [%4];" \
        : "=r"(r0), "=r"(r1), "=r"(r2), "=r"(r3) : "r"(addr))

#define MMA16816(d, a0, a1, a2, a3, b0, b1) \
    asm volatile("mma.sync.aligned.m16n8k16.row.col.f32.bf16.bf16.f32 " \
        "{%0,%1,%2,%3}, {%4,%5,%6,%7}, {%8,%9}, {%0,%1,%2,%3};" \
        : "+f"((d)[0]), "+f"((d)[1]), "+f"((d)[2]), "+f"((d)[3]) \
        : "r"(a0), "r"(a1), "r"(a2), "r"(a3), "r"(b0), "r"(b1))

#define STS128(addr, p0, p1, p2, p3) \
    asm volatile("st.shared.v4.b32 [%0], {%1,%2,%3,%4};" :: \
        "r"(addr), "r"(p0), "r"(p1), "r"(p2), "r"(p3))

// ---------------------------------------------------------------------------
// Graph prologue kernels (proven)
__global__ void k_zero_deg() { g_deg[threadIdx.x] = 0; }

__device__ __forceinline__ int detect_edge_mode(const unsigned* w) {
    bool any_floatish = false, odd_ok = true;
#pragma unroll
    for (int i = 0; i < 24; i++) {
        unsigned v = w[i];
        if (v >= 0x30000000u && v < 0xF0000000u) any_floatish = true;
        if ((i & 1) && !(v == 0u || v == 0xFFFFFFFFu)) odd_ok = false;
    }
    if (any_floatish) return 2;
    if (odd_ok) return 0;
    return 1;
}

__global__ void k_adj(const void* __restrict__ edges_raw) {
    int e = blockIdx.x * blockDim.x + threadIdx.x;
    if (e >= NE) return;
    int mode = detect_edge_mode((const unsigned*)edges_raw);
    int src, dst, sgn;
    if (mode == 0) {
        const long long* p = (const long long*)edges_raw;
        src = (int)p[3 * e]; sgn = (p[3 * e + 1] > 0) ? 1 : -1; dst = (int)p[3 * e + 2];
    } else if (mode == 1) {
        const int* p = (const int*)edges_raw;
        src = p[3 * e]; sgn = (p[3 * e + 1] > 0) ? 1 : -1; dst = p[3 * e + 2];
    } else {
        const float* p = (const float*)edges_raw;
        src = (int)p[3 * e]; sgn = (p[3 * e + 1] > 0.f) ? 1 : -1; dst = (int)p[3 * e + 2];
    }
    if ((unsigned)src >= NN || (unsigned)dst >= NN) return;
    int q = atomicAdd(&g_deg[dst], 1);
    if (q < MAXD) { g_nbr[dst * MAXD + q] = src; g_sgn[dst * MAXD + q] = sgn; }
    q = atomicAdd(&g_deg[src], 1);
    if (q < MAXD) { g_nbr[src * MAXD + q] = dst; g_sgn[src * MAXD + q] = sgn; }
}

__global__ __launch_bounds__(256) void k_build(const float* __restrict__ feats) {
    int n = blockIdx.x;
    __shared__ int s_nbr[MAXD], s_sgn[MAXD], s_deg;
    if (threadIdx.x == 0) s_deg = min(g_deg[n], MAXD);
    if (threadIdx.x < MAXD) {
        int nb = g_nbr[n * MAXD + threadIdx.x];
        s_nbr[threadIdx.x] = ((unsigned)nb < NN) ? nb : 0;
        s_sgn[threadIdx.x] = g_sgn[n * MAXD + threadIdx.x];
    }
    __syncthreads();
    int deg = s_deg;
    const float* f = feats + (size_t)n * (16 * HW);
    float* x = g_x + (size_t)n * (48 * HW);
    for (int j = threadIdx.x; j < 16 * HW; j += 256) {
        float self = f[j];
        float pos = 0.f, neg = 0.f;
        for (int d = 0; d < deg; d++) {
            float v = feats[(size_t)s_nbr[d] * (16 * HW) + j];
            if (s_sgn[d] > 0) pos += v; else neg += v;
        }
        x[j] = self; x[16 * HW + j] = pos; x[32 * HW + j] = neg;
    }
}

// ---------------------------------------------------------------------------
// Weight prep: fp32 OIHW -> [rep][oc][k=tap*CIN+cin], rows padded to KP.
__device__ __forceinline__ void prep_one(const float* __restrict__ wgt,
                                         __nv_bfloat16* __restrict__ gB,
                                         int idx, int CIN, int COUT, int KP) {
    int rep = idx / (COUT * KP);
    int rem = idx % (COUT * KP);
    int oc = rem / KP, kp = rem % KP;
    __nv_bfloat16 val = __float2bfloat16(0.f);
    if (kp < 9 * CIN) {
        int tap = kp / CIN, cin = kp % CIN;
        float wv = wgt[(oc * CIN + cin) * 9 + tap];
        __nv_bfloat16 h = __float2bfloat16(wv);
        val = rep ? __float2bfloat16(wv - __bfloat162float(h)) : h;
    }
    gB[idx] = val;
}
__global__ void k_prep1(const float* __restrict__ w) {
    int idx = blockIdx.x * 256 + threadIdx.x;
    if (idx < 2 * 32 * 440) prep_one(w, g_wb1, idx, 48, 32, 440);
}
__global__ void k_prep2(const float* __restrict__ w) {
    int idx = blockIdx.x * 256 + threadIdx.x;
    if (idx < 2 * 32 * 296) prep_one(w, g_wb2, idx, 32, 32, 296);
}
__global__ void k_prep3(const float* __restrict__ w) {
    int idx = blockIdx.x * 256 + threadIdx.x;
    if (idx < 2 * 16 * 296) prep_one(w, g_wb3, idx, 32, 16, 296);
}

// ---------------------------------------------------------------------------
// HMMA implicit-GEMM conv, plane layout (no A-build phase).
// CTA tile = 256 px (8 image rows). Warp = 32 px (2 m16 tiles).
// Planes P_hi/P_lo: [10 y][34 x][CP=CIN+8 cin] bf16 -> ldmatrix reads directly.
// 3-term split: acc = A_hi*W_hi + A_lo*W_hi + A_hi*W_lo.
template <int CIN, int COUT, int KP, int MAXNCTA>
__device__ void conv_body(const float* __restrict__ in,
                          const __nv_bfloat16* __restrict__ gB,
                          const float* __restrict__ bias,
                          float* __restrict__ out) {
    constexpr int CP  = CIN + 8;
    constexpr int NCG = CIN / 16;        // k16 groups per tap
    constexpr int NT  = COUT / 8;        // n8 tiles
    constexpr int NH  = NT / 2;          // B ldmatrix.x4 per rep (n16 each)
    constexpr int BB  = 2 * COUT * KP * 2;
    constexpr int PB  = 10 * 34 * CP * 2;
    constexpr int NGR = CIN / 8;         // staging groups

    extern __shared__ char smem[];
    char* Bs  = smem;
    char* Phi = smem + BB;
    char* Plo = Phi + PB;
    uint32_t* raws = (uint32_t*)(Plo + PB);   // [8][341] u32

    const int tid = threadIdx.x, wid = tid >> 5, lane = tid & 31;
    const uint32_t Bs_u  = smem_u32(Bs);
    const uint32_t Phi_u = smem_u32(Phi);
    const uint32_t Plo_u = smem_u32(Plo);

    // stage B once (persistent CTA)
    for (int i = tid; i < BB / 4; i += 256)
        ((uint32_t*)Bs)[i] = ((const uint32_t*)gB)[i];

    // A-fragment lane mapping (validated in R7)
    const int arl = (lane & 7) + ((lane >> 3) & 1) * 8;   // row in m16
    const int akb = lane >> 4;                            // k halves
    uint32_t pbase[2];
#pragma unroll
    for (int mt = 0; mt < 2; mt++) {
        int px = wid * 32 + mt * 16 + arl;
        int r = px >> 5, c = px & 31;
        pbase[mt] = (uint32_t)((r * 34 + c) * CP * 2 + akb * 16);
    }
    // B-fragment lane mapping (validated in R7)
    const int boc = ((lane >> 4) & 1) * 8 + (lane & 7);
    const int bkb = (lane >> 3) & 1;
    uint32_t bbase[2][NH];
#pragma unroll
    for (int rep = 0; rep < 2; rep++)
#pragma unroll
        for (int h = 0; h < NH; h++)
            bbase[rep][h] = Bs_u + (uint32_t)(rep * COUT * KP * 2 +
                             (h * 16 + boc) * KP * 2 + bkb * 16);
    // epilogue mapping
    const int g_r = lane >> 2, tg = lane & 3;

    for (int tile = blockIdx.x; tile < NN * 4; tile += gridDim.x) {
        const int n = tile >> 2, y0 = (tile & 3) * 8;
        const float* inb = in + (size_t)n * CIN * HW;

        // ---- stage planes (transpose via padded raw bounce) ----
        for (int g = 0; g < NGR; g++) {
            for (int i = tid; i < 8 * 340; i += 256) {
                int c8 = i / 340, pos = i % 340;
                int y = pos / 34, x = pos % 34;
                int yi = y0 - 1 + y, xi = x - 1;
                uint32_t pk = 0;
                if ((unsigned)yi < 32u && (unsigned)xi < 32u) {
                    float v = inb[(size_t)(g * 8 + c8) * HW + yi * 32 + xi];
                    __nv_bfloat16 h = __float2bfloat16(v);
                    __nv_bfloat16 l = __float2bfloat16(v - __bfloat162float(h));
                    pk = (uint32_t)__bfloat16_as_ushort(h) |
                         ((uint32_t)__bfloat16_as_ushort(l) << 16);
                }
                raws[c8 * 341 + pos] = pk;
            }
            __syncthreads();
            for (int i = tid; i < 340; i += 256) {
                uint32_t p[8];
#pragma unroll
                for (int c = 0; c < 8; c++) p[c] = raws[c * 341 + i];
                uint32_t h0 = __byte_perm(p[0], p[1], 0x5410);
                uint32_t h1 = __byte_perm(p[2], p[3], 0x5410);
                uint32_t h2 = __byte_perm(p[4], p[5], 0x5410);
                uint32_t h3 = __byte_perm(p[6], p[7], 0x5410);
                uint32_t l0 = __byte_perm(p[0], p[1], 0x7632);
                uint32_t l1 = __byte_perm(p[2], p[3], 0x7632);
                uint32_t l2 = __byte_perm(p[4], p[5], 0x7632);
                uint32_t l3 = __byte_perm(p[6], p[7], 0x7632);
                uint32_t off = (uint32_t)(i * CP * 2 + g * 16);
                STS128(Phi_u + off, h0, h1, h2, h3);
                STS128(Plo_u + off, l0, l1, l2, l3);
            }
            __syncthreads();
        }

        // ---- k loop: no syncs, ldmatrix straight from planes ----
        float acc[2][NT][4];
#pragma unroll
        for (int mt = 0; mt < 2; mt++)
#pragma unroll
            for (int nt = 0; nt < NT; nt++)
                acc[mt][nt][0] = acc[mt][nt][1] = acc[mt][nt][2] = acc[mt][nt][3] = 0.f;

#pragma unroll
        for (int tap = 0; tap < 9; tap++) {
            const uint32_t toff = (uint32_t)(((tap / 3) * 34 + (tap % 3)) * CP * 2);
#pragma unroll
            for (int cg = 0; cg < NCG; cg++) {
                const uint32_t aoff = toff + cg * 32;
                const uint32_t koff = (uint32_t)((tap * CIN + cg * 16) * 2);
                uint32_t ah[2][4], al[2][4];
#pragma unroll
                for (int mt = 0; mt < 2; mt++) {
                    LDSM_X4(ah[mt][0], ah[mt][1], ah[mt][2], ah[mt][3],
                            Phi_u + pbase[mt] + aoff);
                    LDSM_X4(al[mt][0], al[mt][1], al[mt][2], al[mt][3],
                            Plo_u + pbase[mt] + aoff);
                }
#pragma unroll
                for (int h = 0; h < NH; h++) {
                    uint32_t b0, b1, b2, b3, c0, c1, c2, c3;
                    LDSM_X4(b0, b1, b2, b3, bbase[0][h] + koff);  // w_hi
                    LDSM_X4(c0, c1, c2, c3, bbase[1][h] + koff);  // w_lo
#pragma unroll
                    for (int mt = 0; mt < 2; mt++) {
                        MMA16816(acc[mt][2*h],   ah[mt][0], ah[mt][1], ah[mt][2], ah[mt][3], b0, b1);
                        MMA16816(acc[mt][2*h+1], ah[mt][0], ah[mt][1], ah[mt][2], ah[mt][3], b2, b3);
                        MMA16816(acc[mt][2*h],   al[mt][0], al[mt][1], al[mt][2], al[mt][3], b0, b1);
                        MMA16816(acc[mt][2*h+1], al[mt][0], al[mt][1], al[mt][2], al[mt][3], b2, b3);
                        MMA16816(acc[mt][2*h],   ah[mt][0], ah[mt][1], ah[mt][2], ah[mt][3], c0, c1);
                        MMA16816(acc[mt][2*h+1], ah[mt][0], ah[mt][1], ah[mt][2], ah[mt][3], c2, c3);
                    }
                }
            }
        }

        // ---- epilogue ----
        {
            float* ob = out + (size_t)n * COUT * HW + y0 * 32;
#pragma unroll
            for (int mt = 0; mt < 2; mt++) {
                const int pA = wid * 32 + mt * 16 + g_r, pB = pA + 8;
#pragma unroll
                for (int nt = 0; nt < NT; nt++) {
                    int oc = nt * 8 + tg * 2;
                    float bv0 = __ldg(bias + oc), bv1 = __ldg(bias + oc + 1);
                    float v;
                    v = acc[mt][nt][0] + bv0; v = v > 0.f ? v : 0.1f * v; ob[(size_t)oc * HW + pA] = v;
                    v = acc[mt][nt][1] + bv1; v = v > 0.f ? v : 0.1f * v; ob[(size_t)(oc + 1) * HW + pA] = v;
                    v = acc[mt][nt][2] + bv0; v = v > 0.f ? v : 0.1f * v; ob[(size_t)oc * HW + pB] = v;
                    v = acc[mt][nt][3] + bv1; v = v > 0.f ? v : 0.1f * v; ob[(size_t)(oc + 1) * HW + pB] = v;
                }
            }
        }
        __syncthreads();   // planes/raw reused next tile
    }
}

__global__ __launch_bounds__(256, 1) void k_mconv1(const float* __restrict__ b) {
    conv_body<48, 32, 440, 1>(g_x, g_wb1, b, g_t1);
}
__global__ __launch_bounds__(256, 2) void k_mconv2(const float* __restrict__ b) {
    conv_body<32, 32, 296, 2>(g_t1, g_wb2, b, g_t2);
}
__global__ __launch_bounds__(256, 2) void k_mconv3(const float* __restrict__ b,
                                                   float* __restrict__ out) {
    conv_body<32, 16, 296, 2>(g_t2, g_wb3, b, out);
}

// ---------------------------------------------------------------------------
static inline int smsz(int CIN, int COUT, int KP) {
    return 2 * COUT * KP * 2 + 2 * (10 * 34 * (CIN + 8) * 2) + 8 * 341 * 4;
}

extern "C" void kernel_launch(void* const* d_in, const int* in_sizes, int n_in,
                              void* d_out, int out_size) {
    const float* feats = nullptr;
    const void*  edges = nullptr;
    const float *w1 = nullptr, *b1 = nullptr, *w2 = nullptr, *b2 = nullptr;
    const float *w3 = nullptr, *b3 = nullptr;
    int b32_seen = 0;
    for (int i = 0; i < n_in; i++) {
        switch (in_sizes[i]) {
            case 16777216: feats = (const float*)d_in[i]; break;
            case 12288:
            case 24576:    edges = d_in[i]; break;
            case 13824:    w1 = (const float*)d_in[i]; break;
            case 9216:     w2 = (const float*)d_in[i]; break;
            case 4608:     w3 = (const float*)d_in[i]; break;
            case 32:       if (b32_seen++ == 0) b1 = (const float*)d_in[i];
                           else                 b2 = (const float*)d_in[i];
                           break;
            case 16:       b3 = (const float*)d_in[i]; break;
            default: break;
        }
    }
    if (!feats || !edges || !w1 || !b1 || !w2 || !b2 || !w3 || !b3) {
        feats = (const float*)d_in[0];
        edges = d_in[1];
        w1 = (const float*)d_in[2]; b1 = (const float*)d_in[3];
        w2 = (const float*)d_in[4]; b2 = (const float*)d_in[5];
        w3 = (const float*)d_in[6]; b3 = (const float*)d_in[7];
    }
    float* out = (float*)d_out;

    // Idempotent, not a stream op — safe on every call.
    cudaFuncSetAttribute(k_mconv1, cudaFuncAttributeMaxDynamicSharedMemorySize, smsz(48, 32, 440));
    cudaFuncSetAttribute(k_mconv2, cudaFuncAttributeMaxDynamicSharedMemorySize, smsz(32, 32, 296));
    cudaFuncSetAttribute(k_mconv3, cudaFuncAttributeMaxDynamicSharedMemorySize, smsz(32, 16, 296));

    k_zero_deg<<<1, NN>>>();
    k_adj<<<(NE + 255) / 256, 256>>>(edges);
    k_prep1<<<(2 * 32 * 440 + 255) / 256, 256>>>(w1);
    k_prep2<<<(2 * 32 * 296 + 255) / 256, 256>>>(w2);
    k_prep3<<<(2 * 16 * 296 + 255) / 256, 256>>>(w3);
    k_build<<<NN, 256>>>(feats);
    k_mconv1<<<148, 256, smsz(48, 32, 440)>>>(b1);
    k_mconv2<<<296, 256, smsz(32, 32, 296)>>>(b2);
    k_mconv3<<<296, 256, smsz(32, 16, 296)>>>(b3, out);
}

// round 9
// speedup vs baseline: 4.1041x; 1.4533x over previous
#include <cuda_runtime.h>
#include <cuda_bf16.h>
#include <cstdint>

// Problem constants
#define NN   1024
#define HW   1024
#define NE   4096
#define MAXD 64

// ---------------------------------------------------------------------------
// Scratch (__device__ globals)
__device__ float g_x [(size_t)NN * 48 * HW];   // concat [feats, pos, neg]
__device__ float g_t1[(size_t)NN * 32 * HW];   // conv1 out
__device__ float g_t2[(size_t)NN * 32 * HW];   // conv2 out
__device__ int   g_deg[NN];
__device__ int   g_nbr[NN * MAXD];
__device__ int   g_sgn[NN * MAXD];
// Weight images: [rep(hi/lo)][oc][k = tap*CIN + cin], row padded to KP elems
__device__ __nv_bfloat16 g_wb1[2 * 32 * 440];
__device__ __nv_bfloat16 g_wb2[2 * 32 * 296];
__device__ __nv_bfloat16 g_wb3[2 * 16 * 296];

// ---------------------------------------------------------------------------
__device__ __forceinline__ uint32_t smem_u32(const void* p) {
    uint32_t a;
    asm("{ .reg .u64 t; cvta.to.shared.u64 t, %1; cvt.u32.u64 %0, t; }" : "=r"(a) : "l"(p));
    return a;
}

#define LDSM_X4(r0, r1, r2, r3, addr) \
    asm volatile("ldmatrix.sync.aligned.m8n8.x4.shared.b16 {%0,%1,%2,%3}, [%4];" \
        : "=r"(r0), "=r"(r1), "=r"(r2), "=r"(r3) : "r"(addr))

#define MMA16816(d, a0, a1, a2, a3, b0, b1) \
    asm volatile("mma.sync.aligned.m16n8k16.row.col.f32.bf16.bf16.f32 " \
        "{%0,%1,%2,%3}, {%4,%5,%6,%7}, {%8,%9}, {%0,%1,%2,%3};" \
        : "+f"((d)[0]), "+f"((d)[1]), "+f"((d)[2]), "+f"((d)[3]) \
        : "r"(a0), "r"(a1), "r"(a2), "r"(a3), "r"(b0), "r"(b1))

#define STS128(addr, p0, p1, p2, p3) \
    asm volatile("st.shared.v4.b32 [%0], {%1,%2,%3,%4};" :: \
        "r"(addr), "r"(p0), "r"(p1), "r"(p2), "r"(p3))

// ---------------------------------------------------------------------------
__device__ __forceinline__ int detect_edge_mode(const unsigned* w) {
    bool any_floatish = false, odd_ok = true;
#pragma unroll
    for (int i = 0; i < 24; i++) {
        unsigned v = w[i];
        if (v >= 0x30000000u && v < 0xF0000000u) any_floatish = true;
        if ((i & 1) && !(v == 0u || v == 0xFFFFFFFFu)) odd_ok = false;
    }
    if (any_floatish) return 2;
    if (odd_ok) return 0;
    return 1;
}

// Fused: zero degree counters + build adjacency. One 1024-thread CTA.
__global__ void k_zeroadj(const void* __restrict__ edges_raw) {
    int tid = threadIdx.x;
    g_deg[tid] = 0;
    __syncthreads();
    int mode = detect_edge_mode((const unsigned*)edges_raw);
    for (int e = tid; e < NE; e += 1024) {
        int src, dst, sgn;
        if (mode == 0) {
            const long long* p = (const long long*)edges_raw;
            src = (int)p[3 * e]; sgn = (p[3 * e + 1] > 0) ? 1 : -1; dst = (int)p[3 * e + 2];
        } else if (mode == 1) {
            const int* p = (const int*)edges_raw;
            src = p[3 * e]; sgn = (p[3 * e + 1] > 0) ? 1 : -1; dst = p[3 * e + 2];
        } else {
            const float* p = (const float*)edges_raw;
            src = (int)p[3 * e]; sgn = (p[3 * e + 1] > 0.f) ? 1 : -1; dst = (int)p[3 * e + 2];
        }
        if ((unsigned)src >= NN || (unsigned)dst >= NN) continue;
        int q = atomicAdd(&g_deg[dst], 1);
        if (q < MAXD) { g_nbr[dst * MAXD + q] = src; g_sgn[dst * MAXD + q] = sgn; }
        q = atomicAdd(&g_deg[src], 1);
        if (q < MAXD) { g_nbr[src * MAXD + q] = dst; g_sgn[src * MAXD + q] = sgn; }
    }
}

__global__ __launch_bounds__(256) void k_build(const float* __restrict__ feats) {
    int n = blockIdx.x;
    __shared__ int s_nbr[MAXD], s_sgn[MAXD], s_deg;
    if (threadIdx.x == 0) s_deg = min(g_deg[n], MAXD);
    if (threadIdx.x < MAXD) {
        int nb = g_nbr[n * MAXD + threadIdx.x];
        s_nbr[threadIdx.x] = ((unsigned)nb < NN) ? nb : 0;
        s_sgn[threadIdx.x] = g_sgn[n * MAXD + threadIdx.x];
    }
    __syncthreads();
    int deg = s_deg;
    const float* f = feats + (size_t)n * (16 * HW);
    float* x = g_x + (size_t)n * (48 * HW);
    for (int j = threadIdx.x; j < 16 * HW; j += 256) {
        float self = f[j];
        float pos = 0.f, neg = 0.f;
        for (int d = 0; d < deg; d++) {
            float v = feats[(size_t)s_nbr[d] * (16 * HW) + j];
            if (s_sgn[d] > 0) pos += v; else neg += v;
        }
        x[j] = self; x[16 * HW + j] = pos; x[32 * HW + j] = neg;
    }
}

// ---------------------------------------------------------------------------
// Weight prep (fused): fp32 OIHW -> [rep][oc][k=tap*CIN+cin], rows padded to KP.
__device__ __forceinline__ void prep_one(const float* __restrict__ wgt,
                                         __nv_bfloat16* __restrict__ gB,
                                         int idx, int CIN, int COUT, int KP) {
    int rep = idx / (COUT * KP);
    int rem = idx % (COUT * KP);
    int oc = rem / KP, kp = rem % KP;
    __nv_bfloat16 val = __float2bfloat16(0.f);
    if (kp < 9 * CIN) {
        int tap = kp / CIN, cin = kp % CIN;
        float wv = wgt[(oc * CIN + cin) * 9 + tap];
        __nv_bfloat16 h = __float2bfloat16(wv);
        val = rep ? __float2bfloat16(wv - __bfloat162float(h)) : h;
    }
    gB[idx] = val;
}
#define PW1 (2 * 32 * 440)
#define PW2 (2 * 32 * 296)
#define PW3 (2 * 16 * 296)
__global__ void k_prep(const float* __restrict__ w1, const float* __restrict__ w2,
                       const float* __restrict__ w3) {
    int idx = blockIdx.x * 256 + threadIdx.x;
    if (idx < PW1) prep_one(w1, g_wb1, idx, 48, 32, 440);
    else if (idx < PW1 + PW2) prep_one(w2, g_wb2, idx - PW1, 32, 32, 296);
    else if (idx < PW1 + PW2 + PW3) prep_one(w3, g_wb3, idx - PW1 - PW2, 32, 16, 296);
}

// ---------------------------------------------------------------------------
// HMMA implicit-GEMM conv, plane layout, direct staging.
// CTA = 8 warps = 512 px (16 image rows). Warp = 64 px (4 m16 tiles).
// Planes P_hi/P_lo: [18 y][34 x][CP cin] bf16; ldmatrix reads directly.
// 3-term split: acc = A_hi*W_hi + A_lo*W_hi + A_hi*W_lo.
template <int CIN, int COUT, int KP>
__device__ void conv_body(const float* __restrict__ in,
                          const __nv_bfloat16* __restrict__ gB,
                          const float* __restrict__ bias,
                          float* __restrict__ out) {
    constexpr int CP  = CIN + 8;
    constexpr int NCG = CIN / 16;        // k16 groups per tap
    constexpr int NT  = COUT / 8;        // n8 tiles
    constexpr int NH  = NT / 2;          // B ldmatrix.x4 per rep (n16 each)
    constexpr int BB  = 2 * COUT * KP * 2;
    constexpr int PB  = 18 * 34 * CP * 2;
    constexpr int NGR = CIN / 8;         // staging channel groups

    extern __shared__ char smem[];
    char* Bs  = smem;
    char* Phi = smem + BB;
    char* Plo = Phi + PB;

    const int tid = threadIdx.x, wid = tid >> 5, lane = tid & 31;
    const uint32_t Bs_u  = smem_u32(Bs);
    const uint32_t Phi_u = smem_u32(Phi);
    const uint32_t Plo_u = smem_u32(Plo);

    // stage B once (persistent CTA)
    for (int i = tid; i < BB / 4; i += 256)
        ((uint32_t*)Bs)[i] = ((const uint32_t*)gB)[i];

    // A-fragment lane mapping (validated R7/R8)
    const int arl = (lane & 7) + ((lane >> 3) & 1) * 8;
    const int akb = lane >> 4;
    uint32_t pbase[4];
#pragma unroll
    for (int mt = 0; mt < 4; mt++) {
        int px = wid * 64 + mt * 16 + arl;
        int r = px >> 5, c = px & 31;
        pbase[mt] = (uint32_t)((r * 34 + c) * CP * 2 + akb * 16);
    }
    // B-fragment lane mapping (validated R7/R8)
    const int boc = ((lane >> 4) & 1) * 8 + (lane & 7);
    const int bkb = (lane >> 3) & 1;
    uint32_t bbase[2][NH];
#pragma unroll
    for (int rep = 0; rep < 2; rep++)
#pragma unroll
        for (int h = 0; h < NH; h++)
            bbase[rep][h] = Bs_u + (uint32_t)(rep * COUT * KP * 2 +
                             (h * 16 + boc) * KP * 2 + bkb * 16);
    // epilogue mapping + bias preload
    const int g_r = lane >> 2, tg = lane & 3;
    float bv[NT][2];
#pragma unroll
    for (int nt = 0; nt < NT; nt++) {
        bv[nt][0] = __ldg(bias + nt * 8 + tg * 2);
        bv[nt][1] = __ldg(bias + nt * 8 + tg * 2 + 1);
    }

    for (int tile = blockIdx.x; tile < NN * 2; tile += gridDim.x) {
        const int n = tile >> 1, y0 = (tile & 1) * 16;
        const float* inb = in + (size_t)n * CIN * HW;

        // ---- direct staging: thread = one (y,x), 8 channels per group ----
        for (int g = 0; g < NGR; g++) {
            const float* gp = inb + (size_t)(g * 8) * HW;
            for (int i = tid; i < 18 * 34; i += 256) {
                int y = i / 34, x = i % 34;
                int yi = y0 - 1 + y, xi = x - 1;
                bool ok = ((unsigned)yi < 32u) && ((unsigned)xi < 32u);
                int base = yi * 32 + xi;
                uint32_t hh[4], ll[4];
#pragma unroll
                for (int c2 = 0; c2 < 4; c2++) {
                    float v0 = ok ? gp[(size_t)(2 * c2) * HW + base] : 0.f;
                    float v1 = ok ? gp[(size_t)(2 * c2 + 1) * HW + base] : 0.f;
                    __nv_bfloat16 h0 = __float2bfloat16(v0);
                    __nv_bfloat16 h1 = __float2bfloat16(v1);
                    __nv_bfloat16 l0 = __float2bfloat16(v0 - __bfloat162float(h0));
                    __nv_bfloat16 l1 = __float2bfloat16(v1 - __bfloat162float(h1));
                    hh[c2] = (uint32_t)__bfloat16_as_ushort(h0) |
                             ((uint32_t)__bfloat16_as_ushort(h1) << 16);
                    ll[c2] = (uint32_t)__bfloat16_as_ushort(l0) |
                             ((uint32_t)__bfloat16_as_ushort(l1) << 16);
                }
                uint32_t off = (uint32_t)(i * CP * 2 + g * 16);
                STS128(Phi_u + off, hh[0], hh[1], hh[2], hh[3]);
                STS128(Plo_u + off, ll[0], ll[1], ll[2], ll[3]);
            }
        }
        __syncthreads();

        // ---- k loop: ldmatrix straight from planes, no syncs ----
        float acc[4][NT][4];
#pragma unroll
        for (int mt = 0; mt < 4; mt++)
#pragma unroll
            for (int nt = 0; nt < NT; nt++)
                acc[mt][nt][0] = acc[mt][nt][1] = acc[mt][nt][2] = acc[mt][nt][3] = 0.f;

#pragma unroll
        for (int tap = 0; tap < 9; tap++) {
            const uint32_t toff = (uint32_t)(((tap / 3) * 34 + (tap % 3)) * CP * 2);
#pragma unroll
            for (int cg = 0; cg < NCG; cg++) {
                const uint32_t aoff = toff + cg * 32;
                const uint32_t koff = (uint32_t)((tap * CIN + cg * 16) * 2);
                uint32_t ah[4][4], al[4][4];
#pragma unroll
                for (int mt = 0; mt < 4; mt++) {
                    LDSM_X4(ah[mt][0], ah[mt][1], ah[mt][2], ah[mt][3],
                            Phi_u + pbase[mt] + aoff);
                    LDSM_X4(al[mt][0], al[mt][1], al[mt][2], al[mt][3],
                            Plo_u + pbase[mt] + aoff);
                }
#pragma unroll
                for (int h = 0; h < NH; h++) {
                    uint32_t b0, b1, b2, b3, c0, c1, c2, c3;
                    LDSM_X4(b0, b1, b2, b3, bbase[0][h] + koff);  // w_hi
                    LDSM_X4(c0, c1, c2, c3, bbase[1][h] + koff);  // w_lo
#pragma unroll
                    for (int mt = 0; mt < 4; mt++) {
                        MMA16816(acc[mt][2*h],   ah[mt][0], ah[mt][1], ah[mt][2], ah[mt][3], b0, b1);
                        MMA16816(acc[mt][2*h+1], ah[mt][0], ah[mt][1], ah[mt][2], ah[mt][3], b2, b3);
                        MMA16816(acc[mt][2*h],   al[mt][0], al[mt][1], al[mt][2], al[mt][3], b0, b1);
                        MMA16816(acc[mt][2*h+1], al[mt][0], al[mt][1], al[mt][2], al[mt][3], b2, b3);
                        MMA16816(acc[mt][2*h],   ah[mt][0], ah[mt][1], ah[mt][2], ah[mt][3], c0, c1);
                        MMA16816(acc[mt][2*h+1], ah[mt][0], ah[mt][1], ah[mt][2], ah[mt][3], c2, c3);
                    }
                }
            }
        }

        // ---- epilogue ----
        {
            float* ob = out + (size_t)n * COUT * HW + y0 * 32;
#pragma unroll
            for (int mt = 0; mt < 4; mt++) {
                const int pA = wid * 64 + mt * 16 + g_r, pB = pA + 8;
#pragma unroll
                for (int nt = 0; nt < NT; nt++) {
                    int oc = nt * 8 + tg * 2;
                    float v;
                    v = acc[mt][nt][0] + bv[nt][0]; v = v > 0.f ? v : 0.1f * v; ob[(size_t)oc * HW + pA] = v;
                    v = acc[mt][nt][1] + bv[nt][1]; v = v > 0.f ? v : 0.1f * v; ob[(size_t)(oc + 1) * HW + pA] = v;
                    v = acc[mt][nt][2] + bv[nt][0]; v = v > 0.f ? v : 0.1f * v; ob[(size_t)oc * HW + pB] = v;
                    v = acc[mt][nt][3] + bv[nt][1]; v = v > 0.f ? v : 0.1f * v; ob[(size_t)(oc + 1) * HW + pB] = v;
                }
            }
        }
        __syncthreads();   // planes reused next tile
    }
}

__global__ __launch_bounds__(256, 1) void k_mconv1(const float* __restrict__ b) {
    conv_body<48, 32, 440>(g_x, g_wb1, b, g_t1);
}
__global__ __launch_bounds__(256, 1) void k_mconv2(const float* __restrict__ b) {
    conv_body<32, 32, 296>(g_t1, g_wb2, b, g_t2);
}
__global__ __launch_bounds__(256, 1) void k_mconv3(const float* __restrict__ b,
                                                   float* __restrict__ out) {
    conv_body<32, 16, 296>(g_t2, g_wb3, b, out);
}

// ---------------------------------------------------------------------------
static inline int smsz(int CIN, int COUT, int KP) {
    return 2 * COUT * KP * 2 + 2 * (18 * 34 * (CIN + 8) * 2);
}

extern "C" void kernel_launch(void* const* d_in, const int* in_sizes, int n_in,
                              void* d_out, int out_size) {
    const float* feats = nullptr;
    const void*  edges = nullptr;
    const float *w1 = nullptr, *b1 = nullptr, *w2 = nullptr, *b2 = nullptr;
    const float *w3 = nullptr, *b3 = nullptr;
    int b32_seen = 0;
    for (int i = 0; i < n_in; i++) {
        switch (in_sizes[i]) {
            case 16777216: feats = (const float*)d_in[i]; break;
            case 12288:
            case 24576:    edges = d_in[i]; break;
            case 13824:    w1 = (const float*)d_in[i]; break;
            case 9216:     w2 = (const float*)d_in[i]; break;
            case 4608:     w3 = (const float*)d_in[i]; break;
            case 32:       if (b32_seen++ == 0) b1 = (const float*)d_in[i];
                           else                 b2 = (const float*)d_in[i];
                           break;
            case 16:       b3 = (const float*)d_in[i]; break;
            default: break;
        }
    }
    if (!feats || !edges || !w1 || !b1 || !w2 || !b2 || !w3 || !b3) {
        feats = (const float*)d_in[0];
        edges = d_in[1];
        w1 = (const float*)d_in[2]; b1 = (const float*)d_in[3];
        w2 = (const float*)d_in[4]; b2 = (const float*)d_in[5];
        w3 = (const float*)d_in[6]; b3 = (const float*)d_in[7];
    }
    float* out = (float*)d_out;

    // Idempotent, not a stream op — safe on every call.
    cudaFuncSetAttribute(k_mconv1, cudaFuncAttributeMaxDynamicSharedMemorySize, smsz(48, 32, 440));
    cudaFuncSetAttribute(k_mconv2, cudaFuncAttributeMaxDynamicSharedMemorySize, smsz(32, 32, 296));
    cudaFuncSetAttribute(k_mconv3, cudaFuncAttributeMaxDynamicSharedMemorySize, smsz(32, 16, 296));

    k_zeroadj<<<1, 1024>>>(edges);
    k_prep<<<(PW1 + PW2 + PW3 + 255) / 256, 256>>>(w1, w2, w3);
    k_build<<<NN, 256>>>(feats);
    k_mconv1<<<148, 256, smsz(48, 32, 440)>>>(b1);
    k_mconv2<<<148, 256, smsz(32, 32, 296)>>>(b2);
    k_mconv3<<<148, 256, smsz(32, 16, 296)>>>(b3, out);
}

// round 10
// speedup vs baseline: 4.7804x; 1.1648x over previous
#include <cuda_runtime.h>
#include <cuda_bf16.h>
#include <cstdint>

// Problem constants
#define NN   1024
#define HW   1024
#define NE   4096
#define MAXD 64

// ---------------------------------------------------------------------------
// Scratch (__device__ globals)
__device__ float g_x [(size_t)NN * 48 * HW];   // concat [feats, pos, neg]
__device__ float g_t1[(size_t)NN * 32 * HW];   // conv1 out
__device__ float g_t2[(size_t)NN * 32 * HW];   // conv2 out
__device__ int   g_deg[NN];
__device__ int   g_nbr[NN * MAXD];
__device__ int   g_sgn[NN * MAXD];
// Weight images: [rep(hi/lo)][oc][k = tap*CIN + cin], row padded to KP elems
__device__ __nv_bfloat16 g_wb1[2 * 32 * 440];
__device__ __nv_bfloat16 g_wb2[2 * 32 * 296];
__device__ __nv_bfloat16 g_wb3[2 * 16 * 296];

// ---------------------------------------------------------------------------
__device__ __forceinline__ uint32_t smem_u32(const void* p) {
    uint32_t a;
    asm("{ .reg .u64 t; cvta.to.shared.u64 t, %1; cvt.u32.u64 %0, t; }" : "=r"(a) : "l"(p));
    return a;
}

#define LDSM_X4(r0, r1, r2, r3, addr) \
    asm volatile("ldmatrix.sync.aligned.m8n8.x4.shared.b16 {%0,%1,%2,%3}, [%4];" \
        : "=r"(r0), "=r"(r1), "=r"(r2), "=r"(r3) : "r"(addr))

#define MMA16816(d, a0, a1, a2, a3, b0, b1) \
    asm volatile("mma.sync.aligned.m16n8k16.row.col.f32.bf16.bf16.f32 " \
        "{%0,%1,%2,%3}, {%4,%5,%6,%7}, {%8,%9}, {%0,%1,%2,%3};" \
        : "+f"((d)[0]), "+f"((d)[1]), "+f"((d)[2]), "+f"((d)[3]) \
        : "r"(a0), "r"(a1), "r"(a2), "r"(a3), "r"(b0), "r"(b1))

#define STS128(addr, p0, p1, p2, p3) \
    asm volatile("st.shared.v4.b32 [%0], {%1,%2,%3,%4};" :: \
        "r"(addr), "r"(p0), "r"(p1), "r"(p2), "r"(p3))

// ---------------------------------------------------------------------------
__device__ __forceinline__ int detect_edge_mode(const unsigned* w) {
    bool any_floatish = false, odd_ok = true;
#pragma unroll
    for (int i = 0; i < 24; i++) {
        unsigned v = w[i];
        if (v >= 0x30000000u && v < 0xF0000000u) any_floatish = true;
        if ((i & 1) && !(v == 0u || v == 0xFFFFFFFFu)) odd_ok = false;
    }
    if (any_floatish) return 2;
    if (odd_ok) return 0;
    return 1;
}

// Fused: zero degree counters + build adjacency. One 1024-thread CTA.
__global__ void k_zeroadj(const void* __restrict__ edges_raw) {
    int tid = threadIdx.x;
    g_deg[tid] = 0;
    __syncthreads();
    int mode = detect_edge_mode((const unsigned*)edges_raw);
    for (int e = tid; e < NE; e += 1024) {
        int src, dst, sgn;
        if (mode == 0) {
            const long long* p = (const long long*)edges_raw;
            src = (int)p[3 * e]; sgn = (p[3 * e + 1] > 0) ? 1 : -1; dst = (int)p[3 * e + 2];
        } else if (mode == 1) {
            const int* p = (const int*)edges_raw;
            src = p[3 * e]; sgn = (p[3 * e + 1] > 0) ? 1 : -1; dst = p[3 * e + 2];
        } else {
            const float* p = (const float*)edges_raw;
            src = (int)p[3 * e]; sgn = (p[3 * e + 1] > 0.f) ? 1 : -1; dst = (int)p[3 * e + 2];
        }
        if ((unsigned)src >= NN || (unsigned)dst >= NN) continue;
        int q = atomicAdd(&g_deg[dst], 1);
        if (q < MAXD) { g_nbr[dst * MAXD + q] = src; g_sgn[dst * MAXD + q] = sgn; }
        q = atomicAdd(&g_deg[src], 1);
        if (q < MAXD) { g_nbr[src * MAXD + q] = dst; g_sgn[src * MAXD + q] = sgn; }
    }
}

__global__ __launch_bounds__(256) void k_build(const float* __restrict__ feats) {
    int n = blockIdx.x;
    __shared__ int s_nbr[MAXD], s_sgn[MAXD], s_deg;
    if (threadIdx.x == 0) s_deg = min(g_deg[n], MAXD);
    if (threadIdx.x < MAXD) {
        int nb = g_nbr[n * MAXD + threadIdx.x];
        s_nbr[threadIdx.x] = ((unsigned)nb < NN) ? nb : 0;
        s_sgn[threadIdx.x] = g_sgn[n * MAXD + threadIdx.x];
    }
    __syncthreads();
    int deg = s_deg;
    const float* f = feats + (size_t)n * (16 * HW);
    float* x = g_x + (size_t)n * (48 * HW);
    for (int j = threadIdx.x; j < 16 * HW; j += 256) {
        float self = f[j];
        float pos = 0.f, neg = 0.f;
        for (int d = 0; d < deg; d++) {
            float v = feats[(size_t)s_nbr[d] * (16 * HW) + j];
            if (s_sgn[d] > 0) pos += v; else neg += v;
        }
        x[j] = self; x[16 * HW + j] = pos; x[32 * HW + j] = neg;
    }
}

// ---------------------------------------------------------------------------
// Weight prep (fused): fp32 OIHW -> [rep][oc][k=tap*CIN+cin], rows padded to KP.
__device__ __forceinline__ void prep_one(const float* __restrict__ wgt,
                                         __nv_bfloat16* __restrict__ gB,
                                         int idx, int CIN, int COUT, int KP) {
    int rep = idx / (COUT * KP);
    int rem = idx % (COUT * KP);
    int oc = rem / KP, kp = rem % KP;
    __nv_bfloat16 val = __float2bfloat16(0.f);
    if (kp < 9 * CIN) {
        int tap = kp / CIN, cin = kp % CIN;
        float wv = wgt[(oc * CIN + cin) * 9 + tap];
        __nv_bfloat16 h = __float2bfloat16(wv);
        val = rep ? __float2bfloat16(wv - __bfloat162float(h)) : h;
    }
    gB[idx] = val;
}
#define PW1 (2 * 32 * 440)
#define PW2 (2 * 32 * 296)
#define PW3 (2 * 16 * 296)
__global__ void k_prep(const float* __restrict__ w1, const float* __restrict__ w2,
                       const float* __restrict__ w3) {
    int idx = blockIdx.x * 256 + threadIdx.x;
    if (idx < PW1) prep_one(w1, g_wb1, idx, 48, 32, 440);
    else if (idx < PW1 + PW2) prep_one(w2, g_wb2, idx - PW1, 32, 32, 296);
    else if (idx < PW1 + PW2 + PW3) prep_one(w3, g_wb3, idx - PW1 - PW2, 32, 16, 296);
}

// ---------------------------------------------------------------------------
// HMMA implicit-GEMM conv, plane layout, direct staging.
// CTA = 16 warps (512 thr) = 512 px (16 image rows). Warp = 32 px (2 m16 tiles).
// Planes P_hi/P_lo: [18 y][34 x][CP cin] bf16; ldmatrix reads directly.
// 3-term split: acc = A_hi*W_hi + A_lo*W_hi + A_hi*W_lo.
#define CTHREADS 512
template <int CIN, int COUT, int KP>
__device__ void conv_body(const float* __restrict__ in,
                          const __nv_bfloat16* __restrict__ gB,
                          const float* __restrict__ bias,
                          float* __restrict__ out) {
    constexpr int CP  = CIN + 8;
    constexpr int NCG = CIN / 16;        // k16 groups per tap
    constexpr int NT  = COUT / 8;        // n8 tiles
    constexpr int NH  = NT / 2;          // B ldmatrix.x4 per rep (n16 each)
    constexpr int BB  = 2 * COUT * KP * 2;
    constexpr int PB  = 18 * 34 * CP * 2;
    constexpr int NGR = CIN / 8;         // staging channel groups
    constexpr int MT  = 2;               // m16 tiles per warp

    extern __shared__ char smem[];
    char* Bs  = smem;
    char* Phi = smem + BB;
    char* Plo = Phi + PB;

    const int tid = threadIdx.x, wid = tid >> 5, lane = tid & 31;
    const uint32_t Bs_u  = smem_u32(Bs);
    const uint32_t Phi_u = smem_u32(Phi);
    const uint32_t Plo_u = smem_u32(Plo);

    // stage B once (persistent CTA)
    for (int i = tid; i < BB / 4; i += CTHREADS)
        ((uint32_t*)Bs)[i] = ((const uint32_t*)gB)[i];

    // A-fragment lane mapping (validated R7-R9)
    const int arl = (lane & 7) + ((lane >> 3) & 1) * 8;
    const int akb = lane >> 4;
    uint32_t pbase[MT];
#pragma unroll
    for (int mt = 0; mt < MT; mt++) {
        int px = wid * (MT * 16) + mt * 16 + arl;
        int r = px >> 5, c = px & 31;
        pbase[mt] = (uint32_t)((r * 34 + c) * CP * 2 + akb * 16);
    }
    // B-fragment lane mapping (validated R7-R9)
    const int boc = ((lane >> 4) & 1) * 8 + (lane & 7);
    const int bkb = (lane >> 3) & 1;
    uint32_t bbase[2][NH];
#pragma unroll
    for (int rep = 0; rep < 2; rep++)
#pragma unroll
        for (int h = 0; h < NH; h++)
            bbase[rep][h] = Bs_u + (uint32_t)(rep * COUT * KP * 2 +
                             (h * 16 + boc) * KP * 2 + bkb * 16);
    // epilogue mapping + bias preload
    const int g_r = lane >> 2, tg = lane & 3;
    float bv[NT][2];
#pragma unroll
    for (int nt = 0; nt < NT; nt++) {
        bv[nt][0] = __ldg(bias + nt * 8 + tg * 2);
        bv[nt][1] = __ldg(bias + nt * 8 + tg * 2 + 1);
    }

    for (int tile = blockIdx.x; tile < NN * 2; tile += gridDim.x) {
        const int n = tile >> 1, y0 = (tile & 1) * 16;
        const float* inb = in + (size_t)n * CIN * HW;

        // ---- direct staging: thread = one (y,x), 8 channels per group ----
        for (int g = 0; g < NGR; g++) {
            const float* gp = inb + (size_t)(g * 8) * HW;
            for (int i = tid; i < 18 * 34; i += CTHREADS) {
                int y = i / 34, x = i % 34;
                int yi = y0 - 1 + y, xi = x - 1;
                bool ok = ((unsigned)yi < 32u) && ((unsigned)xi < 32u);
                int base = yi * 32 + xi;
                uint32_t hh[4], ll[4];
#pragma unroll
                for (int c2 = 0; c2 < 4; c2++) {
                    float v0 = ok ? gp[(size_t)(2 * c2) * HW + base] : 0.f;
                    float v1 = ok ? gp[(size_t)(2 * c2 + 1) * HW + base] : 0.f;
                    __nv_bfloat16 h0 = __float2bfloat16(v0);
                    __nv_bfloat16 h1 = __float2bfloat16(v1);
                    __nv_bfloat16 l0 = __float2bfloat16(v0 - __bfloat162float(h0));
                    __nv_bfloat16 l1 = __float2bfloat16(v1 - __bfloat162float(h1));
                    hh[c2] = (uint32_t)__bfloat16_as_ushort(h0) |
                             ((uint32_t)__bfloat16_as_ushort(h1) << 16);
                    ll[c2] = (uint32_t)__bfloat16_as_ushort(l0) |
                             ((uint32_t)__bfloat16_as_ushort(l1) << 16);
                }
                uint32_t off = (uint32_t)(i * CP * 2 + g * 16);
                STS128(Phi_u + off, hh[0], hh[1], hh[2], hh[3]);
                STS128(Plo_u + off, ll[0], ll[1], ll[2], ll[3]);
            }
        }
        __syncthreads();

        // ---- k loop: ldmatrix straight from planes, no syncs ----
        float acc[MT][NT][4];
#pragma unroll
        for (int mt = 0; mt < MT; mt++)
#pragma unroll
            for (int nt = 0; nt < NT; nt++)
                acc[mt][nt][0] = acc[mt][nt][1] = acc[mt][nt][2] = acc[mt][nt][3] = 0.f;

#pragma unroll
        for (int tap = 0; tap < 9; tap++) {
            const uint32_t toff = (uint32_t)(((tap / 3) * 34 + (tap % 3)) * CP * 2);
#pragma unroll
            for (int cg = 0; cg < NCG; cg++) {
                const uint32_t aoff = toff + cg * 32;
                const uint32_t koff = (uint32_t)((tap * CIN + cg * 16) * 2);
                uint32_t ah[MT][4], al[MT][4];
#pragma unroll
                for (int mt = 0; mt < MT; mt++) {
                    LDSM_X4(ah[mt][0], ah[mt][1], ah[mt][2], ah[mt][3],
                            Phi_u + pbase[mt] + aoff);
                    LDSM_X4(al[mt][0], al[mt][1], al[mt][2], al[mt][3],
                            Plo_u + pbase[mt] + aoff);
                }
#pragma unroll
                for (int h = 0; h < NH; h++) {
                    uint32_t b0, b1, b2, b3, c0, c1, c2, c3;
                    LDSM_X4(b0, b1, b2, b3, bbase[0][h] + koff);  // w_hi
                    LDSM_X4(c0, c1, c2, c3, bbase[1][h] + koff);  // w_lo
#pragma unroll
                    for (int mt = 0; mt < MT; mt++) {
                        MMA16816(acc[mt][2*h],   ah[mt][0], ah[mt][1], ah[mt][2], ah[mt][3], b0, b1);
                        MMA16816(acc[mt][2*h+1], ah[mt][0], ah[mt][1], ah[mt][2], ah[mt][3], b2, b3);
                        MMA16816(acc[mt][2*h],   al[mt][0], al[mt][1], al[mt][2], al[mt][3], b0, b1);
                        MMA16816(acc[mt][2*h+1], al[mt][0], al[mt][1], al[mt][2], al[mt][3], b2, b3);
                        MMA16816(acc[mt][2*h],   ah[mt][0], ah[mt][1], ah[mt][2], ah[mt][3], c0, c1);
                        MMA16816(acc[mt][2*h+1], ah[mt][0], ah[mt][1], ah[mt][2], ah[mt][3], c2, c3);
                    }
                }
            }
        }

        // ---- epilogue ----
        {
            float* ob = out + (size_t)n * COUT * HW + y0 * 32;
#pragma unroll
            for (int mt = 0; mt < MT; mt++) {
                const int pA = wid * (MT * 16) + mt * 16 + g_r, pB = pA + 8;
#pragma unroll
                for (int nt = 0; nt < NT; nt++) {
                    int oc = nt * 8 + tg * 2;
                    float v;
                    v = acc[mt][nt][0] + bv[nt][0]; v = v > 0.f ? v : 0.1f * v; ob[(size_t)oc * HW + pA] = v;
                    v = acc[mt][nt][1] + bv[nt][1]; v = v > 0.f ? v : 0.1f * v; ob[(size_t)(oc + 1) * HW + pA] = v;
                    v = acc[mt][nt][2] + bv[nt][0]; v = v > 0.f ? v : 0.1f * v; ob[(size_t)oc * HW + pB] = v;
                    v = acc[mt][nt][3] + bv[nt][1]; v = v > 0.f ? v : 0.1f * v; ob[(size_t)(oc + 1) * HW + pB] = v;
                }
            }
        }
        __syncthreads();   // planes reused next tile
    }
}

__global__ __launch_bounds__(CTHREADS, 1) void k_mconv1(const float* __restrict__ b) {
    conv_body<48, 32, 440>(g_x, g_wb1, b, g_t1);
}
__global__ __launch_bounds__(CTHREADS, 1) void k_mconv2(const float* __restrict__ b) {
    conv_body<32, 32, 296>(g_t1, g_wb2, b, g_t2);
}
__global__ __launch_bounds__(CTHREADS, 1) void k_mconv3(const float* __restrict__ b,
                                                        float* __restrict__ out) {
    conv_body<32, 16, 296>(g_t2, g_wb3, b, out);
}

// ---------------------------------------------------------------------------
static inline int smsz(int CIN, int COUT, int KP) {
    return 2 * COUT * KP * 2 + 2 * (18 * 34 * (CIN + 8) * 2);
}

extern "C" void kernel_launch(void* const* d_in, const int* in_sizes, int n_in,
                              void* d_out, int out_size) {
    const float* feats = nullptr;
    const void*  edges = nullptr;
    const float *w1 = nullptr, *b1 = nullptr, *w2 = nullptr, *b2 = nullptr;
    const float *w3 = nullptr, *b3 = nullptr;
    int b32_seen = 0;
    for (int i = 0; i < n_in; i++) {
        switch (in_sizes[i]) {
            case 16777216: feats = (const float*)d_in[i]; break;
            case 12288:
            case 24576:    edges = d_in[i]; break;
            case 13824:    w1 = (const float*)d_in[i]; break;
            case 9216:     w2 = (const float*)d_in[i]; break;
            case 4608:     w3 = (const float*)d_in[i]; break;
            case 32:       if (b32_seen++ == 0) b1 = (const float*)d_in[i];
                           else                 b2 = (const float*)d_in[i];
                           break;
            case 16:       b3 = (const float*)d_in[i]; break;
            default: break;
        }
    }
    if (!feats || !edges || !w1 || !b1 || !w2 || !b2 || !w3 || !b3) {
        feats = (const float*)d_in[0];
        edges = d_in[1];
        w1 = (const float*)d_in[2]; b1 = (const float*)d_in[3];
        w2 = (const float*)d_in[4]; b2 = (const float*)d_in[5];
        w3 = (const float*)d_in[6]; b3 = (const float*)d_in[7];
    }
    float* out = (float*)d_out;

    // Idempotent, not a stream op — safe on every call.
    cudaFuncSetAttribute(k_mconv1, cudaFuncAttributeMaxDynamicSharedMemorySize, smsz(48, 32, 440));
    cudaFuncSetAttribute(k_mconv2, cudaFuncAttributeMaxDynamicSharedMemorySize, smsz(32, 32, 296));
    cudaFuncSetAttribute(k_mconv3, cudaFuncAttributeMaxDynamicSharedMemorySize, smsz(32, 16, 296));

    k_zeroadj<<<1, 1024>>>(edges);
    k_prep<<<(PW1 + PW2 + PW3 + 255) / 256, 256>>>(w1, w2, w3);
    k_build<<<NN, 256>>>(feats);
    k_mconv1<<<148, CTHREADS, smsz(48, 32, 440)>>>(b1);
    k_mconv2<<<148, CTHREADS, smsz(32, 32, 296)>>>(b2);
    k_mconv3<<<148, CTHREADS, smsz(32, 16, 296)>>>(b3, out);
}

// round 11
// speedup vs baseline: 5.3639x; 1.1221x over previous
#include <cuda_runtime.h>
#include <cuda_bf16.h>
#include <cstdint>

// Problem constants
#define NN   1024
#define HW   1024
#define NE   4096
#define MAXD 64

// ---------------------------------------------------------------------------
// Scratch (__device__ globals)
__device__ float g_x [(size_t)NN * 48 * HW];   // concat [feats, pos, neg]
__device__ float g_t1[(size_t)NN * 32 * HW];   // conv1 out
__device__ float g_t2[(size_t)NN * 32 * HW];   // conv2 out
__device__ int   g_deg[NN];
__device__ int   g_nbr[NN * MAXD];
__device__ int   g_sgn[NN * MAXD];
// Weight images: [rep(hi/lo)][oc][k = tap*CIN + cin], row padded to KP elems
__device__ __nv_bfloat16 g_wb1[2 * 32 * 440];
__device__ __nv_bfloat16 g_wb2[2 * 32 * 296];
__device__ __nv_bfloat16 g_wb3[2 * 16 * 296];

// ---------------------------------------------------------------------------
__device__ __forceinline__ uint32_t smem_u32(const void* p) {
    uint32_t a;
    asm("{ .reg .u64 t; cvta.to.shared.u64 t, %1; cvt.u32.u64 %0, t; }" : "=r"(a) : "l"(p));
    return a;
}

#define LDSM_X4(r0, r1, r2, r3, addr) \
    asm volatile("ldmatrix.sync.aligned.m8n8.x4.shared.b16 {%0,%1,%2,%3}, [%4];" \
        : "=r"(r0), "=r"(r1), "=r"(r2), "=r"(r3) : "r"(addr))

#define MMA16816(d, a0, a1, a2, a3, b0, b1) \
    asm volatile("mma.sync.aligned.m16n8k16.row.col.f32.bf16.bf16.f32 " \
        "{%0,%1,%2,%3}, {%4,%5,%6,%7}, {%8,%9}, {%0,%1,%2,%3};" \
        : "+f"((d)[0]), "+f"((d)[1]), "+f"((d)[2]), "+f"((d)[3]) \
        : "r"(a0), "r"(a1), "r"(a2), "r"(a3), "r"(b0), "r"(b1))

#define STS128(addr, p0, p1, p2, p3) \
    asm volatile("st.shared.v4.b32 [%0], {%1,%2,%3,%4};" :: \
        "r"(addr), "r"(p0), "r"(p1), "r"(p2), "r"(p3))

// ---------------------------------------------------------------------------
__device__ __forceinline__ int detect_edge_mode(const unsigned* w) {
    bool any_floatish = false, odd_ok = true;
#pragma unroll
    for (int i = 0; i < 24; i++) {
        unsigned v = w[i];
        if (v >= 0x30000000u && v < 0xF0000000u) any_floatish = true;
        if ((i & 1) && !(v == 0u || v == 0xFFFFFFFFu)) odd_ok = false;
    }
    if (any_floatish) return 2;
    if (odd_ok) return 0;
    return 1;
}

// Fused: zero degree counters + build adjacency. One 1024-thread CTA.
__global__ void k_zeroadj(const void* __restrict__ edges_raw) {
    int tid = threadIdx.x;
    g_deg[tid] = 0;
    __syncthreads();
    int mode = detect_edge_mode((const unsigned*)edges_raw);
    for (int e = tid; e < NE; e += 1024) {
        int src, dst, sgn;
        if (mode == 0) {
            const long long* p = (const long long*)edges_raw;
            src = (int)p[3 * e]; sgn = (p[3 * e + 1] > 0) ? 1 : -1; dst = (int)p[3 * e + 2];
        } else if (mode == 1) {
            const int* p = (const int*)edges_raw;
            src = p[3 * e]; sgn = (p[3 * e + 1] > 0) ? 1 : -1; dst = p[3 * e + 2];
        } else {
            const float* p = (const float*)edges_raw;
            src = (int)p[3 * e]; sgn = (p[3 * e + 1] > 0.f) ? 1 : -1; dst = (int)p[3 * e + 2];
        }
        if ((unsigned)src >= NN || (unsigned)dst >= NN) continue;
        int q = atomicAdd(&g_deg[dst], 1);
        if (q < MAXD) { g_nbr[dst * MAXD + q] = src; g_sgn[dst * MAXD + q] = sgn; }
        q = atomicAdd(&g_deg[src], 1);
        if (q < MAXD) { g_nbr[src * MAXD + q] = dst; g_sgn[src * MAXD + q] = sgn; }
    }
}

__global__ __launch_bounds__(256) void k_build(const float* __restrict__ feats) {
    int n = blockIdx.x;
    __shared__ int s_nbr[MAXD], s_sgn[MAXD], s_deg;
    if (threadIdx.x == 0) s_deg = min(g_deg[n], MAXD);
    if (threadIdx.x < MAXD) {
        int nb = g_nbr[n * MAXD + threadIdx.x];
        s_nbr[threadIdx.x] = ((unsigned)nb < NN) ? nb : 0;
        s_sgn[threadIdx.x] = g_sgn[n * MAXD + threadIdx.x];
    }
    __syncthreads();
    int deg = s_deg;
    const float4* f4 = (const float4*)(feats + (size_t)n * (16 * HW));
    float4* x4 = (float4*)(g_x + (size_t)n * (48 * HW));
    for (int j = threadIdx.x; j < 4 * HW; j += 256) {
        float4 self = f4[j];
        float4 pos = {0.f, 0.f, 0.f, 0.f}, neg = {0.f, 0.f, 0.f, 0.f};
        for (int d = 0; d < deg; d++) {
            const float4 v = ((const float4*)(feats + (size_t)s_nbr[d] * (16 * HW)))[j];
            if (s_sgn[d] > 0) {
                pos.x += v.x; pos.y += v.y; pos.z += v.z; pos.w += v.w;
            } else {
                neg.x += v.x; neg.y += v.y; neg.z += v.z; neg.w += v.w;
            }
        }
        x4[j] = self; x4[4 * HW + j] = pos; x4[8 * HW + j] = neg;
    }
}

// ---------------------------------------------------------------------------
// Weight prep (fused): fp32 OIHW -> [rep][oc][k=tap*CIN+cin], rows padded to KP.
__device__ __forceinline__ void prep_one(const float* __restrict__ wgt,
                                         __nv_bfloat16* __restrict__ gB,
                                         int idx, int CIN, int COUT, int KP) {
    int rep = idx / (COUT * KP);
    int rem = idx % (COUT * KP);
    int oc = rem / KP, kp = rem % KP;
    __nv_bfloat16 val = __float2bfloat16(0.f);
    if (kp < 9 * CIN) {
        int tap = kp / CIN, cin = kp % CIN;
        float wv = wgt[(oc * CIN + cin) * 9 + tap];
        __nv_bfloat16 h = __float2bfloat16(wv);
        val = rep ? __float2bfloat16(wv - __bfloat162float(h)) : h;
    }
    gB[idx] = val;
}
#define PW1 (2 * 32 * 440)
#define PW2 (2 * 32 * 296)
#define PW3 (2 * 16 * 296)
__global__ void k_prep(const float* __restrict__ w1, const float* __restrict__ w2,
                       const float* __restrict__ w3) {
    int idx = blockIdx.x * 256 + threadIdx.x;
    if (idx < PW1) prep_one(w1, g_wb1, idx, 48, 32, 440);
    else if (idx < PW1 + PW2) prep_one(w2, g_wb2, idx - PW1, 32, 32, 296);
    else if (idx < PW1 + PW2 + PW3) prep_one(w3, g_wb3, idx - PW1 - PW2, 32, 16, 296);
}

// ---------------------------------------------------------------------------
// HMMA implicit-GEMM conv, plane layout, double-buffered fragment pipeline.
// Tile = ROWS image rows (ROWS*32 px), NWARP warps, warp = 32 px (MT=2 m16).
// Planes P_hi/P_lo: [ROWS+2][34][CP] bf16; ldmatrix reads directly.
// 3-term split: acc = A_hi*W_hi + A_lo*W_hi + A_hi*W_lo.

// Fragment load for iteration `itc` into buffer `bufc` (both unroll-constants).
#define LOADIT(bufc, itc) do { \
    const int _tap = (itc) / NCG, _cg = (itc) % NCG; \
    const uint32_t _ao = (uint32_t)(((((_tap / 3) * 34) + (_tap % 3)) * CP + _cg * 16) * 2); \
    const uint32_t _ko = (uint32_t)((_tap * CIN + _cg * 16) * 2); \
    LDSM_X4(ah[bufc][0][0], ah[bufc][0][1], ah[bufc][0][2], ah[bufc][0][3], Phi_u + pb0 + _ao); \
    LDSM_X4(ah[bufc][1][0], ah[bufc][1][1], ah[bufc][1][2], ah[bufc][1][3], Phi_u + pb1 + _ao); \
    LDSM_X4(al[bufc][0][0], al[bufc][0][1], al[bufc][0][2], al[bufc][0][3], Plo_u + pb0 + _ao); \
    LDSM_X4(al[bufc][1][0], al[bufc][1][1], al[bufc][1][2], al[bufc][1][3], Plo_u + pb1 + _ao); \
    _Pragma("unroll") \
    for (int _h = 0; _h < NH; _h++) { \
        LDSM_X4(bh[bufc][_h][0], bh[bufc][_h][1], bh[bufc][_h][2], bh[bufc][_h][3], bb0[_h] + _ko); \
        LDSM_X4(bl[bufc][_h][0], bl[bufc][_h][1], bl[bufc][_h][2], bl[bufc][_h][3], bb1[_h] + _ko); \
    } \
} while (0)

#define MMAIT(bufc) do { \
    _Pragma("unroll") \
    for (int _h = 0; _h < NH; _h++) { \
        _Pragma("unroll") \
        for (int _mt = 0; _mt < 2; _mt++) { \
            MMA16816(acc[_mt][2*_h],   ah[bufc][_mt][0], ah[bufc][_mt][1], ah[bufc][_mt][2], ah[bufc][_mt][3], bh[bufc][_h][0], bh[bufc][_h][1]); \
            MMA16816(acc[_mt][2*_h+1], ah[bufc][_mt][0], ah[bufc][_mt][1], ah[bufc][_mt][2], ah[bufc][_mt][3], bh[bufc][_h][2], bh[bufc][_h][3]); \
            MMA16816(acc[_mt][2*_h],   al[bufc][_mt][0], al[bufc][_mt][1], al[bufc][_mt][2], al[bufc][_mt][3], bh[bufc][_h][0], bh[bufc][_h][1]); \
            MMA16816(acc[_mt][2*_h+1], al[bufc][_mt][0], al[bufc][_mt][1], al[bufc][_mt][2], al[bufc][_mt][3], bh[bufc][_h][2], bh[bufc][_h][3]); \
            MMA16816(acc[_mt][2*_h],   ah[bufc][_mt][0], ah[bufc][_mt][1], ah[bufc][_mt][2], ah[bufc][_mt][3], bl[bufc][_h][0], bl[bufc][_h][1]); \
            MMA16816(acc[_mt][2*_h+1], ah[bufc][_mt][0], ah[bufc][_mt][1], ah[bufc][_mt][2], ah[bufc][_mt][3], bl[bufc][_h][2], bl[bufc][_h][3]); \
        } \
    } \
} while (0)

template <int CIN, int COUT, int ROWS, int NWARP, int KP>
__device__ __forceinline__ void conv_body(const float* __restrict__ in,
                          const __nv_bfloat16* __restrict__ gB,
                          const float* __restrict__ bias,
                          float* __restrict__ out) {
    constexpr int CP  = CIN + 8;
    constexpr int NCG = CIN / 16;
    constexpr int NT  = COUT / 8;
    constexpr int NH  = NT / 2;
    constexpr int BB  = 2 * COUT * KP * 2;
    constexpr int PB  = (ROWS + 2) * 34 * CP * 2;
    constexpr int NGR = CIN / 8;
    constexpr int NTHR = NWARP * 32;
    constexpr int NITER = 9 * NCG;
    constexpr int TPI = 32 / ROWS;

    extern __shared__ char smem[];
    char* Bs  = smem;
    char* Phi = smem + BB;
    char* Plo = Phi + PB;

    const int tid = threadIdx.x, wid = tid >> 5, lane = tid & 31;
    const uint32_t Bs_u  = smem_u32(Bs);
    const uint32_t Phi_u = smem_u32(Phi);
    const uint32_t Plo_u = smem_u32(Plo);

    // stage B once (persistent CTA)
    for (int i = tid; i < BB / 4; i += NTHR)
        ((uint32_t*)Bs)[i] = ((const uint32_t*)gB)[i];

    // A-fragment lane mapping (validated R7-R10)
    const int arl = (lane & 7) + ((lane >> 3) & 1) * 8;
    const int akb = lane >> 4;
    uint32_t pb0, pb1;
    {
        int px = wid * 32 + arl;
        pb0 = (uint32_t)((((px >> 5) * 34) + (px & 31)) * CP * 2 + akb * 16);
        px += 16;
        pb1 = (uint32_t)((((px >> 5) * 34) + (px & 31)) * CP * 2 + akb * 16);
    }
    // B-fragment lane mapping (validated R7-R10)
    const int boc = ((lane >> 4) & 1) * 8 + (lane & 7);
    const int bkb = (lane >> 3) & 1;
    uint32_t bb0[NH], bb1[NH];
#pragma unroll
    for (int h = 0; h < NH; h++) {
        bb0[h] = Bs_u + (uint32_t)((h * 16 + boc) * KP * 2 + bkb * 16);
        bb1[h] = bb0[h] + (uint32_t)(COUT * KP * 2);
    }
    const int g_r = lane >> 2, tg = lane & 3;

    for (int tile = blockIdx.x; tile < NN * TPI; tile += gridDim.x) {
        const int n = tile / TPI, y0 = (tile % TPI) * ROWS;
        const float* inb = in + (size_t)n * CIN * HW;

        // ---- direct staging: thread = one (y,x), 8 channels per group ----
        for (int g = 0; g < NGR; g++) {
            const float* gp = inb + (size_t)(g * 8) * HW;
            for (int i = tid; i < (ROWS + 2) * 34; i += NTHR) {
                int y = i / 34, x = i % 34;
                int yi = y0 - 1 + y, xi = x - 1;
                bool ok = ((unsigned)yi < 32u) && ((unsigned)xi < 32u);
                int base = yi * 32 + xi;
                uint32_t hh[4], ll[4];
#pragma unroll
                for (int c2 = 0; c2 < 4; c2++) {
                    float v0 = ok ? gp[(size_t)(2 * c2) * HW + base] : 0.f;
                    float v1 = ok ? gp[(size_t)(2 * c2 + 1) * HW + base] : 0.f;
                    __nv_bfloat16 h0 = __float2bfloat16(v0);
                    __nv_bfloat16 h1 = __float2bfloat16(v1);
                    __nv_bfloat16 l0 = __float2bfloat16(v0 - __bfloat162float(h0));
                    __nv_bfloat16 l1 = __float2bfloat16(v1 - __bfloat162float(h1));
                    hh[c2] = (uint32_t)__bfloat16_as_ushort(h0) |
                             ((uint32_t)__bfloat16_as_ushort(h1) << 16);
                    ll[c2] = (uint32_t)__bfloat16_as_ushort(l0) |
                             ((uint32_t)__bfloat16_as_ushort(l1) << 16);
                }
                uint32_t off = (uint32_t)(i * CP * 2 + g * 16);
                STS128(Phi_u + off, hh[0], hh[1], hh[2], hh[3]);
                STS128(Plo_u + off, ll[0], ll[1], ll[2], ll[3]);
            }
        }
        __syncthreads();

        // ---- k loop: double-buffered fragments, no syncs ----
        float acc[2][NT][4];
#pragma unroll
        for (int mt = 0; mt < 2; mt++)
#pragma unroll
            for (int nt = 0; nt < NT; nt++)
                acc[mt][nt][0] = acc[mt][nt][1] = acc[mt][nt][2] = acc[mt][nt][3] = 0.f;

        uint32_t ah[2][2][4], al[2][2][4], bh[2][NH][4], bl[2][NH][4];
        LOADIT(0, 0);
#pragma unroll
        for (int it = 0; it < NITER; it++) {
            const int buf = it & 1;
            if (it + 1 < NITER) {
                if (buf == 0) LOADIT(1, it + 1);
                else          LOADIT(0, it + 1);
            }
            if (buf == 0) MMAIT(0);
            else          MMAIT(1);
        }

        // ---- epilogue ----
        {
            float* ob = out + (size_t)n * COUT * HW + y0 * 32;
#pragma unroll
            for (int mt = 0; mt < 2; mt++) {
                const int pA = wid * 32 + mt * 16 + g_r, pB = pA + 8;
#pragma unroll
                for (int nt = 0; nt < NT; nt++) {
                    int oc = nt * 8 + tg * 2;
                    float bv0 = __ldg(bias + oc), bv1 = __ldg(bias + oc + 1);
                    float v;
                    v = acc[mt][nt][0] + bv0; v = v > 0.f ? v : 0.1f * v; ob[(size_t)oc * HW + pA] = v;
                    v = acc[mt][nt][1] + bv1; v = v > 0.f ? v : 0.1f * v; ob[(size_t)(oc + 1) * HW + pA] = v;
                    v = acc[mt][nt][2] + bv0; v = v > 0.f ? v : 0.1f * v; ob[(size_t)oc * HW + pB] = v;
                    v = acc[mt][nt][3] + bv1; v = v > 0.f ? v : 0.1f * v; ob[(size_t)(oc + 1) * HW + pB] = v;
                }
            }
        }
        __syncthreads();   // planes reused next tile
    }
}

__global__ __launch_bounds__(512, 1) void k_mconv1(const float* __restrict__ b) {
    conv_body<48, 32, 16, 16, 440>(g_x, g_wb1, b, g_t1);
}
__global__ __launch_bounds__(256, 2) void k_mconv2(const float* __restrict__ b) {
    conv_body<32, 32, 8, 8, 296>(g_t1, g_wb2, b, g_t2);
}
__global__ __launch_bounds__(256, 2) void k_mconv3(const float* __restrict__ b,
                                                   float* __restrict__ out) {
    conv_body<32, 16, 8, 8, 296>(g_t2, g_wb3, b, out);
}

// ---------------------------------------------------------------------------
static inline int smsz(int CIN, int COUT, int KP, int ROWS) {
    return 2 * COUT * KP * 2 + 2 * ((ROWS + 2) * 34 * (CIN + 8) * 2);
}

extern "C" void kernel_launch(void* const* d_in, const int* in_sizes, int n_in,
                              void* d_out, int out_size) {
    const float* feats = nullptr;
    const void*  edges = nullptr;
    const float *w1 = nullptr, *b1 = nullptr, *w2 = nullptr, *b2 = nullptr;
    const float *w3 = nullptr, *b3 = nullptr;
    int b32_seen = 0;
    for (int i = 0; i < n_in; i++) {
        switch (in_sizes[i]) {
            case 16777216: feats = (const float*)d_in[i]; break;
            case 12288:
            case 24576:    edges = d_in[i]; break;
            case 13824:    w1 = (const float*)d_in[i]; break;
            case 9216:     w2 = (const float*)d_in[i]; break;
            case 4608:     w3 = (const float*)d_in[i]; break;
            case 32:       if (b32_seen++ == 0) b1 = (const float*)d_in[i];
                           else                 b2 = (const float*)d_in[i];
                           break;
            case 16:       b3 = (const float*)d_in[i]; break;
            default: break;
        }
    }
    if (!feats || !edges || !w1 || !b1 || !w2 || !b2 || !w3 || !b3) {
        feats = (const float*)d_in[0];
        edges = d_in[1];
        w1 = (const float*)d_in[2]; b1 = (const float*)d_in[3];
        w2 = (const float*)d_in[4]; b2 = (const float*)d_in[5];
        w3 = (const float*)d_in[6]; b3 = (const float*)d_in[7];
    }
    float* out = (float*)d_out;

    // Idempotent, not a stream op — safe on every call.
    cudaFuncSetAttribute(k_mconv1, cudaFuncAttributeMaxDynamicSharedMemorySize, smsz(48, 32, 440, 16));
    cudaFuncSetAttribute(k_mconv2, cudaFuncAttributeMaxDynamicSharedMemorySize, smsz(32, 32, 296, 8));
    cudaFuncSetAttribute(k_mconv3, cudaFuncAttributeMaxDynamicSharedMemorySize, smsz(32, 16, 296, 8));

    k_zeroadj<<<1, 1024>>>(edges);
    k_prep<<<(PW1 + PW2 + PW3 + 255) / 256, 256>>>(w1, w2, w3);
    k_build<<<NN, 256>>>(feats);
    k_mconv1<<<148, 512, smsz(48, 32, 440, 16)>>>(b1);
    k_mconv2<<<296, 256, smsz(32, 32, 296, 8)>>>(b2);
    k_mconv3<<<296, 256, smsz(32, 16, 296, 8)>>>(b3, out);
}

// round 12
// speedup vs baseline: 6.1116x; 1.1394x over previous
#include <cuda_runtime.h>
#include <cuda_bf16.h>
#include <cstdint>

// Problem constants
#define NN   1024
#define HW   1024
#define NE   4096
#define MAXD 64

// ---------------------------------------------------------------------------
// Scratch (__device__ globals). All conv tensors pre-split bf16 hi/lo,
// channel-last: arr[n][px][c/2] as u32 = (bf16 c | bf16 c+1 << 16).
__device__ uint32_t g_xh[(size_t)NN * HW * 24];   // x  hi, 48ch -> 24 u32
__device__ uint32_t g_xl[(size_t)NN * HW * 24];   // x  lo
__device__ uint32_t g_t1h[(size_t)NN * HW * 16];  // t1 hi, 32ch
__device__ uint32_t g_t1l[(size_t)NN * HW * 16];
__device__ uint32_t g_t2h[(size_t)NN * HW * 16];
__device__ uint32_t g_t2l[(size_t)NN * HW * 16];
__device__ int g_deg[NN];
__device__ int g_nbr[NN * MAXD];
__device__ int g_sgn[NN * MAXD];
// Weight images: [rep(hi/lo)][oc][k = tap*CIN + cin], rows padded to KP elems
__device__ __nv_bfloat16 g_wb1[2 * 32 * 440];
__device__ __nv_bfloat16 g_wb2[2 * 32 * 296];
__device__ __nv_bfloat16 g_wb3[2 * 16 * 296];

// ---------------------------------------------------------------------------
__device__ __forceinline__ uint32_t smem_u32(const void* p) {
    uint32_t a;
    asm("{ .reg .u64 t; cvta.to.shared.u64 t, %1; cvt.u32.u64 %0, t; }" : "=r"(a) : "l"(p));
    return a;
}

#define LDSM_X4(r0, r1, r2, r3, addr) \
    asm volatile("ldmatrix.sync.aligned.m8n8.x4.shared.b16 {%0,%1,%2,%3}, [%4];" \
        : "=r"(r0), "=r"(r1), "=r"(r2), "=r"(r3) : "r"(addr))

#define MMA16816(d, a0, a1, a2, a3, b0, b1) \
    asm volatile("mma.sync.aligned.m16n8k16.row.col.f32.bf16.bf16.f32 " \
        "{%0,%1,%2,%3}, {%4,%5,%6,%7}, {%8,%9}, {%0,%1,%2,%3};" \
        : "+f"((d)[0]), "+f"((d)[1]), "+f"((d)[2]), "+f"((d)[3]) \
        : "r"(a0), "r"(a1), "r"(a2), "r"(a3), "r"(b0), "r"(b1))

#define CP_ASYNC16(dst, src, sz) \
    asm volatile("cp.async.cg.shared.global [%0], [%1], 16, %2;" \
        :: "r"(dst), "l"(src), "r"(sz))
#define CP_COMMIT() asm volatile("cp.async.commit_group;" ::: "memory")
#define CP_WAIT0()  asm volatile("cp.async.wait_group 0;" ::: "memory")

// Split two floats into packed bf16 hi/lo pair words.
__device__ __forceinline__ void split2(float v0, float v1, uint32_t& hi, uint32_t& lo) {
    __nv_bfloat16 h0 = __float2bfloat16(v0), h1 = __float2bfloat16(v1);
    __nv_bfloat16 l0 = __float2bfloat16(v0 - __bfloat162float(h0));
    __nv_bfloat16 l1 = __float2bfloat16(v1 - __bfloat162float(h1));
    hi = (uint32_t)__bfloat16_as_ushort(h0) | ((uint32_t)__bfloat16_as_ushort(h1) << 16);
    lo = (uint32_t)__bfloat16_as_ushort(l0) | ((uint32_t)__bfloat16_as_ushort(l1) << 16);
}

// ---------------------------------------------------------------------------
__device__ __forceinline__ int detect_edge_mode(const unsigned* w) {
    bool any_floatish = false, odd_ok = true;
#pragma unroll
    for (int i = 0; i < 24; i++) {
        unsigned v = w[i];
        if (v >= 0x30000000u && v < 0xF0000000u) any_floatish = true;
        if ((i & 1) && !(v == 0u || v == 0xFFFFFFFFu)) odd_ok = false;
    }
    if (any_floatish) return 2;
    if (odd_ok) return 0;
    return 1;
}

// Fused: zero degree counters + build adjacency. One 1024-thread CTA.
__global__ void k_zeroadj(const void* __restrict__ edges_raw) {
    int tid = threadIdx.x;
    g_deg[tid] = 0;
    __syncthreads();
    int mode = detect_edge_mode((const unsigned*)edges_raw);
    for (int e = tid; e < NE; e += 1024) {
        int src, dst, sgn;
        if (mode == 0) {
            const long long* p = (const long long*)edges_raw;
            src = (int)p[3 * e]; sgn = (p[3 * e + 1] > 0) ? 1 : -1; dst = (int)p[3 * e + 2];
        } else if (mode == 1) {
            const int* p = (const int*)edges_raw;
            src = p[3 * e]; sgn = (p[3 * e + 1] > 0) ? 1 : -1; dst = p[3 * e + 2];
        } else {
            const float* p = (const float*)edges_raw;
            src = (int)p[3 * e]; sgn = (p[3 * e + 1] > 0.f) ? 1 : -1; dst = (int)p[3 * e + 2];
        }
        if ((unsigned)src >= NN || (unsigned)dst >= NN) continue;
        int q = atomicAdd(&g_deg[dst], 1);
        if (q < MAXD) { g_nbr[dst * MAXD + q] = src; g_sgn[dst * MAXD + q] = sgn; }
        q = atomicAdd(&g_deg[src], 1);
        if (q < MAXD) { g_nbr[src * MAXD + q] = dst; g_sgn[src * MAXD + q] = sgn; }
    }
}

// Pool + concat + hi/lo split, channel-last output. One CTA per node.
// Pixels in chunks of 128; threads split: tid<128 -> ch 0..7, else ch 8..15.
__global__ __launch_bounds__(256) void k_build(const float* __restrict__ feats) {
    int n = blockIdx.x;
    __shared__ int s_nbr[MAXD], s_sgn[MAXD], s_deg;
    __shared__ uint32_t sh[128 * 25], sl[128 * 25];
    if (threadIdx.x == 0) s_deg = min(g_deg[n], MAXD);
    if (threadIdx.x < MAXD) {
        int nb = g_nbr[n * MAXD + threadIdx.x];
        s_nbr[threadIdx.x] = ((unsigned)nb < NN) ? nb : 0;
        s_sgn[threadIdx.x] = g_sgn[n * MAXD + threadIdx.x];
    }
    __syncthreads();
    const int deg = s_deg;
    const int half = threadIdx.x >> 7, p_l = threadIdx.x & 127;
    const int cbase = half * 8;
    for (int chunk = 0; chunk < 8; chunk++) {
        int p = chunk * 128 + p_l;
#pragma unroll
        for (int cp = 0; cp < 4; cp++) {
            int c0 = cbase + 2 * cp;
            const float* f0 = feats + (size_t)n * 16384 + (size_t)c0 * 1024 + p;
            float s0 = f0[0], s1 = f0[1024];
            float p0 = 0.f, p1 = 0.f, q0 = 0.f, q1 = 0.f;
            for (int d = 0; d < deg; d++) {
                const float* fb = feats + (size_t)s_nbr[d] * 16384 + (size_t)c0 * 1024 + p;
                float v0 = fb[0], v1 = fb[1024];
                if (s_sgn[d] > 0) { p0 += v0; p1 += v1; } else { q0 += v0; q1 += v1; }
            }
            uint32_t hi, lo; int u = c0 >> 1;
            split2(s0, s1, hi, lo); sh[p_l * 25 + u] = hi;      sl[p_l * 25 + u] = lo;
            split2(p0, p1, hi, lo); sh[p_l * 25 + 8 + u] = hi;  sl[p_l * 25 + 8 + u] = lo;
            split2(q0, q1, hi, lo); sh[p_l * 25 + 16 + u] = hi; sl[p_l * 25 + 16 + u] = lo;
        }
        __syncthreads();
        size_t gbase = ((size_t)n * 1024 + chunk * 128) * 24;
        for (int g = threadIdx.x; g < 128 * 24; g += 256) {
            int item = g / 24, u = g % 24;
            g_xh[gbase + g] = sh[item * 25 + u];
            g_xl[gbase + g] = sl[item * 25 + u];
        }
        __syncthreads();
    }
}

// ---------------------------------------------------------------------------
// Weight prep (fused): fp32 OIHW -> [rep][oc][k=tap*CIN+cin], rows padded to KP.
__device__ __forceinline__ void prep_one(const float* __restrict__ wgt,
                                         __nv_bfloat16* __restrict__ gB,
                                         int idx, int CIN, int COUT, int KP) {
    int rep = idx / (COUT * KP);
    int rem = idx % (COUT * KP);
    int oc = rem / KP, kp = rem % KP;
    __nv_bfloat16 val = __float2bfloat16(0.f);
    if (kp < 9 * CIN) {
        int tap = kp / CIN, cin = kp % CIN;
        float wv = wgt[(oc * CIN + cin) * 9 + tap];
        __nv_bfloat16 h = __float2bfloat16(wv);
        val = rep ? __float2bfloat16(wv - __bfloat162float(h)) : h;
    }
    gB[idx] = val;
}
#define PW1 (2 * 32 * 440)
#define PW2 (2 * 32 * 296)
#define PW3 (2 * 16 * 296)
__global__ void k_prep(const float* __restrict__ w1, const float* __restrict__ w2,
                       const float* __restrict__ w3) {
    int idx = blockIdx.x * 256 + threadIdx.x;
    if (idx < PW1) prep_one(w1, g_wb1, idx, 48, 32, 440);
    else if (idx < PW1 + PW2) prep_one(w2, g_wb2, idx - PW1, 32, 32, 296);
    else if (idx < PW1 + PW2 + PW3) prep_one(w3, g_wb3, idx - PW1 - PW2, 32, 16, 296);
}

// ---------------------------------------------------------------------------
// HMMA implicit-GEMM conv: pre-split inputs, cp.async staging (no conversion),
// plane layout [ROWS+2][34][CP] bf16 per hi/lo; warp = 32 px (2 m16 tiles).
// 3-term split: acc = A_hi*W_hi + A_lo*W_hi + A_hi*W_lo.
template <int CIN, int COUT, int ROWS, int NWARP, int KP, bool PACKED>
__device__ __forceinline__ void conv_body(
    const uint32_t* __restrict__ in_hi, const uint32_t* __restrict__ in_lo,
    const __nv_bfloat16* __restrict__ gB, const float* __restrict__ bias,
    uint32_t* __restrict__ out_hi, uint32_t* __restrict__ out_lo,
    float* __restrict__ out_f32) {
    constexpr int CP  = CIN + 8;
    constexpr int NCG = CIN / 16;
    constexpr int NT  = COUT / 8;
    constexpr int NH  = NT / 2;
    constexpr int BB  = 2 * COUT * KP * 2;
    constexpr int PB  = (ROWS + 2) * 34 * CP * 2;
    constexpr int NTHR = NWARP * 32;
    constexpr int TPI = 32 / ROWS;
    constexpr int IT  = (ROWS + 2) * 34;
    constexpr int CH  = CIN / 8;        // 16B chunks per pixel per plane
    constexpr int CU  = CIN / 2;        // u32 per pixel in global arrays

    extern __shared__ char smem[];
    char* Bs  = smem;
    char* Phi = smem + BB;
    char* Plo = Phi + PB;

    const int tid = threadIdx.x, wid = tid >> 5, lane = tid & 31;
    const uint32_t Bs_u  = smem_u32(Bs);
    const uint32_t Phi_u = smem_u32(Phi);
    const uint32_t Plo_u = smem_u32(Plo);

    // stage B once (persistent CTA)
    for (int i = tid; i < BB / 4; i += NTHR)
        ((uint32_t*)Bs)[i] = ((const uint32_t*)gB)[i];

    // A-fragment lane mapping (validated R7-R11)
    const int arl = (lane & 7) + ((lane >> 3) & 1) * 8;
    const int akb = lane >> 4;
    uint32_t pb0, pb1;
    {
        int px = wid * 32 + arl;
        pb0 = (uint32_t)((((px >> 5) * 34) + (px & 31)) * CP * 2 + akb * 16);
        px += 16;
        pb1 = (uint32_t)((((px >> 5) * 34) + (px & 31)) * CP * 2 + akb * 16);
    }
    // B-fragment lane mapping (validated R7-R11)
    const int boc = ((lane >> 4) & 1) * 8 + (lane & 7);
    const int bkb = (lane >> 3) & 1;
    uint32_t bb0[NH], bb1[NH];
#pragma unroll
    for (int h = 0; h < NH; h++) {
        bb0[h] = Bs_u + (uint32_t)((h * 16 + boc) * KP * 2 + bkb * 16);
        bb1[h] = bb0[h] + (uint32_t)(COUT * KP * 2);
    }
    const int g_r = lane >> 2, tg = lane & 3;
    float bv[NT][2];
#pragma unroll
    for (int nt = 0; nt < NT; nt++) {
        bv[nt][0] = __ldg(bias + nt * 8 + tg * 2);
        bv[nt][1] = __ldg(bias + nt * 8 + tg * 2 + 1);
    }

    for (int tile = blockIdx.x; tile < NN * TPI; tile += gridDim.x) {
        const int n = tile / TPI, y0 = (tile % TPI) * ROWS;
        const size_t nbase = (size_t)n * 1024;

        // ---- staging: pure 16B async copies, zero-filled halo ----
        for (int idx = tid; idx < 2 * IT * CH; idx += NTHR) {
            int pl = idx >= IT * CH;
            int r = pl ? idx - IT * CH : idx;
            int item = r / CH, ch = r % CH;
            int y = item / 34, x = item % 34;
            int yi = y0 - 1 + y, xi = x - 1;
            bool ok = ((unsigned)yi < 32u) && ((unsigned)xi < 32u);
            const uint32_t* sArr = pl ? in_lo : in_hi;
            const char* src = (const char*)(sArr + (nbase + (ok ? yi * 32 + xi : 0)) * CU) + ch * 16;
            uint32_t dst = (pl ? Plo_u : Phi_u) + (uint32_t)(item * CP * 2 + ch * 16);
            int sz = ok ? 16 : 0;
            CP_ASYNC16(dst, src, sz);
        }
        CP_COMMIT();
        CP_WAIT0();
        __syncthreads();

        // ---- k loop: ldmatrix straight from planes, no syncs ----
        float acc[2][NT][4];
#pragma unroll
        for (int mt = 0; mt < 2; mt++)
#pragma unroll
            for (int nt = 0; nt < NT; nt++)
                acc[mt][nt][0] = acc[mt][nt][1] = acc[mt][nt][2] = acc[mt][nt][3] = 0.f;

#pragma unroll
        for (int tap = 0; tap < 9; tap++) {
            const uint32_t toff = (uint32_t)(((tap / 3) * 34 + (tap % 3)) * CP * 2);
#pragma unroll
            for (int cg = 0; cg < NCG; cg++) {
                const uint32_t aoff = toff + cg * 32;
                const uint32_t koff = (uint32_t)((tap * CIN + cg * 16) * 2);
                uint32_t ah[2][4], al[2][4];
                LDSM_X4(ah[0][0], ah[0][1], ah[0][2], ah[0][3], Phi_u + pb0 + aoff);
                LDSM_X4(ah[1][0], ah[1][1], ah[1][2], ah[1][3], Phi_u + pb1 + aoff);
                LDSM_X4(al[0][0], al[0][1], al[0][2], al[0][3], Plo_u + pb0 + aoff);
                LDSM_X4(al[1][0], al[1][1], al[1][2], al[1][3], Plo_u + pb1 + aoff);
#pragma unroll
                for (int h = 0; h < NH; h++) {
                    uint32_t b0, b1, b2, b3, c0, c1, c2, c3;
                    LDSM_X4(b0, b1, b2, b3, bb0[h] + koff);  // w_hi
                    LDSM_X4(c0, c1, c2, c3, bb1[h] + koff);  // w_lo
#pragma unroll
                    for (int mt = 0; mt < 2; mt++) {
                        MMA16816(acc[mt][2*h],   ah[mt][0], ah[mt][1], ah[mt][2], ah[mt][3], b0, b1);
                        MMA16816(acc[mt][2*h+1], ah[mt][0], ah[mt][1], ah[mt][2], ah[mt][3], b2, b3);
                        MMA16816(acc[mt][2*h],   al[mt][0], al[mt][1], al[mt][2], al[mt][3], b0, b1);
                        MMA16816(acc[mt][2*h+1], al[mt][0], al[mt][1], al[mt][2], al[mt][3], b2, b3);
                        MMA16816(acc[mt][2*h],   ah[mt][0], ah[mt][1], ah[mt][2], ah[mt][3], c0, c1);
                        MMA16816(acc[mt][2*h+1], ah[mt][0], ah[mt][1], ah[mt][2], ah[mt][3], c2, c3);
                    }
                }
            }
        }

        // ---- epilogue ----
        if constexpr (PACKED) {
#pragma unroll
            for (int mt = 0; mt < 2; mt++) {
                const int pA = wid * 32 + mt * 16 + g_r, pB = pA + 8;
                const size_t oA = (nbase + y0 * 32 + pA) * (COUT / 2);
                const size_t oB = (nbase + y0 * 32 + pB) * (COUT / 2);
#pragma unroll
                for (int nt = 0; nt < NT; nt++) {
                    int oc = nt * 8 + tg * 2;
                    float v0 = acc[mt][nt][0] + bv[nt][0];
                    float v1 = acc[mt][nt][1] + bv[nt][1];
                    float v2 = acc[mt][nt][2] + bv[nt][0];
                    float v3 = acc[mt][nt][3] + bv[nt][1];
                    v0 = v0 > 0.f ? v0 : 0.1f * v0;
                    v1 = v1 > 0.f ? v1 : 0.1f * v1;
                    v2 = v2 > 0.f ? v2 : 0.1f * v2;
                    v3 = v3 > 0.f ? v3 : 0.1f * v3;
                    uint32_t hi, lo;
                    split2(v0, v1, hi, lo);
                    out_hi[oA + (oc >> 1)] = hi; out_lo[oA + (oc >> 1)] = lo;
                    split2(v2, v3, hi, lo);
                    out_hi[oB + (oc >> 1)] = hi; out_lo[oB + (oc >> 1)] = lo;
                }
            }
        } else {
            float* ob = out_f32 + (size_t)n * COUT * HW + y0 * 32;
#pragma unroll
            for (int mt = 0; mt < 2; mt++) {
                const int pA = wid * 32 + mt * 16 + g_r, pB = pA + 8;
#pragma unroll
                for (int nt = 0; nt < NT; nt++) {
                    int oc = nt * 8 + tg * 2;
                    float v;
                    v = acc[mt][nt][0] + bv[nt][0]; v = v > 0.f ? v : 0.1f * v; ob[(size_t)oc * HW + pA] = v;
                    v = acc[mt][nt][1] + bv[nt][1]; v = v > 0.f ? v : 0.1f * v; ob[(size_t)(oc + 1) * HW + pA] = v;
                    v = acc[mt][nt][2] + bv[nt][0]; v = v > 0.f ? v : 0.1f * v; ob[(size_t)oc * HW + pB] = v;
                    v = acc[mt][nt][3] + bv[nt][1]; v = v > 0.f ? v : 0.1f * v; ob[(size_t)(oc + 1) * HW + pB] = v;
                }
            }
        }
        __syncthreads();   // planes reused next tile
    }
}

__global__ __launch_bounds__(512, 1) void k_mconv1(const float* __restrict__ b) {
    conv_body<48, 32, 16, 16, 440, true>(g_xh, g_xl, g_wb1, b, g_t1h, g_t1l, nullptr);
}
__global__ __launch_bounds__(256, 2) void k_mconv2(const float* __restrict__ b) {
    conv_body<32, 32, 8, 8, 296, true>(g_t1h, g_t1l, g_wb2, b, g_t2h, g_t2l, nullptr);
}
__global__ __launch_bounds__(256, 2) void k_mconv3(const float* __restrict__ b,
                                                   float* __restrict__ out) {
    conv_body<32, 16, 8, 8, 296, false>(g_t2h, g_t2l, g_wb3, b, nullptr, nullptr, out);
}

// ---------------------------------------------------------------------------
static inline int smsz(int CIN, int COUT, int KP, int ROWS) {
    return 2 * COUT * KP * 2 + 2 * ((ROWS + 2) * 34 * (CIN + 8) * 2);
}

extern "C" void kernel_launch(void* const* d_in, const int* in_sizes, int n_in,
                              void* d_out, int out_size) {
    const float* feats = nullptr;
    const void*  edges = nullptr;
    const float *w1 = nullptr, *b1 = nullptr, *w2 = nullptr, *b2 = nullptr;
    const float *w3 = nullptr, *b3 = nullptr;
    int b32_seen = 0;
    for (int i = 0; i < n_in; i++) {
        switch (in_sizes[i]) {
            case 16777216: feats = (const float*)d_in[i]; break;
            case 12288:
            case 24576:    edges = d_in[i]; break;
            case 13824:    w1 = (const float*)d_in[i]; break;
            case 9216:     w2 = (const float*)d_in[i]; break;
            case 4608:     w3 = (const float*)d_in[i]; break;
            case 32:       if (b32_seen++ == 0) b1 = (const float*)d_in[i];
                           else                 b2 = (const float*)d_in[i];
                           break;
            case 16:       b3 = (const float*)d_in[i]; break;
            default: break;
        }
    }
    if (!feats || !edges || !w1 || !b1 || !w2 || !b2 || !w3 || !b3) {
        feats = (const float*)d_in[0];
        edges = d_in[1];
        w1 = (const float*)d_in[2]; b1 = (const float*)d_in[3];
        w2 = (const float*)d_in[4]; b2 = (const float*)d_in[5];
        w3 = (const float*)d_in[6]; b3 = (const float*)d_in[7];
    }
    float* out = (float*)d_out;

    // Idempotent, not a stream op — safe on every call.
    cudaFuncSetAttribute(k_mconv1, cudaFuncAttributeMaxDynamicSharedMemorySize, smsz(48, 32, 440, 16));
    cudaFuncSetAttribute(k_mconv2, cudaFuncAttributeMaxDynamicSharedMemorySize, smsz(32, 32, 296, 8));
    cudaFuncSetAttribute(k_mconv3, cudaFuncAttributeMaxDynamicSharedMemorySize, smsz(32, 16, 296, 8));

    k_zeroadj<<<1, 1024>>>(edges);
    k_prep<<<(PW1 + PW2 + PW3 + 255) / 256, 256>>>(w1, w2, w3);
    k_build<<<NN, 256>>>(feats);
    k_mconv1<<<148, 512, smsz(48, 32, 440, 16)>>>(b1);
    k_mconv2<<<296, 256, smsz(32, 32, 296, 8)>>>(b2);
    k_mconv3<<<296, 256, smsz(32, 16, 296, 8)>>>(b3, out);
}

// round 13
// speedup vs baseline: 6.2487x; 1.0224x over previous
#include <cuda_runtime.h>
#include <cuda_bf16.h>
#include <cstdint>

// Problem constants
#define NN   1024
#define HW   1024
#define NE   4096
#define MAXD 64

// ---------------------------------------------------------------------------
// Scratch (__device__ globals). All conv tensors pre-split bf16 hi/lo,
// channel-last: arr[n][px][c/2] as u32 = (bf16 c | bf16 c+1 << 16).
__device__ uint32_t g_xh[(size_t)NN * HW * 24];   // x  hi, 48ch -> 24 u32
__device__ uint32_t g_xl[(size_t)NN * HW * 24];   // x  lo
__device__ uint32_t g_t1h[(size_t)NN * HW * 16];  // t1 hi, 32ch
__device__ uint32_t g_t1l[(size_t)NN * HW * 16];
__device__ uint32_t g_t2h[(size_t)NN * HW * 16];
__device__ uint32_t g_t2l[(size_t)NN * HW * 16];
__device__ int g_deg[NN];
__device__ int g_nbr[NN * MAXD];
__device__ int g_sgn[NN * MAXD];
// Weight images: [rep(hi/lo)][oc][k = tap*CIN + cin], rows padded to KP elems
__device__ __nv_bfloat16 g_wb1[2 * 32 * 440];
__device__ __nv_bfloat16 g_wb2[2 * 32 * 296];
__device__ __nv_bfloat16 g_wb3[2 * 16 * 296];

// ---------------------------------------------------------------------------
__device__ __forceinline__ uint32_t smem_u32(const void* p) {
    uint32_t a;
    asm("{ .reg .u64 t; cvta.to.shared.u64 t, %1; cvt.u32.u64 %0, t; }" : "=r"(a) : "l"(p));
    return a;
}

#define LDSM_X4(r0, r1, r2, r3, addr) \
    asm volatile("ldmatrix.sync.aligned.m8n8.x4.shared.b16 {%0,%1,%2,%3}, [%4];" \
        : "=r"(r0), "=r"(r1), "=r"(r2), "=r"(r3) : "r"(addr))

#define MMA16816(d, a0, a1, a2, a3, b0, b1) \
    asm volatile("mma.sync.aligned.m16n8k16.row.col.f32.bf16.bf16.f32 " \
        "{%0,%1,%2,%3}, {%4,%5,%6,%7}, {%8,%9}, {%0,%1,%2,%3};" \
        : "+f"((d)[0]), "+f"((d)[1]), "+f"((d)[2]), "+f"((d)[3]) \
        : "r"(a0), "r"(a1), "r"(a2), "r"(a3), "r"(b0), "r"(b1))

#define CP_ASYNC16(dst, src, sz) \
    asm volatile("cp.async.cg.shared.global [%0], [%1], 16, %2;" \
        :: "r"(dst), "l"(src), "r"(sz))
#define CP_COMMIT() asm volatile("cp.async.commit_group;" ::: "memory")
#define CP_WAIT0()  asm volatile("cp.async.wait_group 0;" ::: "memory")
#define CP_WAIT1()  asm volatile("cp.async.wait_group 1;" ::: "memory")

// Split two floats into packed bf16 hi/lo pair words.
__device__ __forceinline__ void split2(float v0, float v1, uint32_t& hi, uint32_t& lo) {
    __nv_bfloat16 h0 = __float2bfloat16(v0), h1 = __float2bfloat16(v1);
    __nv_bfloat16 l0 = __float2bfloat16(v0 - __bfloat162float(h0));
    __nv_bfloat16 l1 = __float2bfloat16(v1 - __bfloat162float(h1));
    hi = (uint32_t)__bfloat16_as_ushort(h0) | ((uint32_t)__bfloat16_as_ushort(h1) << 16);
    lo = (uint32_t)__bfloat16_as_ushort(l0) | ((uint32_t)__bfloat16_as_ushort(l1) << 16);
}

// ---------------------------------------------------------------------------
__device__ __forceinline__ int detect_edge_mode(const unsigned* w) {
    bool any_floatish = false, odd_ok = true;
#pragma unroll
    for (int i = 0; i < 24; i++) {
        unsigned v = w[i];
        if (v >= 0x30000000u && v < 0xF0000000u) any_floatish = true;
        if ((i & 1) && !(v == 0u || v == 0xFFFFFFFFu)) odd_ok = false;
    }
    if (any_floatish) return 2;
    if (odd_ok) return 0;
    return 1;
}

// Fused: zero degree counters + build adjacency. One 1024-thread CTA.
__global__ void k_zeroadj(const void* __restrict__ edges_raw) {
    int tid = threadIdx.x;
    g_deg[tid] = 0;
    __syncthreads();
    int mode = detect_edge_mode((const unsigned*)edges_raw);
    for (int e = tid; e < NE; e += 1024) {
        int src, dst, sgn;
        if (mode == 0) {
            const long long* p = (const long long*)edges_raw;
            src = (int)p[3 * e]; sgn = (p[3 * e + 1] > 0) ? 1 : -1; dst = (int)p[3 * e + 2];
        } else if (mode == 1) {
            const int* p = (const int*)edges_raw;
            src = p[3 * e]; sgn = (p[3 * e + 1] > 0) ? 1 : -1; dst = p[3 * e + 2];
        } else {
            const float* p = (const float*)edges_raw;
            src = (int)p[3 * e]; sgn = (p[3 * e + 1] > 0.f) ? 1 : -1; dst = (int)p[3 * e + 2];
        }
        if ((unsigned)src >= NN || (unsigned)dst >= NN) continue;
        int q = atomicAdd(&g_deg[dst], 1);
        if (q < MAXD) { g_nbr[dst * MAXD + q] = src; g_sgn[dst * MAXD + q] = sgn; }
        q = atomicAdd(&g_deg[src], 1);
        if (q < MAXD) { g_nbr[src * MAXD + q] = dst; g_sgn[src * MAXD + q] = sgn; }
    }
}

// Pool + concat + hi/lo split, channel-last output. One CTA per node.
__global__ __launch_bounds__(256) void k_build(const float* __restrict__ feats) {
    int n = blockIdx.x;
    __shared__ int s_nbr[MAXD], s_sgn[MAXD], s_deg;
    __shared__ uint32_t sh[128 * 25], sl[128 * 25];
    if (threadIdx.x == 0) s_deg = min(g_deg[n], MAXD);
    if (threadIdx.x < MAXD) {
        int nb = g_nbr[n * MAXD + threadIdx.x];
        s_nbr[threadIdx.x] = ((unsigned)nb < NN) ? nb : 0;
        s_sgn[threadIdx.x] = g_sgn[n * MAXD + threadIdx.x];
    }
    __syncthreads();
    const int deg = s_deg;
    const int half = threadIdx.x >> 7, p_l = threadIdx.x & 127;
    const int cbase = half * 8;
    for (int chunk = 0; chunk < 8; chunk++) {
        int p = chunk * 128 + p_l;
#pragma unroll
        for (int cp = 0; cp < 4; cp++) {
            int c0 = cbase + 2 * cp;
            const float* f0 = feats + (size_t)n * 16384 + (size_t)c0 * 1024 + p;
            float s0 = f0[0], s1 = f0[1024];
            float p0 = 0.f, p1 = 0.f, q0 = 0.f, q1 = 0.f;
            for (int d = 0; d < deg; d++) {
                const float* fb = feats + (size_t)s_nbr[d] * 16384 + (size_t)c0 * 1024 + p;
                float v0 = fb[0], v1 = fb[1024];
                if (s_sgn[d] > 0) { p0 += v0; p1 += v1; } else { q0 += v0; q1 += v1; }
            }
            uint32_t hi, lo; int u = c0 >> 1;
            split2(s0, s1, hi, lo); sh[p_l * 25 + u] = hi;      sl[p_l * 25 + u] = lo;
            split2(p0, p1, hi, lo); sh[p_l * 25 + 8 + u] = hi;  sl[p_l * 25 + 8 + u] = lo;
            split2(q0, q1, hi, lo); sh[p_l * 25 + 16 + u] = hi; sl[p_l * 25 + 16 + u] = lo;
        }
        __syncthreads();
        size_t gbase = ((size_t)n * 1024 + chunk * 128) * 24;
        for (int g = threadIdx.x; g < 128 * 24; g += 256) {
            int item = g / 24, u = g % 24;
            g_xh[gbase + g] = sh[item * 25 + u];
            g_xl[gbase + g] = sl[item * 25 + u];
        }
        __syncthreads();
    }
}

// ---------------------------------------------------------------------------
// Weight prep (fused): fp32 OIHW -> [rep][oc][k=tap*CIN+cin], rows padded to KP.
__device__ __forceinline__ void prep_one(const float* __restrict__ wgt,
                                         __nv_bfloat16* __restrict__ gB,
                                         int idx, int CIN, int COUT, int KP) {
    int rep = idx / (COUT * KP);
    int rem = idx % (COUT * KP);
    int oc = rem / KP, kp = rem % KP;
    __nv_bfloat16 val = __float2bfloat16(0.f);
    if (kp < 9 * CIN) {
        int tap = kp / CIN, cin = kp % CIN;
        float wv = wgt[(oc * CIN + cin) * 9 + tap];
        __nv_bfloat16 h = __float2bfloat16(wv);
        val = rep ? __float2bfloat16(wv - __bfloat162float(h)) : h;
    }
    gB[idx] = val;
}
#define PW1 (2 * 32 * 440)
#define PW2 (2 * 32 * 296)
#define PW3 (2 * 16 * 296)
__global__ void k_prep(const float* __restrict__ w1, const float* __restrict__ w2,
                       const float* __restrict__ w3) {
    int idx = blockIdx.x * 256 + threadIdx.x;
    if (idx < PW1) prep_one(w1, g_wb1, idx, 48, 32, 440);
    else if (idx < PW1 + PW2) prep_one(w2, g_wb2, idx - PW1, 32, 32, 296);
    else if (idx < PW1 + PW2 + PW3) prep_one(w3, g_wb3, idx - PW1 - PW2, 32, 16, 296);
}

// ---------------------------------------------------------------------------
// HMMA implicit-GEMM conv: pre-split inputs, cp.async staging, optional
// double-buffered tile pipeline (DBUF). Warp = MT m16 tiles (MT*16 px).
// Planes [ROWS+2][34][CP] bf16 per rep per buffer.
// 3-term split: acc = A_hi*W_hi + A_lo*W_hi + A_hi*W_lo.
template <int CIN, int COUT, int ROWS, int NWARP, int MT, int KP, bool PACKED, bool DBUF>
__device__ __forceinline__ void conv_body(
    const uint32_t* __restrict__ in_hi, const uint32_t* __restrict__ in_lo,
    const __nv_bfloat16* __restrict__ gB, const float* __restrict__ bias,
    uint32_t* __restrict__ out_hi, uint32_t* __restrict__ out_lo,
    float* __restrict__ out_f32) {
    constexpr int CP  = CIN + 8;
    constexpr int NCG = CIN / 16;
    constexpr int NT  = COUT / 8;
    constexpr int NH  = NT / 2;
    constexpr int BB  = 2 * COUT * KP * 2;
    constexpr int PB  = (ROWS + 2) * 34 * CP * 2;   // one plane (hi or lo)
    constexpr int NTHR = NWARP * 32;
    constexpr int TPI = 32 / ROWS;
    constexpr int NTILES = NN * TPI;
    constexpr int IT  = (ROWS + 2) * 34;
    constexpr int CH  = CIN / 8;
    constexpr int CU  = CIN / 2;

    extern __shared__ char smem[];
    char* Bs = smem;

    const int tid = threadIdx.x, wid = tid >> 5, lane = tid & 31;
    const uint32_t Bs_u = smem_u32(Bs);
    const uint32_t P0_u = Bs_u + BB;          // buffer 0 hi; lo at +PB

    // stage B once (persistent CTA)
    for (int i = tid; i < BB / 4; i += NTHR)
        ((uint32_t*)Bs)[i] = ((const uint32_t*)gB)[i];

    // A-fragment lane mapping (validated R7-R12)
    const int arl = (lane & 7) + ((lane >> 3) & 1) * 8;
    const int akb = lane >> 4;
    uint32_t pb[MT];
#pragma unroll
    for (int mt = 0; mt < MT; mt++) {
        int px = wid * (MT * 16) + mt * 16 + arl;
        pb[mt] = (uint32_t)((((px >> 5) * 34) + (px & 31)) * CP * 2 + akb * 16);
    }
    // B-fragment lane mapping (validated R7-R12)
    const int boc = ((lane >> 4) & 1) * 8 + (lane & 7);
    const int bkb = (lane >> 3) & 1;
    uint32_t bb0[NH], bb1[NH];
#pragma unroll
    for (int h = 0; h < NH; h++) {
        bb0[h] = Bs_u + (uint32_t)((h * 16 + boc) * KP * 2 + bkb * 16);
        bb1[h] = bb0[h] + (uint32_t)(COUT * KP * 2);
    }
    const int g_r = lane >> 2, tg = lane & 3;
    float bv[NT][2];
#pragma unroll
    for (int nt = 0; nt < NT; nt++) {
        bv[nt][0] = __ldg(bias + nt * 8 + tg * 2);
        bv[nt][1] = __ldg(bias + nt * 8 + tg * 2 + 1);
    }

    // staging: pure 16B async copies into buffer at plane base `pbase_u`
    auto stage = [&](int t, uint32_t pbase_u) {
        const int n = t / TPI, y0 = (t % TPI) * ROWS;
        const size_t nb = (size_t)n * 1024;
        for (int idx = tid; idx < 2 * IT * CH; idx += NTHR) {
            int pl = idx >= IT * CH;
            int r = pl ? idx - IT * CH : idx;
            int item = r / CH, ch = r % CH;
            int y = item / 34, x = item % 34;
            int yi = y0 - 1 + y, xi = x - 1;
            bool ok = ((unsigned)yi < 32u) && ((unsigned)xi < 32u);
            const uint32_t* sArr = pl ? in_lo : in_hi;
            const char* src = (const char*)(sArr + (nb + (ok ? yi * 32 + xi : 0)) * CU) + ch * 16;
            uint32_t dst = pbase_u + (pl ? PB : 0) + (uint32_t)(item * CP * 2 + ch * 16);
            CP_ASYNC16(dst, src, ok ? 16 : 0);
        }
    };

    int parity = 0;
    if (DBUF && blockIdx.x < NTILES) stage(blockIdx.x, P0_u);
    if (DBUF) CP_COMMIT();

    for (int tile = blockIdx.x; tile < NTILES; tile += gridDim.x) {
        const int n = tile / TPI, y0 = (tile % TPI) * ROWS;
        const size_t nbase = (size_t)n * 1024;
        const uint32_t Phi_u = DBUF ? (P0_u + (uint32_t)(parity * 2 * PB)) : P0_u;
        const uint32_t Plo_u = Phi_u + PB;

        if (DBUF) {
            int nxt = tile + gridDim.x;
            if (nxt < NTILES) stage(nxt, P0_u + (uint32_t)((parity ^ 1) * 2 * PB));
            CP_COMMIT();
            CP_WAIT1();
        } else {
            stage(tile, P0_u);
            CP_COMMIT();
            CP_WAIT0();
        }
        __syncthreads();

        // ---- k loop: ldmatrix straight from planes, no syncs ----
        float acc[MT][NT][4];
#pragma unroll
        for (int mt = 0; mt < MT; mt++)
#pragma unroll
            for (int nt = 0; nt < NT; nt++)
                acc[mt][nt][0] = acc[mt][nt][1] = acc[mt][nt][2] = acc[mt][nt][3] = 0.f;

#pragma unroll
        for (int tap = 0; tap < 9; tap++) {
            const uint32_t toff = (uint32_t)(((tap / 3) * 34 + (tap % 3)) * CP * 2);
#pragma unroll
            for (int cg = 0; cg < NCG; cg++) {
                const uint32_t aoff = toff + cg * 32;
                const uint32_t koff = (uint32_t)((tap * CIN + cg * 16) * 2);
                uint32_t ah[MT][4], al[MT][4];
#pragma unroll
                for (int mt = 0; mt < MT; mt++) {
                    LDSM_X4(ah[mt][0], ah[mt][1], ah[mt][2], ah[mt][3], Phi_u + pb[mt] + aoff);
                    LDSM_X4(al[mt][0], al[mt][1], al[mt][2], al[mt][3], Plo_u + pb[mt] + aoff);
                }
#pragma unroll
                for (int h = 0; h < NH; h++) {
                    uint32_t b0, b1, b2, b3, c0, c1, c2, c3;
                    LDSM_X4(b0, b1, b2, b3, bb0[h] + koff);  // w_hi
                    LDSM_X4(c0, c1, c2, c3, bb1[h] + koff);  // w_lo
#pragma unroll
                    for (int mt = 0; mt < MT; mt++) {
                        MMA16816(acc[mt][2*h],   ah[mt][0], ah[mt][1], ah[mt][2], ah[mt][3], b0, b1);
                        MMA16816(acc[mt][2*h+1], ah[mt][0], ah[mt][1], ah[mt][2], ah[mt][3], b2, b3);
                        MMA16816(acc[mt][2*h],   al[mt][0], al[mt][1], al[mt][2], al[mt][3], b0, b1);
                        MMA16816(acc[mt][2*h+1], al[mt][0], al[mt][1], al[mt][2], al[mt][3], b2, b3);
                        MMA16816(acc[mt][2*h],   ah[mt][0], ah[mt][1], ah[mt][2], ah[mt][3], c0, c1);
                        MMA16816(acc[mt][2*h+1], ah[mt][0], ah[mt][1], ah[mt][2], ah[mt][3], c2, c3);
                    }
                }
            }
        }

        // ---- epilogue ----
        if constexpr (PACKED) {
#pragma unroll
            for (int mt = 0; mt < MT; mt++) {
                const int pA = wid * (MT * 16) + mt * 16 + g_r, pB2 = pA + 8;
                const size_t oA = (nbase + y0 * 32 + pA) * (COUT / 2);
                const size_t oB = (nbase + y0 * 32 + pB2) * (COUT / 2);
#pragma unroll
                for (int nt = 0; nt < NT; nt++) {
                    int oc = nt * 8 + tg * 2;
                    float v0 = acc[mt][nt][0] + bv[nt][0];
                    float v1 = acc[mt][nt][1] + bv[nt][1];
                    float v2 = acc[mt][nt][2] + bv[nt][0];
                    float v3 = acc[mt][nt][3] + bv[nt][1];
                    v0 = v0 > 0.f ? v0 : 0.1f * v0;
                    v1 = v1 > 0.f ? v1 : 0.1f * v1;
                    v2 = v2 > 0.f ? v2 : 0.1f * v2;
                    v3 = v3 > 0.f ? v3 : 0.1f * v3;
                    uint32_t hi, lo;
                    split2(v0, v1, hi, lo);
                    out_hi[oA + (oc >> 1)] = hi; out_lo[oA + (oc >> 1)] = lo;
                    split2(v2, v3, hi, lo);
                    out_hi[oB + (oc >> 1)] = hi; out_lo[oB + (oc >> 1)] = lo;
                }
            }
        } else {
            float* ob = out_f32 + (size_t)n * COUT * HW + y0 * 32;
#pragma unroll
            for (int mt = 0; mt < MT; mt++) {
                const int pA = wid * (MT * 16) + mt * 16 + g_r, pB2 = pA + 8;
#pragma unroll
                for (int nt = 0; nt < NT; nt++) {
                    int oc = nt * 8 + tg * 2;
                    float v;
                    v = acc[mt][nt][0] + bv[nt][0]; v = v > 0.f ? v : 0.1f * v; ob[(size_t)oc * HW + pA] = v;
                    v = acc[mt][nt][1] + bv[nt][1]; v = v > 0.f ? v : 0.1f * v; ob[(size_t)(oc + 1) * HW + pA] = v;
                    v = acc[mt][nt][2] + bv[nt][0]; v = v > 0.f ? v : 0.1f * v; ob[(size_t)oc * HW + pB2] = v;
                    v = acc[mt][nt][3] + bv[nt][1]; v = v > 0.f ? v : 0.1f * v; ob[(size_t)(oc + 1) * HW + pB2] = v;
                }
            }
        }
        __syncthreads();   // protect planes before next-tile staging overwrites
        parity ^= 1;
    }
}

// conv1: ROWS=8, 16 warps, MT=1, double-buffered pipeline (1 CTA/SM)
__global__ __launch_bounds__(512, 1) void k_mconv1(const float* __restrict__ b) {
    conv_body<48, 32, 8, 16, 1, 440, true, true>(g_xh, g_xl, g_wb1, b, g_t1h, g_t1l, nullptr);
}
// conv2/3: ROWS=8, 8 warps, MT=2, single buffer, 2 CTAs/SM overlap
__global__ __launch_bounds__(256, 2) void k_mconv2(const float* __restrict__ b) {
    conv_body<32, 32, 8, 8, 2, 296, true, false>(g_t1h, g_t1l, g_wb2, b, g_t2h, g_t2l, nullptr);
}
__global__ __launch_bounds__(256, 2) void k_mconv3(const float* __restrict__ b,
                                                   float* __restrict__ out) {
    conv_body<32, 16, 8, 8, 2, 296, false, false>(g_t2h, g_t2l, g_wb3, b, nullptr, nullptr, out);
}

// ---------------------------------------------------------------------------
static inline int smsz(int CIN, int COUT, int KP, int ROWS, int nbuf) {
    return 2 * COUT * KP * 2 + nbuf * 2 * ((ROWS + 2) * 34 * (CIN + 8) * 2);
}

extern "C" void kernel_launch(void* const* d_in, const int* in_sizes, int n_in,
                              void* d_out, int out_size) {
    const float* feats = nullptr;
    const void*  edges = nullptr;
    const float *w1 = nullptr, *b1 = nullptr, *w2 = nullptr, *b2 = nullptr;
    const float *w3 = nullptr, *b3 = nullptr;
    int b32_seen = 0;
    for (int i = 0; i < n_in; i++) {
        switch (in_sizes[i]) {
            case 16777216: feats = (const float*)d_in[i]; break;
            case 12288:
            case 24576:    edges = d_in[i]; break;
            case 13824:    w1 = (const float*)d_in[i]; break;
            case 9216:     w2 = (const float*)d_in[i]; break;
            case 4608:     w3 = (const float*)d_in[i]; break;
            case 32:       if (b32_seen++ == 0) b1 = (const float*)d_in[i];
                           else                 b2 = (const float*)d_in[i];
                           break;
            case 16:       b3 = (const float*)d_in[i]; break;
            default: break;
        }
    }
    if (!feats || !edges || !w1 || !b1 || !w2 || !b2 || !w3 || !b3) {
        feats = (const float*)d_in[0];
        edges = d_in[1];
        w1 = (const float*)d_in[2]; b1 = (const float*)d_in[3];
        w2 = (const float*)d_in[4]; b2 = (const float*)d_in[5];
        w3 = (const float*)d_in[6]; b3 = (const float*)d_in[7];
    }
    float* out = (float*)d_out;

    // Idempotent, not a stream op — safe on every call.
    cudaFuncSetAttribute(k_mconv1, cudaFuncAttributeMaxDynamicSharedMemorySize, smsz(48, 32, 440, 8, 2));
    cudaFuncSetAttribute(k_mconv2, cudaFuncAttributeMaxDynamicSharedMemorySize, smsz(32, 32, 296, 8, 1));
    cudaFuncSetAttribute(k_mconv3, cudaFuncAttributeMaxDynamicSharedMemorySize, smsz(32, 16, 296, 8, 1));

    k_zeroadj<<<1, 1024>>>(edges);
    k_prep<<<(PW1 + PW2 + PW3 + 255) / 256, 256>>>(w1, w2, w3);
    k_build<<<NN, 256>>>(feats);
    k_mconv1<<<148, 512, smsz(48, 32, 440, 8, 2)>>>(b1);
    k_mconv2<<<296, 256, smsz(32, 32, 296, 8, 1)>>>(b2);
    k_mconv3<<<296, 256, smsz(32, 16, 296, 8, 1)>>>(b3, out);
}

// round 14
// speedup vs baseline: 8.7152x; 1.3947x over previous
#include <cuda_runtime.h>
#include <cuda_fp16.h>
#include <cstdint>

// Problem constants
#define NN   1024
#define HW   1024
#define NE   4096
#define MAXD 64

// ---------------------------------------------------------------------------
// Scratch (__device__ globals). Conv tensors stored fp16 channel-last:
// arr[n][px][c/2] as u32 = (fp16 c | fp16 c+1 << 16).
__device__ uint32_t g_x16 [(size_t)NN * HW * 24];  // x, 48ch -> 24 u32
__device__ uint32_t g_t116[(size_t)NN * HW * 16];  // t1, 32ch
__device__ uint32_t g_t216[(size_t)NN * HW * 16];  // t2, 32ch
__device__ int g_deg[NN];
__device__ int g_nbr[NN * MAXD];
__device__ int g_sgn[NN * MAXD];
// Weight images fp16: [rep(hi/lo)][oc][k = tap*CIN + cin], rows padded to KP
__device__ __half g_wb1[2 * 32 * 440];
__device__ __half g_wb2[2 * 32 * 296];
__device__ __half g_wb3[2 * 16 * 296];

// ---------------------------------------------------------------------------
__device__ __forceinline__ uint32_t smem_u32(const void* p) {
    uint32_t a;
    asm("{ .reg .u64 t; cvta.to.shared.u64 t, %1; cvt.u32.u64 %0, t; }" : "=r"(a) : "l"(p));
    return a;
}

#define LDSM_X4(r0, r1, r2, r3, addr) \
    asm volatile("ldmatrix.sync.aligned.m8n8.x4.shared.b16 {%0,%1,%2,%3}, [%4];" \
        : "=r"(r0), "=r"(r1), "=r"(r2), "=r"(r3) : "r"(addr))

#define MMA16816H(d, a0, a1, a2, a3, b0, b1) \
    asm volatile("mma.sync.aligned.m16n8k16.row.col.f32.f16.f16.f32 " \
        "{%0,%1,%2,%3}, {%4,%5,%6,%7}, {%8,%9}, {%0,%1,%2,%3};" \
        : "+f"((d)[0]), "+f"((d)[1]), "+f"((d)[2]), "+f"((d)[3]) \
        : "r"(a0), "r"(a1), "r"(a2), "r"(a3), "r"(b0), "r"(b1))

#define CP_ASYNC16(dst, src, sz) \
    asm volatile("cp.async.cg.shared.global [%0], [%1], 16, %2;" \
        :: "r"(dst), "l"(src), "r"(sz))
#define CP_COMMIT() asm volatile("cp.async.commit_group;" ::: "memory")
#define CP_WAIT0()  asm volatile("cp.async.wait_group 0;" ::: "memory")
#define CP_WAIT1()  asm volatile("cp.async.wait_group 1;" ::: "memory")

__device__ __forceinline__ uint32_t pack2h(float v0, float v1) {
    __half h0 = __float2half(v0), h1 = __float2half(v1);
    return (uint32_t)__half_as_ushort(h0) | ((uint32_t)__half_as_ushort(h1) << 16);
}

// ---------------------------------------------------------------------------
__device__ __forceinline__ int detect_edge_mode(const unsigned* w) {
    bool any_floatish = false, odd_ok = true;
#pragma unroll
    for (int i = 0; i < 24; i++) {
        unsigned v = w[i];
        if (v >= 0x30000000u && v < 0xF0000000u) any_floatish = true;
        if ((i & 1) && !(v == 0u || v == 0xFFFFFFFFu)) odd_ok = false;
    }
    if (any_floatish) return 2;
    if (odd_ok) return 0;
    return 1;
}

// Fused: zero degree counters + build adjacency. One 1024-thread CTA.
__global__ void k_zeroadj(const void* __restrict__ edges_raw) {
    int tid = threadIdx.x;
    g_deg[tid] = 0;
    __syncthreads();
    int mode = detect_edge_mode((const unsigned*)edges_raw);
    for (int e = tid; e < NE; e += 1024) {
        int src, dst, sgn;
        if (mode == 0) {
            const long long* p = (const long long*)edges_raw;
            src = (int)p[3 * e]; sgn = (p[3 * e + 1] > 0) ? 1 : -1; dst = (int)p[3 * e + 2];
        } else if (mode == 1) {
            const int* p = (const int*)edges_raw;
            src = p[3 * e]; sgn = (p[3 * e + 1] > 0) ? 1 : -1; dst = p[3 * e + 2];
        } else {
            const float* p = (const float*)edges_raw;
            src = (int)p[3 * e]; sgn = (p[3 * e + 1] > 0.f) ? 1 : -1; dst = (int)p[3 * e + 2];
        }
        if ((unsigned)src >= NN || (unsigned)dst >= NN) continue;
        int q = atomicAdd(&g_deg[dst], 1);
        if (q < MAXD) { g_nbr[dst * MAXD + q] = src; g_sgn[dst * MAXD + q] = sgn; }
        q = atomicAdd(&g_deg[src], 1);
        if (q < MAXD) { g_nbr[src * MAXD + q] = dst; g_sgn[src * MAXD + q] = sgn; }
    }
}

// Pool + concat + fp16 pack, channel-last output. One CTA per node.
__global__ __launch_bounds__(256) void k_build(const float* __restrict__ feats) {
    int n = blockIdx.x;
    __shared__ int s_nbr[MAXD], s_sgn[MAXD], s_deg;
    __shared__ uint32_t sh[128 * 25];
    if (threadIdx.x == 0) s_deg = min(g_deg[n], MAXD);
    if (threadIdx.x < MAXD) {
        int nb = g_nbr[n * MAXD + threadIdx.x];
        s_nbr[threadIdx.x] = ((unsigned)nb < NN) ? nb : 0;
        s_sgn[threadIdx.x] = g_sgn[n * MAXD + threadIdx.x];
    }
    __syncthreads();
    const int deg = s_deg;
    const int half = threadIdx.x >> 7, p_l = threadIdx.x & 127;
    const int cbase = half * 8;
    for (int chunk = 0; chunk < 8; chunk++) {
        int p = chunk * 128 + p_l;
#pragma unroll
        for (int cp = 0; cp < 4; cp++) {
            int c0 = cbase + 2 * cp;
            const float* f0 = feats + (size_t)n * 16384 + (size_t)c0 * 1024 + p;
            float s0 = f0[0], s1 = f0[1024];
            float p0 = 0.f, p1 = 0.f, q0 = 0.f, q1 = 0.f;
            for (int d = 0; d < deg; d++) {
                const float* fb = feats + (size_t)s_nbr[d] * 16384 + (size_t)c0 * 1024 + p;
                float v0 = fb[0], v1 = fb[1024];
                if (s_sgn[d] > 0) { p0 += v0; p1 += v1; } else { q0 += v0; q1 += v1; }
            }
            int u = c0 >> 1;
            sh[p_l * 25 + u]      = pack2h(s0, s1);
            sh[p_l * 25 + 8 + u]  = pack2h(p0, p1);
            sh[p_l * 25 + 16 + u] = pack2h(q0, q1);
        }
        __syncthreads();
        size_t gbase = ((size_t)n * 1024 + chunk * 128) * 24;
        for (int g = threadIdx.x; g < 128 * 24; g += 256) {
            int item = g / 24, u = g % 24;
            g_x16[gbase + g] = sh[item * 25 + u];
        }
        __syncthreads();
    }
}

// ---------------------------------------------------------------------------
// Weight prep (fused): fp32 OIHW -> fp16 [rep][oc][k=tap*CIN+cin] rows pad KP.
// rep 0 = w_hi = fp16(w); rep 1 = w_lo = fp16(w - w_hi).
__device__ __forceinline__ void prep_one(const float* __restrict__ wgt,
                                         __half* __restrict__ gB,
                                         int idx, int CIN, int COUT, int KP) {
    int rep = idx / (COUT * KP);
    int rem = idx % (COUT * KP);
    int oc = rem / KP, kp = rem % KP;
    __half val = __float2half(0.f);
    if (kp < 9 * CIN) {
        int tap = kp / CIN, cin = kp % CIN;
        float wv = wgt[(oc * CIN + cin) * 9 + tap];
        __half h = __float2half(wv);
        val = rep ? __float2half(wv - __half2float(h)) : h;
    }
    gB[idx] = val;
}
#define PW1 (2 * 32 * 440)
#define PW2 (2 * 32 * 296)
#define PW3 (2 * 16 * 296)
__global__ void k_prep(const float* __restrict__ w1, const float* __restrict__ w2,
                       const float* __restrict__ w3) {
    int idx = blockIdx.x * 256 + threadIdx.x;
    if (idx < PW1) prep_one(w1, g_wb1, idx, 48, 32, 440);
    else if (idx < PW1 + PW2) prep_one(w2, g_wb2, idx - PW1, 32, 32, 296);
    else if (idx < PW1 + PW2 + PW3) prep_one(w3, g_wb3, idx - PW1 - PW2, 32, 16, 296);
}

// ---------------------------------------------------------------------------
// HMMA implicit-GEMM conv, fp16 2-term (acc = A*W_hi + A*W_lo), single A plane,
// cp.async staging, optional double-buffered tile pipeline.
// Warp = MT m16 tiles. Plane [ROWS+2][34][CP] fp16 per buffer.
template <int CIN, int COUT, int ROWS, int NWARP, int MT, int KP, bool PACKED, bool DBUF>
__device__ __forceinline__ void conv_body(
    const uint32_t* __restrict__ in16, const __half* __restrict__ gB,
    const float* __restrict__ bias,
    uint32_t* __restrict__ out_pk, float* __restrict__ out_f32) {
    constexpr int CP  = CIN + 8;
    constexpr int NCG = CIN / 16;
    constexpr int NT  = COUT / 8;
    constexpr int NH  = NT / 2;
    constexpr int BB  = 2 * COUT * KP * 2;
    constexpr int PB  = (ROWS + 2) * 34 * CP * 2;   // one fp16 plane
    constexpr int NTHR = NWARP * 32;
    constexpr int TPI = 32 / ROWS;
    constexpr int NTILES = NN * TPI;
    constexpr int IT  = (ROWS + 2) * 34;
    constexpr int CH  = CIN / 8;        // 16B chunks per pixel
    constexpr int CU  = CIN / 2;        // u32 per pixel in global array

    extern __shared__ char smem[];
    char* Bs = smem;

    const int tid = threadIdx.x, wid = tid >> 5, lane = tid & 31;
    const uint32_t Bs_u = smem_u32(Bs);
    const uint32_t P0_u = Bs_u + BB;

    // stage B once (persistent CTA)
    for (int i = tid; i < BB / 4; i += NTHR)
        ((uint32_t*)Bs)[i] = ((const uint32_t*)gB)[i];

    // A-fragment lane mapping (validated R7-R13)
    const int arl = (lane & 7) + ((lane >> 3) & 1) * 8;
    const int akb = lane >> 4;
    uint32_t pb[MT];
#pragma unroll
    for (int mt = 0; mt < MT; mt++) {
        int px = wid * (MT * 16) + mt * 16 + arl;
        pb[mt] = (uint32_t)((((px >> 5) * 34) + (px & 31)) * CP * 2 + akb * 16);
    }
    // B-fragment lane mapping (validated R7-R13)
    const int boc = ((lane >> 4) & 1) * 8 + (lane & 7);
    const int bkb = (lane >> 3) & 1;
    uint32_t bb0[NH], bb1[NH];
#pragma unroll
    for (int h = 0; h < NH; h++) {
        bb0[h] = Bs_u + (uint32_t)((h * 16 + boc) * KP * 2 + bkb * 16);
        bb1[h] = bb0[h] + (uint32_t)(COUT * KP * 2);
    }
    const int g_r = lane >> 2, tg = lane & 3;
    float bv[NT][2];
#pragma unroll
    for (int nt = 0; nt < NT; nt++) {
        bv[nt][0] = __ldg(bias + nt * 8 + tg * 2);
        bv[nt][1] = __ldg(bias + nt * 8 + tg * 2 + 1);
    }

    // staging: pure 16B async copies into plane at `pbase_u`
    auto stage = [&](int t, uint32_t pbase_u) {
        const int n = t / TPI, y0 = (t % TPI) * ROWS;
        const size_t nb = (size_t)n * 1024;
        for (int idx = tid; idx < IT * CH; idx += NTHR) {
            int item = idx / CH, ch = idx % CH;
            int y = item / 34, x = item % 34;
            int yi = y0 - 1 + y, xi = x - 1;
            bool ok = ((unsigned)yi < 32u) && ((unsigned)xi < 32u);
            const char* src = (const char*)(in16 + (nb + (ok ? yi * 32 + xi : 0)) * CU) + ch * 16;
            uint32_t dst = pbase_u + (uint32_t)(item * CP * 2 + ch * 16);
            CP_ASYNC16(dst, src, ok ? 16 : 0);
        }
    };

    int parity = 0;
    if (DBUF && blockIdx.x < NTILES) stage(blockIdx.x, P0_u);
    if (DBUF) CP_COMMIT();

    for (int tile = blockIdx.x; tile < NTILES; tile += gridDim.x) {
        const int n = tile / TPI, y0 = (tile % TPI) * ROWS;
        const size_t nbase = (size_t)n * 1024;
        const uint32_t P_u = DBUF ? (P0_u + (uint32_t)(parity * PB)) : P0_u;

        if (DBUF) {
            int nxt = tile + gridDim.x;
            if (nxt < NTILES) stage(nxt, P0_u + (uint32_t)((parity ^ 1) * PB));
            CP_COMMIT();
            CP_WAIT1();
        } else {
            stage(tile, P0_u);
            CP_COMMIT();
            CP_WAIT0();
        }
        __syncthreads();

        // ---- k loop: A single plane; 2 weight reps (hi, lo) onto same acc ----
        float acc[MT][NT][4];
#pragma unroll
        for (int mt = 0; mt < MT; mt++)
#pragma unroll
            for (int nt = 0; nt < NT; nt++)
                acc[mt][nt][0] = acc[mt][nt][1] = acc[mt][nt][2] = acc[mt][nt][3] = 0.f;

#pragma unroll
        for (int tap = 0; tap < 9; tap++) {
            const uint32_t toff = (uint32_t)(((tap / 3) * 34 + (tap % 3)) * CP * 2);
#pragma unroll
            for (int cg = 0; cg < NCG; cg++) {
                const uint32_t aoff = toff + cg * 32;
                const uint32_t koff = (uint32_t)((tap * CIN + cg * 16) * 2);
                uint32_t a[MT][4];
#pragma unroll
                for (int mt = 0; mt < MT; mt++)
                    LDSM_X4(a[mt][0], a[mt][1], a[mt][2], a[mt][3], P_u + pb[mt] + aoff);
#pragma unroll
                for (int h = 0; h < NH; h++) {
                    uint32_t b0, b1, b2, b3, c0, c1, c2, c3;
                    LDSM_X4(b0, b1, b2, b3, bb0[h] + koff);  // w_hi
                    LDSM_X4(c0, c1, c2, c3, bb1[h] + koff);  // w_lo
#pragma unroll
                    for (int mt = 0; mt < MT; mt++) {
                        MMA16816H(acc[mt][2*h],   a[mt][0], a[mt][1], a[mt][2], a[mt][3], b0, b1);
                        MMA16816H(acc[mt][2*h+1], a[mt][0], a[mt][1], a[mt][2], a[mt][3], b2, b3);
                        MMA16816H(acc[mt][2*h],   a[mt][0], a[mt][1], a[mt][2], a[mt][3], c0, c1);
                        MMA16816H(acc[mt][2*h+1], a[mt][0], a[mt][1], a[mt][2], a[mt][3], c2, c3);
                    }
                }
            }
        }

        // ---- epilogue ----
        if constexpr (PACKED) {
#pragma unroll
            for (int mt = 0; mt < MT; mt++) {
                const int pA = wid * (MT * 16) + mt * 16 + g_r, pB2 = pA + 8;
                const size_t oA = (nbase + y0 * 32 + pA) * (COUT / 2);
                const size_t oB = (nbase + y0 * 32 + pB2) * (COUT / 2);
#pragma unroll
                for (int nt = 0; nt < NT; nt++) {
                    int oc = nt * 8 + tg * 2;
                    float v0 = acc[mt][nt][0] + bv[nt][0];
                    float v1 = acc[mt][nt][1] + bv[nt][1];
                    float v2 = acc[mt][nt][2] + bv[nt][0];
                    float v3 = acc[mt][nt][3] + bv[nt][1];
                    v0 = v0 > 0.f ? v0 : 0.1f * v0;
                    v1 = v1 > 0.f ? v1 : 0.1f * v1;
                    v2 = v2 > 0.f ? v2 : 0.1f * v2;
                    v3 = v3 > 0.f ? v3 : 0.1f * v3;
                    out_pk[oA + (oc >> 1)] = pack2h(v0, v1);
                    out_pk[oB + (oc >> 1)] = pack2h(v2, v3);
                }
            }
        } else {
            float* ob = out_f32 + (size_t)n * COUT * HW + y0 * 32;
#pragma unroll
            for (int mt = 0; mt < MT; mt++) {
                const int pA = wid * (MT * 16) + mt * 16 + g_r, pB2 = pA + 8;
#pragma unroll
                for (int nt = 0; nt < NT; nt++) {
                    int oc = nt * 8 + tg * 2;
                    float v;
                    v = acc[mt][nt][0] + bv[nt][0]; v = v > 0.f ? v : 0.1f * v; ob[(size_t)oc * HW + pA] = v;
                    v = acc[mt][nt][1] + bv[nt][1]; v = v > 0.f ? v : 0.1f * v; ob[(size_t)(oc + 1) * HW + pA] = v;
                    v = acc[mt][nt][2] + bv[nt][0]; v = v > 0.f ? v : 0.1f * v; ob[(size_t)oc * HW + pB2] = v;
                    v = acc[mt][nt][3] + bv[nt][1]; v = v > 0.f ? v : 0.1f * v; ob[(size_t)(oc + 1) * HW + pB2] = v;
                }
            }
        }
        __syncthreads();   // protect plane before next staging overwrites
        parity ^= 1;
    }
}

// conv1: ROWS=16, 16 warps, MT=2, double-buffered (1 CTA/SM, 193 KB smem)
__global__ __launch_bounds__(512, 1) void k_mconv1(const float* __restrict__ b) {
    conv_body<48, 32, 16, 16, 2, 440, true, true>(g_x16, g_wb1, b, g_t116, nullptr);
}
// conv2/3: ROWS=8, 8 warps, MT=2, double-buffered, 2 CTAs/SM
__global__ __launch_bounds__(256, 2) void k_mconv2(const float* __restrict__ b) {
    conv_body<32, 32, 8, 8, 2, 296, true, true>(g_t116, g_wb2, b, g_t216, nullptr);
}
__global__ __launch_bounds__(256, 2) void k_mconv3(const float* __restrict__ b,
                                                   float* __restrict__ out) {
    conv_body<32, 16, 8, 8, 2, 296, false, true>(g_t216, g_wb3, b, nullptr, out);
}

// ---------------------------------------------------------------------------
static inline int smsz(int CIN, int COUT, int KP, int ROWS, int nbuf) {
    return 2 * COUT * KP * 2 + nbuf * ((ROWS + 2) * 34 * (CIN + 8) * 2);
}

extern "C" void kernel_launch(void* const* d_in, const int* in_sizes, int n_in,
                              void* d_out, int out_size) {
    const float* feats = nullptr;
    const void*  edges = nullptr;
    const float *w1 = nullptr, *b1 = nullptr, *w2 = nullptr, *b2 = nullptr;
    const float *w3 = nullptr, *b3 = nullptr;
    int b32_seen = 0;
    for (int i = 0; i < n_in; i++) {
        switch (in_sizes[i]) {
            case 16777216: feats = (const float*)d_in[i]; break;
            case 12288:
            case 24576:    edges = d_in[i]; break;
            case 13824:    w1 = (const float*)d_in[i]; break;
            case 9216:     w2 = (const float*)d_in[i]; break;
            case 4608:     w3 = (const float*)d_in[i]; break;
            case 32:       if (b32_seen++ == 0) b1 = (const float*)d_in[i];
                           else                 b2 = (const float*)d_in[i];
                           break;
            case 16:       b3 = (const float*)d_in[i]; break;
            default: break;
        }
    }
    if (!feats || !edges || !w1 || !b1 || !w2 || !b2 || !w3 || !b3) {
        feats = (const float*)d_in[0];
        edges = d_in[1];
        w1 = (const float*)d_in[2]; b1 = (const float*)d_in[3];
        w2 = (const float*)d_in[4]; b2 = (const float*)d_in[5];
        w3 = (const float*)d_in[6]; b3 = (const float*)d_in[7];
    }
    float* out = (float*)d_out;

    // Idempotent, not a stream op — safe on every call.
    cudaFuncSetAttribute(k_mconv1, cudaFuncAttributeMaxDynamicSharedMemorySize, smsz(48, 32, 440, 16, 2));
    cudaFuncSetAttribute(k_mconv2, cudaFuncAttributeMaxDynamicSharedMemorySize, smsz(32, 32, 296, 8, 2));
    cudaFuncSetAttribute(k_mconv3, cudaFuncAttributeMaxDynamicSharedMemorySize, smsz(32, 16, 296, 8, 2));

    k_zeroadj<<<1, 1024>>>(edges);
    k_prep<<<(PW1 + PW2 + PW3 + 255) / 256, 256>>>(w1, w2, w3);
    k_build<<<NN, 256>>>(feats);
    k_mconv1<<<148, 512, smsz(48, 32, 440, 16, 2)>>>(b1);
    k_mconv2<<<296, 256, smsz(32, 32, 296, 8, 2)>>>(b2);
    k_mconv3<<<296, 256, smsz(32, 16, 296, 8, 2)>>>(b3, out);
}

// round 15
// speedup vs baseline: 8.8279x; 1.0129x over previous
#include <cuda_runtime.h>
#include <cuda_fp16.h>
#include <cstdint>

// Problem constants
#define NN   1024
#define HW   1024
#define NE   4096
#define MAXD 64

// ---------------------------------------------------------------------------
// Scratch (__device__ globals). Conv tensors stored fp16 channel-last:
// arr[n][px][c/2] as u32 = (fp16 c | fp16 c+1 << 16).
__device__ uint32_t g_f16 [(size_t)NN * 8 * HW];   // feats, plane layout [n][c/2][px]
__device__ uint32_t g_x16 [(size_t)NN * HW * 24];  // x, 48ch -> 24 u32 (channel-last)
__device__ uint32_t g_t116[(size_t)NN * HW * 16];  // t1, 32ch
__device__ uint32_t g_t216[(size_t)NN * HW * 16];  // t2, 32ch
__device__ int g_deg[NN];
__device__ int g_nbr[NN * MAXD];
__device__ int g_sgn[NN * MAXD];
// Weight images fp16: [rep(hi/lo)][oc][k = tap*CIN + cin], rows padded to KP
__device__ __half g_wb1[2 * 32 * 440];
__device__ __half g_wb2[2 * 32 * 296];
__device__ __half g_wb3[2 * 16 * 296];

// ---------------------------------------------------------------------------
__device__ __forceinline__ uint32_t smem_u32(const void* p) {
    uint32_t a;
    asm("{ .reg .u64 t; cvta.to.shared.u64 t, %1; cvt.u32.u64 %0, t; }" : "=r"(a) : "l"(p));
    return a;
}

#define LDSM_X4(r0, r1, r2, r3, addr) \
    asm volatile("ldmatrix.sync.aligned.m8n8.x4.shared.b16 {%0,%1,%2,%3}, [%4];" \
        : "=r"(r0), "=r"(r1), "=r"(r2), "=r"(r3) : "r"(addr))

#define MMA16816H(d, a0, a1, a2, a3, b0, b1) \
    asm volatile("mma.sync.aligned.m16n8k16.row.col.f32.f16.f16.f32 " \
        "{%0,%1,%2,%3}, {%4,%5,%6,%7}, {%8,%9}, {%0,%1,%2,%3};" \
        : "+f"((d)[0]), "+f"((d)[1]), "+f"((d)[2]), "+f"((d)[3]) \
        : "r"(a0), "r"(a1), "r"(a2), "r"(a3), "r"(b0), "r"(b1))

#define CP_ASYNC16(dst, src, sz) \
    asm volatile("cp.async.cg.shared.global [%0], [%1], 16, %2;" \
        :: "r"(dst), "l"(src), "r"(sz))
#define CP_COMMIT() asm volatile("cp.async.commit_group;" ::: "memory")
#define CP_WAIT0()  asm volatile("cp.async.wait_group 0;" ::: "memory")
#define CP_WAIT1()  asm volatile("cp.async.wait_group 1;" ::: "memory")

__device__ __forceinline__ uint32_t pack2h(float v0, float v1) {
    __half h0 = __float2half(v0), h1 = __float2half(v1);
    return (uint32_t)__half_as_ushort(h0) | ((uint32_t)__half_as_ushort(h1) << 16);
}

// ---------------------------------------------------------------------------
__device__ __forceinline__ int detect_edge_mode(const unsigned* w) {
    bool any_floatish = false, odd_ok = true;
#pragma unroll
    for (int i = 0; i < 24; i++) {
        unsigned v = w[i];
        if (v >= 0x30000000u && v < 0xF0000000u) any_floatish = true;
        if ((i & 1) && !(v == 0u || v == 0xFFFFFFFFu)) odd_ok = false;
    }
    if (any_floatish) return 2;
    if (odd_ok) return 0;
    return 1;
}

// Fused: zero degree counters + build adjacency. One 1024-thread CTA.
__global__ void k_zeroadj(const void* __restrict__ edges_raw) {
    int tid = threadIdx.x;
    g_deg[tid] = 0;
    __syncthreads();
    int mode = detect_edge_mode((const unsigned*)edges_raw);
    for (int e = tid; e < NE; e += 1024) {
        int src, dst, sgn;
        if (mode == 0) {
            const long long* p = (const long long*)edges_raw;
            src = (int)p[3 * e]; sgn = (p[3 * e + 1] > 0) ? 1 : -1; dst = (int)p[3 * e + 2];
        } else if (mode == 1) {
            const int* p = (const int*)edges_raw;
            src = p[3 * e]; sgn = (p[3 * e + 1] > 0) ? 1 : -1; dst = p[3 * e + 2];
        } else {
            const float* p = (const float*)edges_raw;
            src = (int)p[3 * e]; sgn = (p[3 * e + 1] > 0.f) ? 1 : -1; dst = (int)p[3 * e + 2];
        }
        if ((unsigned)src >= NN || (unsigned)dst >= NN) continue;
        int q = atomicAdd(&g_deg[dst], 1);
        if (q < MAXD) { g_nbr[dst * MAXD + q] = src; g_sgn[dst * MAXD + q] = sgn; }
        q = atomicAdd(&g_deg[src], 1);
        if (q < MAXD) { g_nbr[src * MAXD + q] = dst; g_sgn[src * MAXD + q] = sgn; }
    }
}

// feats fp32 NCHW -> fp16 packed channel-pair planes [n][c/2][px]. Coalesced.
__global__ void k_cvt(const float* __restrict__ feats) {
    size_t i = (size_t)blockIdx.x * 256 + threadIdx.x;   // over NN*8*HW
    int n = (int)(i >> 13);
    int r = (int)(i & 8191);
    int c2 = r >> 10, p = r & 1023;
    const float* f = feats + (size_t)n * 16384 + (size_t)c2 * 2048 + p;
    g_f16[i] = pack2h(f[0], f[1024]);
}

// Pool + concat + fp16 pack, channel-last output. One CTA per node.
// Reads fp16 packed planes (half the gather traffic of fp32).
__global__ __launch_bounds__(256) void k_build() {
    int n = blockIdx.x;
    __shared__ int s_nbr[MAXD], s_sgn[MAXD], s_deg;
    __shared__ uint32_t sh[128 * 25];
    if (threadIdx.x == 0) s_deg = min(g_deg[n], MAXD);
    if (threadIdx.x < MAXD) {
        int nb = g_nbr[n * MAXD + threadIdx.x];
        s_nbr[threadIdx.x] = ((unsigned)nb < NN) ? nb : 0;
        s_sgn[threadIdx.x] = g_sgn[n * MAXD + threadIdx.x];
    }
    __syncthreads();
    const int deg = s_deg;
    const int half = threadIdx.x >> 7, p_l = threadIdx.x & 127;
    for (int chunk = 0; chunk < 8; chunk++) {
        int p = chunk * 128 + p_l;
#pragma unroll
        for (int cp = 0; cp < 4; cp++) {
            int u = half * 4 + cp;                    // channel pair index 0..7
            uint32_t sv = g_f16[(size_t)n * 8192 + u * 1024 + p];
            float p0 = 0.f, p1 = 0.f, q0 = 0.f, q1 = 0.f;
            for (int d = 0; d < deg; d++) {
                uint32_t v = g_f16[(size_t)s_nbr[d] * 8192 + u * 1024 + p];
                float2 f2 = __half22float2(*(__half2*)&v);
                if (s_sgn[d] > 0) { p0 += f2.x; p1 += f2.y; }
                else              { q0 += f2.x; q1 += f2.y; }
            }
            sh[p_l * 25 + u]      = sv;               // self: bit-identical copy
            sh[p_l * 25 + 8 + u]  = pack2h(p0, p1);
            sh[p_l * 25 + 16 + u] = pack2h(q0, q1);
        }
        __syncthreads();
        size_t gbase = ((size_t)n * 1024 + chunk * 128) * 24;
        for (int g = threadIdx.x; g < 128 * 24; g += 256) {
            int item = g / 24, u = g % 24;
            g_x16[gbase + g] = sh[item * 25 + u];
        }
        __syncthreads();
    }
}

// ---------------------------------------------------------------------------
// Weight prep (fused): fp32 OIHW -> fp16 [rep][oc][k=tap*CIN+cin] rows pad KP.
// rep 0 = w_hi = fp16(w); rep 1 = w_lo = fp16(w - w_hi).
__device__ __forceinline__ void prep_one(const float* __restrict__ wgt,
                                         __half* __restrict__ gB,
                                         int idx, int CIN, int COUT, int KP) {
    int rep = idx / (COUT * KP);
    int rem = idx % (COUT * KP);
    int oc = rem / KP, kp = rem % KP;
    __half val = __float2half(0.f);
    if (kp < 9 * CIN) {
        int tap = kp / CIN, cin = kp % CIN;
        float wv = wgt[(oc * CIN + cin) * 9 + tap];
        __half h = __float2half(wv);
        val = rep ? __float2half(wv - __half2float(h)) : h;
    }
    gB[idx] = val;
}
#define PW1 (2 * 32 * 440)
#define PW2 (2 * 32 * 296)
#define PW3 (2 * 16 * 296)
__global__ void k_prep(const float* __restrict__ w1, const float* __restrict__ w2,
                       const float* __restrict__ w3) {
    int idx = blockIdx.x * 256 + threadIdx.x;
    if (idx < PW1) prep_one(w1, g_wb1, idx, 48, 32, 440);
    else if (idx < PW1 + PW2) prep_one(w2, g_wb2, idx - PW1, 32, 32, 296);
    else if (idx < PW1 + PW2 + PW3) prep_one(w3, g_wb3, idx - PW1 - PW2, 32, 16, 296);
}

// ---------------------------------------------------------------------------
// HMMA implicit-GEMM conv, fp16 2-term (acc = A*W_hi + A*W_lo), single A plane,
// cp.async staging, optional double-buffered tile pipeline.
// Warp = MT m16 tiles. Plane [ROWS+2][34][CP] fp16 per buffer.
template <int CIN, int COUT, int ROWS, int NWARP, int MT, int KP, bool PACKED, bool DBUF>
__device__ __forceinline__ void conv_body(
    const uint32_t* __restrict__ in16, const __half* __restrict__ gB,
    const float* __restrict__ bias,
    uint32_t* __restrict__ out_pk, float* __restrict__ out_f32) {
    constexpr int CP  = CIN + 8;
    constexpr int NCG = CIN / 16;
    constexpr int NT  = COUT / 8;
    constexpr int NH  = NT / 2;
    constexpr int BB  = 2 * COUT * KP * 2;
    constexpr int PB  = (ROWS + 2) * 34 * CP * 2;   // one fp16 plane
    constexpr int NTHR = NWARP * 32;
    constexpr int TPI = 32 / ROWS;
    constexpr int NTILES = NN * TPI;
    constexpr int IT  = (ROWS + 2) * 34;
    constexpr int CH  = CIN / 8;        // 16B chunks per pixel
    constexpr int CU  = CIN / 2;        // u32 per pixel in global array

    extern __shared__ char smem[];
    char* Bs = smem;

    const int tid = threadIdx.x, wid = tid >> 5, lane = tid & 31;
    const uint32_t Bs_u = smem_u32(Bs);
    const uint32_t P0_u = Bs_u + BB;

    // stage B once (persistent CTA)
    for (int i = tid; i < BB / 4; i += NTHR)
        ((uint32_t*)Bs)[i] = ((const uint32_t*)gB)[i];

    // A-fragment lane mapping (validated R7-R14)
    const int arl = (lane & 7) + ((lane >> 3) & 1) * 8;
    const int akb = lane >> 4;
    uint32_t pb[MT];
#pragma unroll
    for (int mt = 0; mt < MT; mt++) {
        int px = wid * (MT * 16) + mt * 16 + arl;
        pb[mt] = (uint32_t)((((px >> 5) * 34) + (px & 31)) * CP * 2 + akb * 16);
    }
    // B-fragment lane mapping (validated R7-R14)
    const int boc = ((lane >> 4) & 1) * 8 + (lane & 7);
    const int bkb = (lane >> 3) & 1;
    uint32_t bb0[NH], bb1[NH];
#pragma unroll
    for (int h = 0; h < NH; h++) {
        bb0[h] = Bs_u + (uint32_t)((h * 16 + boc) * KP * 2 + bkb * 16);
        bb1[h] = bb0[h] + (uint32_t)(COUT * KP * 2);
    }
    const int g_r = lane >> 2, tg = lane & 3;
    float bv[NT][2];
#pragma unroll
    for (int nt = 0; nt < NT; nt++) {
        bv[nt][0] = __ldg(bias + nt * 8 + tg * 2);
        bv[nt][1] = __ldg(bias + nt * 8 + tg * 2 + 1);
    }

    // staging: pure 16B async copies into plane at `pbase_u`
    auto stage = [&](int t, uint32_t pbase_u) {
        const int n = t / TPI, y0 = (t % TPI) * ROWS;
        const size_t nb = (size_t)n * 1024;
        for (int idx = tid; idx < IT * CH; idx += NTHR) {
            int item = idx / CH, ch = idx % CH;
            int y = item / 34, x = item % 34;
            int yi = y0 - 1 + y, xi = x - 1;
            bool ok = ((unsigned)yi < 32u) && ((unsigned)xi < 32u);
            const char* src = (const char*)(in16 + (nb + (ok ? yi * 32 + xi : 0)) * CU) + ch * 16;
            uint32_t dst = pbase_u + (uint32_t)(item * CP * 2 + ch * 16);
            CP_ASYNC16(dst, src, ok ? 16 : 0);
        }
    };

    int parity = 0;
    if (DBUF && blockIdx.x < NTILES) stage(blockIdx.x, P0_u);
    if (DBUF) CP_COMMIT();

    for (int tile = blockIdx.x; tile < NTILES; tile += gridDim.x) {
        const int n = tile / TPI, y0 = (tile % TPI) * ROWS;
        const size_t nbase = (size_t)n * 1024;
        const uint32_t P_u = DBUF ? (P0_u + (uint32_t)(parity * PB)) : P0_u;

        if (DBUF) {
            int nxt = tile + gridDim.x;
            if (nxt < NTILES) stage(nxt, P0_u + (uint32_t)((parity ^ 1) * PB));
            CP_COMMIT();
            CP_WAIT1();
        } else {
            stage(tile, P0_u);
            CP_COMMIT();
            CP_WAIT0();
        }
        __syncthreads();

        // ---- k loop: A single plane; 2 weight reps (hi, lo) onto same acc ----
        float acc[MT][NT][4];
#pragma unroll
        for (int mt = 0; mt < MT; mt++)
#pragma unroll
            for (int nt = 0; nt < NT; nt++)
                acc[mt][nt][0] = acc[mt][nt][1] = acc[mt][nt][2] = acc[mt][nt][3] = 0.f;

#pragma unroll
        for (int tap = 0; tap < 9; tap++) {
            const uint32_t toff = (uint32_t)(((tap / 3) * 34 + (tap % 3)) * CP * 2);
#pragma unroll
            for (int cg = 0; cg < NCG; cg++) {
                const uint32_t aoff = toff + cg * 32;
                const uint32_t koff = (uint32_t)((tap * CIN + cg * 16) * 2);
                uint32_t a[MT][4];
#pragma unroll
                for (int mt = 0; mt < MT; mt++)
                    LDSM_X4(a[mt][0], a[mt][1], a[mt][2], a[mt][3], P_u + pb[mt] + aoff);
#pragma unroll
                for (int h = 0; h < NH; h++) {
                    uint32_t b0, b1, b2, b3, c0, c1, c2, c3;
                    LDSM_X4(b0, b1, b2, b3, bb0[h] + koff);  // w_hi
                    LDSM_X4(c0, c1, c2, c3, bb1[h] + koff);  // w_lo
#pragma unroll
                    for (int mt = 0; mt < MT; mt++) {
                        MMA16816H(acc[mt][2*h],   a[mt][0], a[mt][1], a[mt][2], a[mt][3], b0, b1);
                        MMA16816H(acc[mt][2*h+1], a[mt][0], a[mt][1], a[mt][2], a[mt][3], b2, b3);
                        MMA16816H(acc[mt][2*h],   a[mt][0], a[mt][1], a[mt][2], a[mt][3], c0, c1);
                        MMA16816H(acc[mt][2*h+1], a[mt][0], a[mt][1], a[mt][2], a[mt][3], c2, c3);
                    }
                }
            }
        }

        // ---- epilogue ----
        if constexpr (PACKED) {
#pragma unroll
            for (int mt = 0; mt < MT; mt++) {
                const int pA = wid * (MT * 16) + mt * 16 + g_r, pB2 = pA + 8;
                const size_t oA = (nbase + y0 * 32 + pA) * (COUT / 2);
                const size_t oB = (nbase + y0 * 32 + pB2) * (COUT / 2);
#pragma unroll
                for (int nt = 0; nt < NT; nt++) {
                    int oc = nt * 8 + tg * 2;
                    float v0 = acc[mt][nt][0] + bv[nt][0];
                    float v1 = acc[mt][nt][1] + bv[nt][1];
                    float v2 = acc[mt][nt][2] + bv[nt][0];
                    float v3 = acc[mt][nt][3] + bv[nt][1];
                    v0 = v0 > 0.f ? v0 : 0.1f * v0;
                    v1 = v1 > 0.f ? v1 : 0.1f * v1;
                    v2 = v2 > 0.f ? v2 : 0.1f * v2;
                    v3 = v3 > 0.f ? v3 : 0.1f * v3;
                    out_pk[oA + (oc >> 1)] = pack2h(v0, v1);
                    out_pk[oB + (oc >> 1)] = pack2h(v2, v3);
                }
            }
        } else {
            float* ob = out_f32 + (size_t)n * COUT * HW + y0 * 32;
#pragma unroll
            for (int mt = 0; mt < MT; mt++) {
                const int pA = wid * (MT * 16) + mt * 16 + g_r, pB2 = pA + 8;
#pragma unroll
                for (int nt = 0; nt < NT; nt++) {
                    int oc = nt * 8 + tg * 2;
                    float v;
                    v = acc[mt][nt][0] + bv[nt][0]; v = v > 0.f ? v : 0.1f * v; ob[(size_t)oc * HW + pA] = v;
                    v = acc[mt][nt][1] + bv[nt][1]; v = v > 0.f ? v : 0.1f * v; ob[(size_t)(oc + 1) * HW + pA] = v;
                    v = acc[mt][nt][2] + bv[nt][0]; v = v > 0.f ? v : 0.1f * v; ob[(size_t)oc * HW + pB2] = v;
                    v = acc[mt][nt][3] + bv[nt][1]; v = v > 0.f ? v : 0.1f * v; ob[(size_t)(oc + 1) * HW + pB2] = v;
                }
            }
        }
        __syncthreads();   // protect plane before next staging overwrites
        parity ^= 1;
    }
}

// conv1: ROWS=16, 16 warps, MT=2, double-buffered (1 CTA/SM)
__global__ __launch_bounds__(512, 1) void k_mconv1(const float* __restrict__ b) {
    conv_body<48, 32, 16, 16, 2, 440, true, true>(g_x16, g_wb1, b, g_t116, nullptr);
}
// conv2/3: ROWS=8, 8 warps, MT=2, double-buffered, 2 CTAs/SM
__global__ __launch_bounds__(256, 2) void k_mconv2(const float* __restrict__ b) {
    conv_body<32, 32, 8, 8, 2, 296, true, true>(g_t116, g_wb2, b, g_t216, nullptr);
}
__global__ __launch_bounds__(256, 2) void k_mconv3(const float* __restrict__ b,
                                                   float* __restrict__ out) {
    conv_body<32, 16, 8, 8, 2, 296, false, true>(g_t216, g_wb3, b, nullptr, out);
}

// ---------------------------------------------------------------------------
static inline int smsz(int CIN, int COUT, int KP, int ROWS, int nbuf) {
    return 2 * COUT * KP * 2 + nbuf * ((ROWS + 2) * 34 * (CIN + 8) * 2);
}

extern "C" void kernel_launch(void* const* d_in, const int* in_sizes, int n_in,
                              void* d_out, int out_size) {
    const float* feats = nullptr;
    const void*  edges = nullptr;
    const float *w1 = nullptr, *b1 = nullptr, *w2 = nullptr, *b2 = nullptr;
    const float *w3 = nullptr, *b3 = nullptr;
    int b32_seen = 0;
    for (int i = 0; i < n_in; i++) {
        switch (in_sizes[i]) {
            case 16777216: feats = (const float*)d_in[i]; break;
            case 12288:
            case 24576:    edges = d_in[i]; break;
            case 13824:    w1 = (const float*)d_in[i]; break;
            case 9216:     w2 = (const float*)d_in[i]; break;
            case 4608:     w3 = (const float*)d_in[i]; break;
            case 32:       if (b32_seen++ == 0) b1 = (const float*)d_in[i];
                           else                 b2 = (const float*)d_in[i];
                           break;
            case 16:       b3 = (const float*)d_in[i]; break;
            default: break;
        }
    }
    if (!feats || !edges || !w1 || !b1 || !w2 || !b2 || !w3 || !b3) {
        feats = (const float*)d_in[0];
        edges = d_in[1];
        w1 = (const float*)d_in[2]; b1 = (const float*)d_in[3];
        w2 = (const float*)d_in[4]; b2 = (const float*)d_in[5];
        w3 = (const float*)d_in[6]; b3 = (const float*)d_in[7];
    }
    float* out = (float*)d_out;

    // Idempotent, not a stream op — safe on every call.
    cudaFuncSetAttribute(k_mconv1, cudaFuncAttributeMaxDynamicSharedMemorySize, smsz(48, 32, 440, 16, 2));
    cudaFuncSetAttribute(k_mconv2, cudaFuncAttributeMaxDynamicSharedMemorySize, smsz(32, 32, 296, 8, 2));
    cudaFuncSetAttribute(k_mconv3, cudaFuncAttributeMaxDynamicSharedMemorySize, smsz(32, 16, 296, 8, 2));

    k_zeroadj<<<1, 1024>>>(edges);
    k_cvt<<<(NN * 8 * HW) / 256, 256>>>(feats);
    k_prep<<<(PW1 + PW2 + PW3 + 255) / 256, 256>>>(w1, w2, w3);
    k_build<<<NN, 256>>>();
    k_mconv1<<<148, 512, smsz(48, 32, 440, 16, 2)>>>(b1);
    k_mconv2<<<296, 256, smsz(32, 32, 296, 8, 2)>>>(b2);
    k_mconv3<<<296, 256, smsz(32, 16, 296, 8, 2)>>>(b3, out);
}

// round 16
// speedup vs baseline: 9.8923x; 1.1206x over previous
#include <cuda_runtime.h>
#include <cuda_fp16.h>
#include <cstdint>

// Problem constants
#define NN   1024
#define HW   1024
#define NE   4096
#define MAXD 64

// ---------------------------------------------------------------------------
// Scratch (__device__ globals). Conv tensors stored fp16 channel-last:
// arr[n][px][c/2] as u32 = (fp16 c | fp16 c+1 << 16).
__device__ uint32_t g_f16 [(size_t)NN * HW * 8];   // feats, channel-last [n][px][8]
__device__ uint32_t g_x16 [(size_t)NN * HW * 24];  // x, 48ch -> 24 u32 (channel-last)
__device__ uint32_t g_t116[(size_t)NN * HW * 16];  // t1, 32ch
__device__ uint32_t g_t216[(size_t)NN * HW * 16];  // t2, 32ch
__device__ int g_deg[NN];
__device__ int g_nbr[NN * MAXD];
__device__ int g_sgn[NN * MAXD];
// Weight images fp16: [rep(hi/lo)][oc][k = tap*CIN + cin], rows padded to KP
__device__ __half g_wb1[2 * 32 * 440];
__device__ __half g_wb2[2 * 32 * 296];
__device__ __half g_wb3[2 * 16 * 296];

// ---------------------------------------------------------------------------
__device__ __forceinline__ uint32_t smem_u32(const void* p) {
    uint32_t a;
    asm("{ .reg .u64 t; cvta.to.shared.u64 t, %1; cvt.u32.u64 %0, t; }" : "=r"(a) : "l"(p));
    return a;
}

#define LDSM_X4(r0, r1, r2, r3, addr) \
    asm volatile("ldmatrix.sync.aligned.m8n8.x4.shared.b16 {%0,%1,%2,%3}, [%4];" \
        : "=r"(r0), "=r"(r1), "=r"(r2), "=r"(r3) : "r"(addr))

#define MMA16816H(d, a0, a1, a2, a3, b0, b1) \
    asm volatile("mma.sync.aligned.m16n8k16.row.col.f32.f16.f16.f32 " \
        "{%0,%1,%2,%3}, {%4,%5,%6,%7}, {%8,%9}, {%0,%1,%2,%3};" \
        : "+f"((d)[0]), "+f"((d)[1]), "+f"((d)[2]), "+f"((d)[3]) \
        : "r"(a0), "r"(a1), "r"(a2), "r"(a3), "r"(b0), "r"(b1))

#define CP_ASYNC16(dst, src, sz) \
    asm volatile("cp.async.cg.shared.global [%0], [%1], 16, %2;" \
        :: "r"(dst), "l"(src), "r"(sz))
#define CP_COMMIT() asm volatile("cp.async.commit_group;" ::: "memory")
#define CP_WAIT0()  asm volatile("cp.async.wait_group 0;" ::: "memory")
#define CP_WAIT1()  asm volatile("cp.async.wait_group 1;" ::: "memory")

__device__ __forceinline__ uint32_t pack2h(float v0, float v1) {
    __half h0 = __float2half(v0), h1 = __float2half(v1);
    return (uint32_t)__half_as_ushort(h0) | ((uint32_t)__half_as_ushort(h1) << 16);
}
__device__ __forceinline__ __half2 u2h2(uint32_t u) {
    return *reinterpret_cast<__half2*>(&u);
}
__device__ __forceinline__ uint32_t h22u(__half2 h) {
    return *reinterpret_cast<uint32_t*>(&h);
}

// ---------------------------------------------------------------------------
__device__ __forceinline__ int detect_edge_mode(const unsigned* w) {
    bool any_floatish = false, odd_ok = true;
#pragma unroll
    for (int i = 0; i < 24; i++) {
        unsigned v = w[i];
        if (v >= 0x30000000u && v < 0xF0000000u) any_floatish = true;
        if ((i & 1) && !(v == 0u || v == 0xFFFFFFFFu)) odd_ok = false;
    }
    if (any_floatish) return 2;
    if (odd_ok) return 0;
    return 1;
}

// Fused: zero degree counters + build adjacency. One 1024-thread CTA.
__global__ void k_zeroadj(const void* __restrict__ edges_raw) {
    int tid = threadIdx.x;
    g_deg[tid] = 0;
    __syncthreads();
    int mode = detect_edge_mode((const unsigned*)edges_raw);
    for (int e = tid; e < NE; e += 1024) {
        int src, dst, sgn;
        if (mode == 0) {
            const long long* p = (const long long*)edges_raw;
            src = (int)p[3 * e]; sgn = (p[3 * e + 1] > 0) ? 1 : -1; dst = (int)p[3 * e + 2];
        } else if (mode == 1) {
            const int* p = (const int*)edges_raw;
            src = p[3 * e]; sgn = (p[3 * e + 1] > 0) ? 1 : -1; dst = p[3 * e + 2];
        } else {
            const float* p = (const float*)edges_raw;
            src = (int)p[3 * e]; sgn = (p[3 * e + 1] > 0.f) ? 1 : -1; dst = (int)p[3 * e + 2];
        }
        if ((unsigned)src >= NN || (unsigned)dst >= NN) continue;
        int q = atomicAdd(&g_deg[dst], 1);
        if (q < MAXD) { g_nbr[dst * MAXD + q] = src; g_sgn[dst * MAXD + q] = sgn; }
        q = atomicAdd(&g_deg[src], 1);
        if (q < MAXD) { g_nbr[src * MAXD + q] = dst; g_sgn[src * MAXD + q] = sgn; }
    }
}

// feats fp32 NCHW -> fp16 packed channel-last [n][px][8 u32].
__global__ void k_cvt(const float* __restrict__ feats) {
    size_t i = (size_t)blockIdx.x * 256 + threadIdx.x;   // over NN*HW*8
    int n = (int)(i >> 13);
    int r = (int)(i & 8191);
    int px = r >> 3, c2 = r & 7;
    const float* f = feats + (size_t)n * 16384 + (size_t)c2 * 2048 + px;
    g_f16[i] = pack2h(f[0], f[1024]);
}

// Pool + concat, channel-last in/out, vectorized 16B gathers, half2 accum.
// One CTA per node; thread handles 4 pixels.
__global__ __launch_bounds__(256) void k_build() {
    int n = blockIdx.x;
    __shared__ int s_nbr[MAXD], s_sgn[MAXD], s_deg;
    if (threadIdx.x == 0) s_deg = min(g_deg[n], MAXD);
    if (threadIdx.x < MAXD) {
        int nb = g_nbr[n * MAXD + threadIdx.x];
        s_nbr[threadIdx.x] = ((unsigned)nb < NN) ? nb : 0;
        s_sgn[threadIdx.x] = g_sgn[n * MAXD + threadIdx.x];
    }
    __syncthreads();
    const int deg = s_deg;
#pragma unroll
    for (int j = 0; j < 4; j++) {
        int px = j * 256 + threadIdx.x;
        const uint4* sp = (const uint4*)(g_f16 + ((size_t)n * 1024 + px) * 8);
        uint4 s0 = sp[0], s1 = sp[1];
        __half2 pos[8], neg[8];
#pragma unroll
        for (int u = 0; u < 8; u++) {
            pos[u] = __floats2half2_rn(0.f, 0.f);
            neg[u] = __floats2half2_rn(0.f, 0.f);
        }
        for (int d = 0; d < deg; d++) {
            const uint4* np = (const uint4*)(g_f16 + ((size_t)s_nbr[d] * 1024 + px) * 8);
            uint4 v0 = np[0], v1 = np[1];
            if (s_sgn[d] > 0) {                     // warp-uniform branch
                pos[0] = __hadd2(pos[0], u2h2(v0.x));
                pos[1] = __hadd2(pos[1], u2h2(v0.y));
                pos[2] = __hadd2(pos[2], u2h2(v0.z));
                pos[3] = __hadd2(pos[3], u2h2(v0.w));
                pos[4] = __hadd2(pos[4], u2h2(v1.x));
                pos[5] = __hadd2(pos[5], u2h2(v1.y));
                pos[6] = __hadd2(pos[6], u2h2(v1.z));
                pos[7] = __hadd2(pos[7], u2h2(v1.w));
            } else {
                neg[0] = __hadd2(neg[0], u2h2(v0.x));
                neg[1] = __hadd2(neg[1], u2h2(v0.y));
                neg[2] = __hadd2(neg[2], u2h2(v0.z));
                neg[3] = __hadd2(neg[3], u2h2(v0.w));
                neg[4] = __hadd2(neg[4], u2h2(v1.x));
                neg[5] = __hadd2(neg[5], u2h2(v1.y));
                neg[6] = __hadd2(neg[6], u2h2(v1.z));
                neg[7] = __hadd2(neg[7], u2h2(v1.w));
            }
        }
        uint4* op = (uint4*)(g_x16 + ((size_t)n * 1024 + px) * 24);
        op[0] = s0;                                 // self: bit-identical
        op[1] = s1;
        uint4 o;
        o.x = h22u(pos[0]); o.y = h22u(pos[1]); o.z = h22u(pos[2]); o.w = h22u(pos[3]);
        op[2] = o;
        o.x = h22u(pos[4]); o.y = h22u(pos[5]); o.z = h22u(pos[6]); o.w = h22u(pos[7]);
        op[3] = o;
        o.x = h22u(neg[0]); o.y = h22u(neg[1]); o.z = h22u(neg[2]); o.w = h22u(neg[3]);
        op[4] = o;
        o.x = h22u(neg[4]); o.y = h22u(neg[5]); o.z = h22u(neg[6]); o.w = h22u(neg[7]);
        op[5] = o;
    }
}

// ---------------------------------------------------------------------------
// Weight prep (fused): fp32 OIHW -> fp16 [rep][oc][k=tap*CIN+cin] rows pad KP.
// rep 0 = w_hi = fp16(w); rep 1 = w_lo = fp16(w - w_hi).
__device__ __forceinline__ void prep_one(const float* __restrict__ wgt,
                                         __half* __restrict__ gB,
                                         int idx, int CIN, int COUT, int KP) {
    int rep = idx / (COUT * KP);
    int rem = idx % (COUT * KP);
    int oc = rem / KP, kp = rem % KP;
    __half val = __float2half(0.f);
    if (kp < 9 * CIN) {
        int tap = kp / CIN, cin = kp % CIN;
        float wv = wgt[(oc * CIN + cin) * 9 + tap];
        __half h = __float2half(wv);
        val = rep ? __float2half(wv - __half2float(h)) : h;
    }
    gB[idx] = val;
}
#define PW1 (2 * 32 * 440)
#define PW2 (2 * 32 * 296)
#define PW3 (2 * 16 * 296)
__global__ void k_prep(const float* __restrict__ w1, const float* __restrict__ w2,
                       const float* __restrict__ w3) {
    int idx = blockIdx.x * 256 + threadIdx.x;
    if (idx < PW1) prep_one(w1, g_wb1, idx, 48, 32, 440);
    else if (idx < PW1 + PW2) prep_one(w2, g_wb2, idx - PW1, 32, 32, 296);
    else if (idx < PW1 + PW2 + PW3) prep_one(w3, g_wb3, idx - PW1 - PW2, 32, 16, 296);
}

// ---------------------------------------------------------------------------
// HMMA implicit-GEMM conv, fp16 2-term (acc = A*W_hi + A*W_lo), single A plane,
// cp.async staging, optional double-buffered tile pipeline.
// Warp = MT m16 tiles. Plane [ROWS+2][34][CP] fp16 per buffer.
template <int CIN, int COUT, int ROWS, int NWARP, int MT, int KP, bool PACKED, bool DBUF>
__device__ __forceinline__ void conv_body(
    const uint32_t* __restrict__ in16, const __half* __restrict__ gB,
    const float* __restrict__ bias,
    uint32_t* __restrict__ out_pk, float* __restrict__ out_f32) {
    constexpr int CP  = CIN + 8;
    constexpr int NCG = CIN / 16;
    constexpr int NT  = COUT / 8;
    constexpr int NH  = NT / 2;
    constexpr int BB  = 2 * COUT * KP * 2;
    constexpr int PB  = (ROWS + 2) * 34 * CP * 2;   // one fp16 plane
    constexpr int NTHR = NWARP * 32;
    constexpr int TPI = 32 / ROWS;
    constexpr int NTILES = NN * TPI;
    constexpr int IT  = (ROWS + 2) * 34;
    constexpr int CH  = CIN / 8;        // 16B chunks per pixel
    constexpr int CU  = CIN / 2;        // u32 per pixel in global array

    extern __shared__ char smem[];
    char* Bs = smem;

    const int tid = threadIdx.x, wid = tid >> 5, lane = tid & 31;
    const uint32_t Bs_u = smem_u32(Bs);
    const uint32_t P0_u = Bs_u + BB;

    // stage B once (persistent CTA)
    for (int i = tid; i < BB / 4; i += NTHR)
        ((uint32_t*)Bs)[i] = ((const uint32_t*)gB)[i];

    // A-fragment lane mapping (validated R7-R15)
    const int arl = (lane & 7) + ((lane >> 3) & 1) * 8;
    const int akb = lane >> 4;
    uint32_t pb[MT];
#pragma unroll
    for (int mt = 0; mt < MT; mt++) {
        int px = wid * (MT * 16) + mt * 16 + arl;
        pb[mt] = (uint32_t)((((px >> 5) * 34) + (px & 31)) * CP * 2 + akb * 16);
    }
    // B-fragment lane mapping (validated R7-R15)
    const int boc = ((lane >> 4) & 1) * 8 + (lane & 7);
    const int bkb = (lane >> 3) & 1;
    uint32_t bb0[NH], bb1[NH];
#pragma unroll
    for (int h = 0; h < NH; h++) {
        bb0[h] = Bs_u + (uint32_t)((h * 16 + boc) * KP * 2 + bkb * 16);
        bb1[h] = bb0[h] + (uint32_t)(COUT * KP * 2);
    }
    const int g_r = lane >> 2, tg = lane & 3;
    float bv[NT][2];
#pragma unroll
    for (int nt = 0; nt < NT; nt++) {
        bv[nt][0] = __ldg(bias + nt * 8 + tg * 2);
        bv[nt][1] = __ldg(bias + nt * 8 + tg * 2 + 1);
    }

    // staging: pure 16B async copies into plane at `pbase_u`
    auto stage = [&](int t, uint32_t pbase_u) {
        const int n = t / TPI, y0 = (t % TPI) * ROWS;
        const size_t nb = (size_t)n * 1024;
        for (int idx = tid; idx < IT * CH; idx += NTHR) {
            int item = idx / CH, ch = idx % CH;
            int y = item / 34, x = item % 34;
            int yi = y0 - 1 + y, xi = x - 1;
            bool ok = ((unsigned)yi < 32u) && ((unsigned)xi < 32u);
            const char* src = (const char*)(in16 + (nb + (ok ? yi * 32 + xi : 0)) * CU) + ch * 16;
            uint32_t dst = pbase_u + (uint32_t)(item * CP * 2 + ch * 16);
            CP_ASYNC16(dst, src, ok ? 16 : 0);
        }
    };

    int parity = 0;
    if (DBUF && blockIdx.x < NTILES) stage(blockIdx.x, P0_u);
    if (DBUF) CP_COMMIT();

    for (int tile = blockIdx.x; tile < NTILES; tile += gridDim.x) {
        const int n = tile / TPI, y0 = (tile % TPI) * ROWS;
        const size_t nbase = (size_t)n * 1024;
        const uint32_t P_u = DBUF ? (P0_u + (uint32_t)(parity * PB)) : P0_u;

        if (DBUF) {
            int nxt = tile + gridDim.x;
            if (nxt < NTILES) stage(nxt, P0_u + (uint32_t)((parity ^ 1) * PB));
            CP_COMMIT();
            CP_WAIT1();
        } else {
            stage(tile, P0_u);
            CP_COMMIT();
            CP_WAIT0();
        }
        __syncthreads();

        // ---- k loop: A single plane; 2 weight reps (hi, lo) onto same acc ----
        float acc[MT][NT][4];
#pragma unroll
        for (int mt = 0; mt < MT; mt++)
#pragma unroll
            for (int nt = 0; nt < NT; nt++)
                acc[mt][nt][0] = acc[mt][nt][1] = acc[mt][nt][2] = acc[mt][nt][3] = 0.f;

#pragma unroll
        for (int tap = 0; tap < 9; tap++) {
            const uint32_t toff = (uint32_t)(((tap / 3) * 34 + (tap % 3)) * CP * 2);
#pragma unroll
            for (int cg = 0; cg < NCG; cg++) {
                const uint32_t aoff = toff + cg * 32;
                const uint32_t koff = (uint32_t)((tap * CIN + cg * 16) * 2);
                uint32_t a[MT][4];
#pragma unroll
                for (int mt = 0; mt < MT; mt++)
                    LDSM_X4(a[mt][0], a[mt][1], a[mt][2], a[mt][3], P_u + pb[mt] + aoff);
#pragma unroll
                for (int h = 0; h < NH; h++) {
                    uint32_t b0, b1, b2, b3, c0, c1, c2, c3;
                    LDSM_X4(b0, b1, b2, b3, bb0[h] + koff);  // w_hi
                    LDSM_X4(c0, c1, c2, c3, bb1[h] + koff);  // w_lo
#pragma unroll
                    for (int mt = 0; mt < MT; mt++) {
                        MMA16816H(acc[mt][2*h],   a[mt][0], a[mt][1], a[mt][2], a[mt][3], b0, b1);
                        MMA16816H(acc[mt][2*h+1], a[mt][0], a[mt][1], a[mt][2], a[mt][3], b2, b3);
                        MMA16816H(acc[mt][2*h],   a[mt][0], a[mt][1], a[mt][2], a[mt][3], c0, c1);
                        MMA16816H(acc[mt][2*h+1], a[mt][0], a[mt][1], a[mt][2], a[mt][3], c2, c3);
                    }
                }
            }
        }

        // ---- epilogue ----
        if constexpr (PACKED) {
#pragma unroll
            for (int mt = 0; mt < MT; mt++) {
                const int pA = wid * (MT * 16) + mt * 16 + g_r, pB2 = pA + 8;
                const size_t oA = (nbase + y0 * 32 + pA) * (COUT / 2);
                const size_t oB = (nbase + y0 * 32 + pB2) * (COUT / 2);
#pragma unroll
                for (int nt = 0; nt < NT; nt++) {
                    int oc = nt * 8 + tg * 2;
                    float v0 = acc[mt][nt][0] + bv[nt][0];
                    float v1 = acc[mt][nt][1] + bv[nt][1];
                    float v2 = acc[mt][nt][2] + bv[nt][0];
                    float v3 = acc[mt][nt][3] + bv[nt][1];
                    v0 = v0 > 0.f ? v0 : 0.1f * v0;
                    v1 = v1 > 0.f ? v1 : 0.1f * v1;
                    v2 = v2 > 0.f ? v2 : 0.1f * v2;
                    v3 = v3 > 0.f ? v3 : 0.1f * v3;
                    out_pk[oA + (oc >> 1)] = pack2h(v0, v1);
                    out_pk[oB + (oc >> 1)] = pack2h(v2, v3);
                }
            }
        } else {
            float* ob = out_f32 + (size_t)n * COUT * HW + y0 * 32;
#pragma unroll
            for (int mt = 0; mt < MT; mt++) {
                const int pA = wid * (MT * 16) + mt * 16 + g_r, pB2 = pA + 8;
#pragma unroll
                for (int nt = 0; nt < NT; nt++) {
                    int oc = nt * 8 + tg * 2;
                    float v;
                    v = acc[mt][nt][0] + bv[nt][0]; v = v > 0.f ? v : 0.1f * v; ob[(size_t)oc * HW + pA] = v;
                    v = acc[mt][nt][1] + bv[nt][1]; v = v > 0.f ? v : 0.1f * v; ob[(size_t)(oc + 1) * HW + pA] = v;
                    v = acc[mt][nt][2] + bv[nt][0]; v = v > 0.f ? v : 0.1f * v; ob[(size_t)oc * HW + pB2] = v;
                    v = acc[mt][nt][3] + bv[nt][1]; v = v > 0.f ? v : 0.1f * v; ob[(size_t)(oc + 1) * HW + pB2] = v;
                }
            }
        }
        __syncthreads();   // protect plane before next staging overwrites
        parity ^= 1;
    }
}

// conv1: ROWS=16, 16 warps, MT=2, double-buffered (1 CTA/SM)
__global__ __launch_bounds__(512, 1) void k_mconv1(const float* __restrict__ b) {
    conv_body<48, 32, 16, 16, 2, 440, true, true>(g_x16, g_wb1, b, g_t116, nullptr);
}
// conv2/3: ROWS=8, 8 warps, MT=2, double-buffered, 2 CTAs/SM
__global__ __launch_bounds__(256, 2) void k_mconv2(const float* __restrict__ b) {
    conv_body<32, 32, 8, 8, 2, 296, true, true>(g_t116, g_wb2, b, g_t216, nullptr);
}
__global__ __launch_bounds__(256, 2) void k_mconv3(const float* __restrict__ b,
                                                   float* __restrict__ out) {
    conv_body<32, 16, 8, 8, 2, 296, false, true>(g_t216, g_wb3, b, nullptr, out);
}

// ---------------------------------------------------------------------------
static inline int smsz(int CIN, int COUT, int KP, int ROWS, int nbuf) {
    return 2 * COUT * KP * 2 + nbuf * ((ROWS + 2) * 34 * (CIN + 8) * 2);
}

extern "C" void kernel_launch(void* const* d_in, const int* in_sizes, int n_in,
                              void* d_out, int out_size) {
    const float* feats = nullptr;
    const void*  edges = nullptr;
    const float *w1 = nullptr, *b1 = nullptr, *w2 = nullptr, *b2 = nullptr;
    const float *w3 = nullptr, *b3 = nullptr;
    int b32_seen = 0;
    for (int i = 0; i < n_in; i++) {
        switch (in_sizes[i]) {
            case 16777216: feats = (const float*)d_in[i]; break;
            case 12288:
            case 24576:    edges = d_in[i]; break;
            case 13824:    w1 = (const float*)d_in[i]; break;
            case 9216:     w2 = (const float*)d_in[i]; break;
            case 4608:     w3 = (const float*)d_in[i]; break;
            case 32:       if (b32_seen++ == 0) b1 = (const float*)d_in[i];
                           else                 b2 = (const float*)d_in[i];
                           break;
            case 16:       b3 = (const float*)d_in[i]; break;
            default: break;
        }
    }
    if (!feats || !edges || !w1 || !b1 || !w2 || !b2 || !w3 || !b3) {
        feats = (const float*)d_in[0];
        edges = d_in[1];
        w1 = (const float*)d_in[2]; b1 = (const float*)d_in[3];
        w2 = (const float*)d_in[4]; b2 = (const float*)d_in[5];
        w3 = (const float*)d_in[6]; b3 = (const float*)d_in[7];
    }
    float* out = (float*)d_out;

    // Idempotent, not a stream op — safe on every call.
    cudaFuncSetAttribute(k_mconv1, cudaFuncAttributeMaxDynamicSharedMemorySize, smsz(48, 32, 440, 16, 2));
    cudaFuncSetAttribute(k_mconv2, cudaFuncAttributeMaxDynamicSharedMemorySize, smsz(32, 32, 296, 8, 2));
    cudaFuncSetAttribute(k_mconv3, cudaFuncAttributeMaxDynamicSharedMemorySize, smsz(32, 16, 296, 8, 2));

    k_zeroadj<<<1, 1024>>>(edges);
    k_cvt<<<(NN * 8 * HW) / 256, 256>>>(feats);
    k_prep<<<(PW1 + PW2 + PW3 + 255) / 256, 256>>>(w1, w2, w3);
    k_build<<<NN, 256>>>();
    k_mconv1<<<148, 512, smsz(48, 32, 440, 16, 2)>>>(b1);
    k_mconv2<<<296, 256, smsz(32, 32, 296, 8, 2)>>>(b2);
    k_mconv3<<<296, 256, smsz(32, 16, 296, 8, 2)>>>(b3, out);
}

// round 17
// speedup vs baseline: 10.0477x; 1.0157x over previous
#include <cuda_runtime.h>
#include <cuda_fp16.h>
#include <cstdint>

// Problem constants
#define NN   1024
#define HW   1024
#define NE   4096
#define MAXD 64

// ---------------------------------------------------------------------------
// Scratch (__device__ globals). Conv tensors stored fp16 channel-last:
// arr[n][px][c/2] as u32 = (fp16 c | fp16 c+1 << 16).
__device__ uint32_t g_f16 [(size_t)NN * HW * 8];   // feats, channel-last [n][px][8]
__device__ uint32_t g_x16 [(size_t)NN * HW * 24];  // x, 48ch -> 24 u32 (channel-last)
__device__ uint32_t g_t116[(size_t)NN * HW * 16];  // t1, 32ch
__device__ uint32_t g_t216[(size_t)NN * HW * 16];  // t2, 32ch
__device__ int g_deg[NN];
__device__ int g_nbr[NN * MAXD];
__device__ int g_sgn[NN * MAXD];
// Weight images fp16: [rep(hi/lo)][oc][k = tap*CIN + cin], rows padded to KP
__device__ __half g_wb1[2 * 32 * 440];
__device__ __half g_wb2[2 * 32 * 296];
__device__ __half g_wb3[2 * 16 * 296];

// ---------------------------------------------------------------------------
__device__ __forceinline__ uint32_t smem_u32(const void* p) {
    uint32_t a;
    asm("{ .reg .u64 t; cvta.to.shared.u64 t, %1; cvt.u32.u64 %0, t; }" : "=r"(a) : "l"(p));
    return a;
}

#define LDSM_X4(r0, r1, r2, r3, addr) \
    asm volatile("ldmatrix.sync.aligned.m8n8.x4.shared.b16 {%0,%1,%2,%3}, [%4];" \
        : "=r"(r0), "=r"(r1), "=r"(r2), "=r"(r3) : "r"(addr))

#define MMA16816H(d, a0, a1, a2, a3, b0, b1) \
    asm volatile("mma.sync.aligned.m16n8k16.row.col.f32.f16.f16.f32 " \
        "{%0,%1,%2,%3}, {%4,%5,%6,%7}, {%8,%9}, {%0,%1,%2,%3};" \
        : "+f"((d)[0]), "+f"((d)[1]), "+f"((d)[2]), "+f"((d)[3]) \
        : "r"(a0), "r"(a1), "r"(a2), "r"(a3), "r"(b0), "r"(b1))

#define CP_ASYNC16(dst, src, sz) \
    asm volatile("cp.async.cg.shared.global [%0], [%1], 16, %2;" \
        :: "r"(dst), "l"(src), "r"(sz))
#define CP_COMMIT() asm volatile("cp.async.commit_group;" ::: "memory")
#define CP_WAIT0()  asm volatile("cp.async.wait_group 0;" ::: "memory")
#define CP_WAIT1()  asm volatile("cp.async.wait_group 1;" ::: "memory")

__device__ __forceinline__ uint32_t pack2h(float v0, float v1) {
    __half h0 = __float2half(v0), h1 = __float2half(v1);
    return (uint32_t)__half_as_ushort(h0) | ((uint32_t)__half_as_ushort(h1) << 16);
}
__device__ __forceinline__ __half2 u2h2(uint32_t u) {
    return *reinterpret_cast<__half2*>(&u);
}
__device__ __forceinline__ uint32_t h22u(__half2 h) {
    return *reinterpret_cast<uint32_t*>(&h);
}

// ---------------------------------------------------------------------------
__device__ __forceinline__ int detect_edge_mode(const unsigned* w) {
    bool any_floatish = false, odd_ok = true;
#pragma unroll
    for (int i = 0; i < 24; i++) {
        unsigned v = w[i];
        if (v >= 0x30000000u && v < 0xF0000000u) any_floatish = true;
        if ((i & 1) && !(v == 0u || v == 0xFFFFFFFFu)) odd_ok = false;
    }
    if (any_floatish) return 2;
    if (odd_ok) return 0;
    return 1;
}

// Fused: zero degree counters + build adjacency. One 1024-thread CTA.
__global__ void k_zeroadj(const void* __restrict__ edges_raw) {
    int tid = threadIdx.x;
    g_deg[tid] = 0;
    __syncthreads();
    int mode = detect_edge_mode((const unsigned*)edges_raw);
    for (int e = tid; e < NE; e += 1024) {
        int src, dst, sgn;
        if (mode == 0) {
            const long long* p = (const long long*)edges_raw;
            src = (int)p[3 * e]; sgn = (p[3 * e + 1] > 0) ? 1 : -1; dst = (int)p[3 * e + 2];
        } else if (mode == 1) {
            const int* p = (const int*)edges_raw;
            src = p[3 * e]; sgn = (p[3 * e + 1] > 0) ? 1 : -1; dst = p[3 * e + 2];
        } else {
            const float* p = (const float*)edges_raw;
            src = (int)p[3 * e]; sgn = (p[3 * e + 1] > 0.f) ? 1 : -1; dst = (int)p[3 * e + 2];
        }
        if ((unsigned)src >= NN || (unsigned)dst >= NN) continue;
        int q = atomicAdd(&g_deg[dst], 1);
        if (q < MAXD) { g_nbr[dst * MAXD + q] = src; g_sgn[dst * MAXD + q] = sgn; }
        q = atomicAdd(&g_deg[src], 1);
        if (q < MAXD) { g_nbr[src * MAXD + q] = dst; g_sgn[src * MAXD + q] = sgn; }
    }
}

// feats fp32 NCHW -> fp16 packed channel-last [n][px][8 u32].
__global__ void k_cvt(const float* __restrict__ feats) {
    size_t i = (size_t)blockIdx.x * 256 + threadIdx.x;   // over NN*HW*8
    int n = (int)(i >> 13);
    int r = (int)(i & 8191);
    int px = r >> 3, c2 = r & 7;
    const float* f = feats + (size_t)n * 16384 + (size_t)c2 * 2048 + px;
    g_f16[i] = pack2h(f[0], f[1024]);
}

// Pool + concat, channel-last in/out, vectorized 16B gathers, half2 accum.
// One CTA per (node, quarter): 4096 CTAs, 1 pixel per thread (max MLP/occ).
__global__ __launch_bounds__(256) void k_build() {
    int n = blockIdx.x >> 2;
    int px = (blockIdx.x & 3) * 256 + threadIdx.x;
    __shared__ int s_nbr[MAXD], s_sgn[MAXD], s_deg;
    if (threadIdx.x == 0) s_deg = min(g_deg[n], MAXD);
    if (threadIdx.x < MAXD) {
        int nb = g_nbr[n * MAXD + threadIdx.x];
        s_nbr[threadIdx.x] = ((unsigned)nb < NN) ? nb : 0;
        s_sgn[threadIdx.x] = g_sgn[n * MAXD + threadIdx.x];
    }
    __syncthreads();
    const int deg = s_deg;

    const uint4* sp = (const uint4*)(g_f16 + ((size_t)n * 1024 + px) * 8);
    uint4 s0 = sp[0], s1 = sp[1];
    __half2 pos[8], neg[8];
#pragma unroll
    for (int u = 0; u < 8; u++) {
        pos[u] = __floats2half2_rn(0.f, 0.f);
        neg[u] = __floats2half2_rn(0.f, 0.f);
    }
    for (int d = 0; d < deg; d++) {
        const uint4* np = (const uint4*)(g_f16 + ((size_t)s_nbr[d] * 1024 + px) * 8);
        uint4 v0 = np[0], v1 = np[1];
        if (s_sgn[d] > 0) {                     // warp-uniform branch
            pos[0] = __hadd2(pos[0], u2h2(v0.x));
            pos[1] = __hadd2(pos[1], u2h2(v0.y));
            pos[2] = __hadd2(pos[2], u2h2(v0.z));
            pos[3] = __hadd2(pos[3], u2h2(v0.w));
            pos[4] = __hadd2(pos[4], u2h2(v1.x));
            pos[5] = __hadd2(pos[5], u2h2(v1.y));
            pos[6] = __hadd2(pos[6], u2h2(v1.z));
            pos[7] = __hadd2(pos[7], u2h2(v1.w));
        } else {
            neg[0] = __hadd2(neg[0], u2h2(v0.x));
            neg[1] = __hadd2(neg[1], u2h2(v0.y));
            neg[2] = __hadd2(neg[2], u2h2(v0.z));
            neg[3] = __hadd2(neg[3], u2h2(v0.w));
            neg[4] = __hadd2(neg[4], u2h2(v1.x));
            neg[5] = __hadd2(neg[5], u2h2(v1.y));
            neg[6] = __hadd2(neg[6], u2h2(v1.z));
            neg[7] = __hadd2(neg[7], u2h2(v1.w));
        }
    }
    uint4* op = (uint4*)(g_x16 + ((size_t)n * 1024 + px) * 24);
    op[0] = s0;                                 // self: bit-identical
    op[1] = s1;
    uint4 o;
    o.x = h22u(pos[0]); o.y = h22u(pos[1]); o.z = h22u(pos[2]); o.w = h22u(pos[3]);
    op[2] = o;
    o.x = h22u(pos[4]); o.y = h22u(pos[5]); o.z = h22u(pos[6]); o.w = h22u(pos[7]);
    op[3] = o;
    o.x = h22u(neg[0]); o.y = h22u(neg[1]); o.z = h22u(neg[2]); o.w = h22u(neg[3]);
    op[4] = o;
    o.x = h22u(neg[4]); o.y = h22u(neg[5]); o.z = h22u(neg[6]); o.w = h22u(neg[7]);
    op[5] = o;
}

// ---------------------------------------------------------------------------
// Weight prep (fused): fp32 OIHW -> fp16 [rep][oc][k=tap*CIN+cin] rows pad KP.
// rep 0 = w_hi = fp16(w); rep 1 = w_lo = fp16(w - w_hi).
__device__ __forceinline__ void prep_one(const float* __restrict__ wgt,
                                         __half* __restrict__ gB,
                                         int idx, int CIN, int COUT, int KP) {
    int rep = idx / (COUT * KP);
    int rem = idx % (COUT * KP);
    int oc = rem / KP, kp = rem % KP;
    __half val = __float2half(0.f);
    if (kp < 9 * CIN) {
        int tap = kp / CIN, cin = kp % CIN;
        float wv = wgt[(oc * CIN + cin) * 9 + tap];
        __half h = __float2half(wv);
        val = rep ? __float2half(wv - __half2float(h)) : h;
    }
    gB[idx] = val;
}
#define PW1 (2 * 32 * 440)
#define PW2 (2 * 32 * 296)
#define PW3 (2 * 16 * 296)
__global__ void k_prep(const float* __restrict__ w1, const float* __restrict__ w2,
                       const float* __restrict__ w3) {
    int idx = blockIdx.x * 256 + threadIdx.x;
    if (idx < PW1) prep_one(w1, g_wb1, idx, 48, 32, 440);
    else if (idx < PW1 + PW2) prep_one(w2, g_wb2, idx - PW1, 32, 32, 296);
    else if (idx < PW1 + PW2 + PW3) prep_one(w3, g_wb3, idx - PW1 - PW2, 32, 16, 296);
}

// ---------------------------------------------------------------------------
// HMMA implicit-GEMM conv, fp16 2-term (acc = A*W_hi + A*W_lo), single A plane,
// cp.async staging, optional double-buffered tile pipeline.
// Warp = MT m16 tiles. Plane [ROWS+2][34][CP] fp16 per buffer.
template <int CIN, int COUT, int ROWS, int NWARP, int MT, int KP, bool PACKED, bool DBUF>
__device__ __forceinline__ void conv_body(
    const uint32_t* __restrict__ in16, const __half* __restrict__ gB,
    const float* __restrict__ bias,
    uint32_t* __restrict__ out_pk, float* __restrict__ out_f32) {
    constexpr int CP  = CIN + 8;
    constexpr int NCG = CIN / 16;
    constexpr int NT  = COUT / 8;
    constexpr int NH  = NT / 2;
    constexpr int BB  = 2 * COUT * KP * 2;
    constexpr int PB  = (ROWS + 2) * 34 * CP * 2;   // one fp16 plane
    constexpr int NTHR = NWARP * 32;
    constexpr int TPI = 32 / ROWS;
    constexpr int NTILES = NN * TPI;
    constexpr int IT  = (ROWS + 2) * 34;
    constexpr int CH  = CIN / 8;        // 16B chunks per pixel
    constexpr int CU  = CIN / 2;        // u32 per pixel in global array

    extern __shared__ char smem[];
    char* Bs = smem;

    const int tid = threadIdx.x, wid = tid >> 5, lane = tid & 31;
    const uint32_t Bs_u = smem_u32(Bs);
    const uint32_t P0_u = Bs_u + BB;

    // stage B once (persistent CTA)
    for (int i = tid; i < BB / 4; i += NTHR)
        ((uint32_t*)Bs)[i] = ((const uint32_t*)gB)[i];

    // A-fragment lane mapping (validated R7-R16)
    const int arl = (lane & 7) + ((lane >> 3) & 1) * 8;
    const int akb = lane >> 4;
    uint32_t pb[MT];
#pragma unroll
    for (int mt = 0; mt < MT; mt++) {
        int px = wid * (MT * 16) + mt * 16 + arl;
        pb[mt] = (uint32_t)((((px >> 5) * 34) + (px & 31)) * CP * 2 + akb * 16);
    }
    // B-fragment lane mapping (validated R7-R16)
    const int boc = ((lane >> 4) & 1) * 8 + (lane & 7);
    const int bkb = (lane >> 3) & 1;
    uint32_t bb0[NH], bb1[NH];
#pragma unroll
    for (int h = 0; h < NH; h++) {
        bb0[h] = Bs_u + (uint32_t)((h * 16 + boc) * KP * 2 + bkb * 16);
        bb1[h] = bb0[h] + (uint32_t)(COUT * KP * 2);
    }
    const int g_r = lane >> 2, tg = lane & 3;
    float bv[NT][2];
#pragma unroll
    for (int nt = 0; nt < NT; nt++) {
        bv[nt][0] = __ldg(bias + nt * 8 + tg * 2);
        bv[nt][1] = __ldg(bias + nt * 8 + tg * 2 + 1);
    }

    // staging: pure 16B async copies into plane at `pbase_u`
    auto stage = [&](int t, uint32_t pbase_u) {
        const int n = t / TPI, y0 = (t % TPI) * ROWS;
        const size_t nb = (size_t)n * 1024;
        for (int idx = tid; idx < IT * CH; idx += NTHR) {
            int item = idx / CH, ch = idx % CH;
            int y = item / 34, x = item % 34;
            int yi = y0 - 1 + y, xi = x - 1;
            bool ok = ((unsigned)yi < 32u) && ((unsigned)xi < 32u);
            const char* src = (const char*)(in16 + (nb + (ok ? yi * 32 + xi : 0)) * CU) + ch * 16;
            uint32_t dst = pbase_u + (uint32_t)(item * CP * 2 + ch * 16);
            CP_ASYNC16(dst, src, ok ? 16 : 0);
        }
    };

    int parity = 0;
    if (DBUF && blockIdx.x < NTILES) stage(blockIdx.x, P0_u);
    if (DBUF) CP_COMMIT();

    for (int tile = blockIdx.x; tile < NTILES; tile += gridDim.x) {
        const int n = tile / TPI, y0 = (tile % TPI) * ROWS;
        const size_t nbase = (size_t)n * 1024;
        const uint32_t P_u = DBUF ? (P0_u + (uint32_t)(parity * PB)) : P0_u;

        if (DBUF) {
            int nxt = tile + gridDim.x;
            if (nxt < NTILES) stage(nxt, P0_u + (uint32_t)((parity ^ 1) * PB));
            CP_COMMIT();
            CP_WAIT1();
        } else {
            stage(tile, P0_u);
            CP_COMMIT();
            CP_WAIT0();
        }
        __syncthreads();

        // ---- k loop: A single plane; 2 weight reps (hi, lo) onto same acc ----
        float acc[MT][NT][4];
#pragma unroll
        for (int mt = 0; mt < MT; mt++)
#pragma unroll
            for (int nt = 0; nt < NT; nt++)
                acc[mt][nt][0] = acc[mt][nt][1] = acc[mt][nt][2] = acc[mt][nt][3] = 0.f;

#pragma unroll
        for (int tap = 0; tap < 9; tap++) {
            const uint32_t toff = (uint32_t)(((tap / 3) * 34 + (tap % 3)) * CP * 2);
#pragma unroll
            for (int cg = 0; cg < NCG; cg++) {
                const uint32_t aoff = toff + cg * 32;
                const uint32_t koff = (uint32_t)((tap * CIN + cg * 16) * 2);
                uint32_t a[MT][4];
#pragma unroll
                for (int mt = 0; mt < MT; mt++)
                    LDSM_X4(a[mt][0], a[mt][1], a[mt][2], a[mt][3], P_u + pb[mt] + aoff);
#pragma unroll
                for (int h = 0; h < NH; h++) {
                    uint32_t b0, b1, b2, b3, c0, c1, c2, c3;
                    LDSM_X4(b0, b1, b2, b3, bb0[h] + koff);  // w_hi
                    LDSM_X4(c0, c1, c2, c3, bb1[h] + koff);  // w_lo
#pragma unroll
                    for (int mt = 0; mt < MT; mt++) {
                        MMA16816H(acc[mt][2*h],   a[mt][0], a[mt][1], a[mt][2], a[mt][3], b0, b1);
                        MMA16816H(acc[mt][2*h+1], a[mt][0], a[mt][1], a[mt][2], a[mt][3], b2, b3);
                        MMA16816H(acc[mt][2*h],   a[mt][0], a[mt][1], a[mt][2], a[mt][3], c0, c1);
                        MMA16816H(acc[mt][2*h+1], a[mt][0], a[mt][1], a[mt][2], a[mt][3], c2, c3);
                    }
                }
            }
        }

        // ---- epilogue ----
        if constexpr (PACKED) {
#pragma unroll
            for (int mt = 0; mt < MT; mt++) {
                const int pA = wid * (MT * 16) + mt * 16 + g_r, pB2 = pA + 8;
                const size_t oA = (nbase + y0 * 32 + pA) * (COUT / 2);
                const size_t oB = (nbase + y0 * 32 + pB2) * (COUT / 2);
#pragma unroll
                for (int nt = 0; nt < NT; nt++) {
                    int oc = nt * 8 + tg * 2;
                    float v0 = acc[mt][nt][0] + bv[nt][0];
                    float v1 = acc[mt][nt][1] + bv[nt][1];
                    float v2 = acc[mt][nt][2] + bv[nt][0];
                    float v3 = acc[mt][nt][3] + bv[nt][1];
                    v0 = v0 > 0.f ? v0 : 0.1f * v0;
                    v1 = v1 > 0.f ? v1 : 0.1f * v1;
                    v2 = v2 > 0.f ? v2 : 0.1f * v2;
                    v3 = v3 > 0.f ? v3 : 0.1f * v3;
                    out_pk[oA + (oc >> 1)] = pack2h(v0, v1);
                    out_pk[oB + (oc >> 1)] = pack2h(v2, v3);
                }
            }
        } else {
            float* ob = out_f32 + (size_t)n * COUT * HW + y0 * 32;
#pragma unroll
            for (int mt = 0; mt < MT; mt++) {
                const int pA = wid * (MT * 16) + mt * 16 + g_r, pB2 = pA + 8;
#pragma unroll
                for (int nt = 0; nt < NT; nt++) {
                    int oc = nt * 8 + tg * 2;
                    float v;
                    v = acc[mt][nt][0] + bv[nt][0]; v = v > 0.f ? v : 0.1f * v; ob[(size_t)oc * HW + pA] = v;
                    v = acc[mt][nt][1] + bv[nt][1]; v = v > 0.f ? v : 0.1f * v; ob[(size_t)(oc + 1) * HW + pA] = v;
                    v = acc[mt][nt][2] + bv[nt][0]; v = v > 0.f ? v : 0.1f * v; ob[(size_t)oc * HW + pB2] = v;
                    v = acc[mt][nt][3] + bv[nt][1]; v = v > 0.f ? v : 0.1f * v; ob[(size_t)(oc + 1) * HW + pB2] = v;
                }
            }
        }
        __syncthreads();   // protect plane before next staging overwrites
        parity ^= 1;
    }
}

// conv1: ROWS=16, 16 warps, MT=2, double-buffered (1 CTA/SM)
__global__ __launch_bounds__(512, 1) void k_mconv1(const float* __restrict__ b) {
    conv_body<48, 32, 16, 16, 2, 440, true, true>(g_x16, g_wb1, b, g_t116, nullptr);
}
// conv2/3: ROWS=8, 8 warps, MT=2, double-buffered, 2 CTAs/SM
__global__ __launch_bounds__(256, 2) void k_mconv2(const float* __restrict__ b) {
    conv_body<32, 32, 8, 8, 2, 296, true, true>(g_t116, g_wb2, b, g_t216, nullptr);
}
__global__ __launch_bounds__(256, 2) void k_mconv3(const float* __restrict__ b,
                                                   float* __restrict__ out) {
    conv_body<32, 16, 8, 8, 2, 296, false, true>(g_t216, g_wb3, b, nullptr, out);
}

// ---------------------------------------------------------------------------
static inline int smsz(int CIN, int COUT, int KP, int ROWS, int nbuf) {
    return 2 * COUT * KP * 2 + nbuf * ((ROWS + 2) * 34 * (CIN + 8) * 2);
}

extern "C" void kernel_launch(void* const* d_in, const int* in_sizes, int n_in,
                              void* d_out, int out_size) {
    const float* feats = nullptr;
    const void*  edges = nullptr;
    const float *w1 = nullptr, *b1 = nullptr, *w2 = nullptr, *b2 = nullptr;
    const float *w3 = nullptr, *b3 = nullptr;
    int b32_seen = 0;
    for (int i = 0; i < n_in; i++) {
        switch (in_sizes[i]) {
            case 16777216: feats = (const float*)d_in[i]; break;
            case 12288:
            case 24576:    edges = d_in[i]; break;
            case 13824:    w1 = (const float*)d_in[i]; break;
            case 9216:     w2 = (const float*)d_in[i]; break;
            case 4608:     w3 = (const float*)d_in[i]; break;
            case 32:       if (b32_seen++ == 0) b1 = (const float*)d_in[i];
                           else                 b2 = (const float*)d_in[i];
                           break;
            case 16:       b3 = (const float*)d_in[i]; break;
            default: break;
        }
    }
    if (!feats || !edges || !w1 || !b1 || !w2 || !b2 || !w3 || !b3) {
        feats = (const float*)d_in[0];
        edges = d_in[1];
        w1 = (const float*)d_in[2]; b1 = (const float*)d_in[3];
        w2 = (const float*)d_in[4]; b2 = (const float*)d_in[5];
        w3 = (const float*)d_in[6]; b3 = (const float*)d_in[7];
    }
    float* out = (float*)d_out;

    // Idempotent, not a stream op — safe on every call.
    cudaFuncSetAttribute(k_mconv1, cudaFuncAttributeMaxDynamicSharedMemorySize, smsz(48, 32, 440, 16, 2));
    cudaFuncSetAttribute(k_mconv2, cudaFuncAttributeMaxDynamicSharedMemorySize, smsz(32, 32, 296, 8, 2));
    cudaFuncSetAttribute(k_mconv3, cudaFuncAttributeMaxDynamicSharedMemorySize, smsz(32, 16, 296, 8, 2));

    k_zeroadj<<<1, 1024>>>(edges);
    k_cvt<<<(NN * 8 * HW) / 256, 256>>>(feats);
    k_prep<<<(PW1 + PW2 + PW3 + 255) / 256, 256>>>(w1, w2, w3);
    k_build<<<NN * 4, 256>>>();
    k_mconv1<<<148, 512, smsz(48, 32, 440, 16, 2)>>>(b1);
    k_mconv2<<<296, 256, smsz(32, 32, 296, 8, 2)>>>(b2);
    k_mconv3<<<296, 256, smsz(32, 16, 296, 8, 2)>>>(b3, out);
}